// round 9
// baseline (speedup 1.0000x reference)
#include <cuda_runtime.h>
#include <cuda_fp16.h>
#include <cstdint>

#define AGENTS 16
#define BATCH  8192
#define OBS    128
#define ACT    16
#define HID    128
#define NHEAD  4
#define DHEAD  32
#define INP    (OBS + ACT)   // 144

#define CHUNK  32
#define STRIDE (CHUNK + 8)   // 40
#define PLANE  (128 * STRIDE)     // elements
#define PLANE_B (PLANE * 2)       // 10240 bytes
#define BUF_B   (3 * PLANE_B)     // 30720 bytes (Ah, Al, Bh)
#define SMEM_TOT (3 * BUF_B)      // 92160 bytes (3-stage)

// ---------------- scratch (static device globals; no runtime alloc) -----------
__device__ float g_ps [AGENTS * 160 * 8];
__device__ float g_ps2[AGENTS * 160 * 8];
__device__ float g_mean[AGENTS * INP];
__device__ float g_istd[AGENTS * INP];
__device__ float g_b1  [AGENTS * 256];       // [bsaf | bsf]
__device__ float g_bkv [256];                // [0 | bv]
// fp16 weight images (hi only), [n][Kpad] row-major (B^T)
__device__ __half w1_h [(long)AGENTS * 256 * 160];
__device__ __half wkv_h[256 * HID];
__device__ __half wsel_h[HID * HID];
__device__ __half wc1_h[(long)AGENTS * HID * 2 * HID];
// fp16 hi/lo activation planes
__device__ __half g_obsH[(long)AGENTS * BATCH * OBS];
__device__ __half g_obsL[(long)AGENTS * BATCH * OBS];
__device__ __half g_actH[(long)AGENTS * BATCH * ACT];
__device__ __half g_actL[(long)AGENTS * BATCH * ACT];
__device__ __half g_aseH[(long)AGENTS * BATCH * 256];   // [sa | se]
__device__ __half g_aseL[(long)AGENTS * BATCH * 256];
__device__ __half g_othH[(long)AGENTS * BATCH * HID];
__device__ __half g_othL[(long)AGENTS * BATCH * HID];
// fp32 buffers for attention inputs
__device__ float g_KV   [(long)AGENTS * BATCH * 256];   // [K | V]
__device__ float g_S    [(long)AGENTS * BATCH * HID];

// ---------------- helpers ------------------------------------------------------
__device__ __forceinline__ uint32_t smem_u32(const void* p) {
    uint32_t r;
    asm("{ .reg .u64 t; cvta.to.shared.u64 t, %1; cvt.u32.u64 %0, t; }" : "=r"(r) : "l"(p));
    return r;
}
__device__ __forceinline__ void ldm_x4(uint32_t* r, uint32_t addr) {
    asm volatile("ldmatrix.sync.aligned.m8n8.x4.shared.b16 {%0,%1,%2,%3}, [%4];"
                 : "=r"(r[0]), "=r"(r[1]), "=r"(r[2]), "=r"(r[3]) : "r"(addr));
}
__device__ __forceinline__ void mma_f16(float* c, const uint32_t* a, uint32_t b0, uint32_t b1) {
    asm volatile("mma.sync.aligned.m16n8k16.row.col.f32.f16.f16.f32 "
                 "{%0,%1,%2,%3}, {%4,%5,%6,%7}, {%8,%9}, {%0,%1,%2,%3};"
                 : "+f"(c[0]), "+f"(c[1]), "+f"(c[2]), "+f"(c[3])
                 : "r"(a[0]), "r"(a[1]), "r"(a[2]), "r"(a[3]), "r"(b0), "r"(b1));
}
__device__ __forceinline__ void cp16(uint32_t dst, const void* src) {
    asm volatile("cp.async.cg.shared.global [%0], [%1], 16;" :: "r"(dst), "l"(src));
}
__device__ __forceinline__ void cp16p(uint32_t dst, const void* src, int ok) {
    asm volatile("{\n\t.reg .pred p;\n\tsetp.ne.b32 p, %2, 0;\n\t"
                 "@p cp.async.cg.shared.global [%0], [%1], 16;\n\t"
                 "@!p cp.async.cg.shared.global [%0], [%1], 16, 0;\n\t}"
                 :: "r"(dst), "l"(src), "r"(ok));
}
__device__ __forceinline__ void cp_commit() { asm volatile("cp.async.commit_group;" ::: "memory"); }
__device__ __forceinline__ void cp_wait1()  { asm volatile("cp.async.wait_group 1;" ::: "memory"); }
__device__ __forceinline__ void cp_wait0()  { asm volatile("cp.async.wait_group 0;" ::: "memory"); }
__device__ __forceinline__ uint32_t pack_h2(float x, float y) {
    __half hx = __float2half_rn(x), hy = __float2half_rn(y);
    return (uint32_t)__half_as_ushort(hx) | ((uint32_t)__half_as_ushort(hy) << 16);
}

// ---------------- BN pass 1: partial sums + fp16 split planes ------------------
__global__ void bn_part_kernel(const float* __restrict__ obs,
                               const float* __restrict__ actions,
                               float* __restrict__ ps, float* __restrict__ ps2,
                               __half* __restrict__ oH, __half* __restrict__ oL,
                               __half* __restrict__ aH, __half* __restrict__ aL)
{
    int a = blockIdx.x;
    int f = blockIdx.y * 32 + threadIdx.x;
    int seg = blockIdx.z;
    float s = 0.f, s2 = 0.f;
    if (f < INP) {
        if (f < OBS) {
            long base = (long)a * BATCH * OBS + (long)seg * 1024 * OBS + f;
            const float* src = obs + base;
            for (int b = threadIdx.y; b < 1024; b += 32) {
                float x = src[(long)b * OBS]; s += x; s2 += x * x;
                __half h = __float2half_rn(x);
                oH[base + (long)b * OBS] = h;
                oL[base + (long)b * OBS] = __float2half_rn(x - __half2float(h));
            }
        } else {
            long base = (long)a * BATCH * ACT + (long)seg * 1024 * ACT + (f - OBS);
            const float* src = actions + base;
            for (int b = threadIdx.y; b < 1024; b += 32) {
                float x = src[(long)b * ACT]; s += x; s2 += x * x;
                __half h = __float2half_rn(x);
                aH[base + (long)b * ACT] = h;
                aL[base + (long)b * ACT] = __float2half_rn(x - __half2float(h));
            }
        }
    }
    __shared__ float sh1[32][33];
    __shared__ float sh2[32][33];
    sh1[threadIdx.y][threadIdx.x] = s;
    sh2[threadIdx.y][threadIdx.x] = s2;
    __syncthreads();
    for (int st = 16; st > 0; st >>= 1) {
        if (threadIdx.y < st) {
            sh1[threadIdx.y][threadIdx.x] += sh1[threadIdx.y + st][threadIdx.x];
            sh2[threadIdx.y][threadIdx.x] += sh2[threadIdx.y + st][threadIdx.x];
        }
        __syncthreads();
    }
    if (threadIdx.y == 0) {
        int fi = blockIdx.y * 32 + threadIdx.x;
        ps [(a * 160 + fi) * 8 + seg] = sh1[0][threadIdx.x];
        ps2[(a * 160 + fi) * 8 + seg] = sh2[0][threadIdx.x];
    }
}

// ---------------- BN pass 2 -----------------------------------------------------
__global__ void bn_fin_kernel(const float* __restrict__ ps, const float* __restrict__ ps2,
                              float* __restrict__ mean, float* __restrict__ istd)
{
    int a = blockIdx.x;
    int f = threadIdx.x;
    if (f >= INP) return;
    float s = 0.f, s2 = 0.f;
    for (int seg = 0; seg < 8; seg++) {
        s  += ps [(a * 160 + f) * 8 + seg];
        s2 += ps2[(a * 160 + f) * 8 + seg];
    }
    float m = s * (1.0f / BATCH);
    float v = s2 * (1.0f / BATCH) - m * m;
    mean[a * INP + f] = m;
    istd[a * INP + f] = rsqrtf(v + 1e-5f);
}

// ---------------- prep_all: BN-folded fp16 weight images + biases --------------
__global__ void prep_all(const float* __restrict__ W_sa, const float* __restrict__ b_sa,
                         const float* __restrict__ W_s,  const float* __restrict__ b_s,
                         const float* __restrict__ Wk, const float* __restrict__ Wsel,
                         const float* __restrict__ Wv, const float* __restrict__ bv,
                         const float* __restrict__ Wc1,
                         const float* __restrict__ mean, const float* __restrict__ istd,
                         __half* __restrict__ w1h, __half* __restrict__ kvh,
                         __half* __restrict__ selh, __half* __restrict__ c1h,
                         float* __restrict__ b1, float* __restrict__ bkv)
{
    int img = blockIdx.y;
    int a = blockIdx.z;
    int e = blockIdx.x * 256 + threadIdx.x;

    if (img == 0) {
        if (e >= 256 * 160) return;
        int n = e / 160, k = e - n * 160;
        float v = 0.f;
        if (n < 128) { if (k < INP) v = W_sa[((long)a * INP + k) * HID + n] * istd[a * INP + k]; }
        else         { if (k < OBS) v = W_s [((long)a * OBS + k) * HID + (n - 128)] * istd[a * INP + k]; }
        w1h[(long)a * 256 * 160 + e] = __float2half_rn(v);
    } else if (img == 1) {
        if (a != 0 || e >= 256 * 128) return;
        int n = e >> 7, k = e & 127;
        float v = (n < 128) ? Wk[(((n >> 5) * HID) + k) * DHEAD + (n & 31)]
                            : Wv[((((n - 128) >> 5) * HID) + k) * DHEAD + ((n - 128) & 31)];
        kvh[e] = __float2half_rn(v);
    } else if (img == 2) {
        if (a != 0 || e >= 128 * 128) return;
        int n = e >> 7, k = e & 127;
        selh[e] = __float2half_rn(Wsel[(((n >> 5) * HID) + k) * DHEAD + (n & 31)]);
    } else if (img == 3) {
        if (e >= 128 * 256) return;
        int n = e >> 8, k = e & 255;
        c1h[(long)a * 128 * 256 + e] = __float2half_rn(Wc1[((long)a * 2 * HID + k) * HID + n]);
    } else {
        if (blockIdx.x != 0) return;
        int n = threadIdx.x;   // 0..255
        float acc = 0.f;
        if (n < 128) {
            for (int k = 0; k < INP; k++)
                acc += mean[a * INP + k] * istd[a * INP + k] * W_sa[((long)a * INP + k) * HID + n];
            b1[a * 256 + n] = b_sa[a * HID + n] - acc;
        } else {
            for (int k = 0; k < OBS; k++)
                acc += mean[a * INP + k] * istd[a * INP + k] * W_s[((long)a * OBS + k) * HID + (n - 128)];
            b1[a * 256 + n] = b_s[a * HID + (n - 128)] - acc;
        }
        if (a == 0) bkv[n] = (n < 128) ? 0.f : bv[n - 128];
    }
}

// ---------------- tensor-core GEMM (fp16 2-term split, fp32 accum) -------------
// 3-stage cp.async pipeline, one barrier per chunk, hoisted ldmatrix addresses.
__global__ void __launch_bounds__(256, 2) gemm_mma(
    const __half* __restrict__ A0h, const __half* __restrict__ A0l, long sA0, int lda0,
    const __half* __restrict__ A1h, const __half* __restrict__ A1l, long sA1, int lda1,
    int ksplit, int Kreal,
    const __half* __restrict__ Bh_, long sB, int Kpad,
    const float* __restrict__ bias, long sBias,
    float* __restrict__ C, long sC, int ldc, int actFrom,
    int outHalf, __half* __restrict__ Ch, __half* __restrict__ Cl,
    int mergedSel, const __half* __restrict__ B2h, float* __restrict__ C2, long sC2,
    int fuseFinal, const float* __restrict__ actions, const float* __restrict__ Wc2,
    const float* __restrict__ bc2, float* __restrict__ outq)
{
    extern __shared__ __half sm[];
    __shared__ float sWc2[HID * ACT];
    __shared__ int   sIdx[128];
    __shared__ float sQred[2][128];

    int tid = threadIdx.x, wid = tid >> 5, lane = tid & 31;
    int a = blockIdx.z;
    long mBase = (long)blockIdx.x * 128;
    int wm = (wid & 3) * 32;
    int wn = (wid >> 2) * 64;

    // per-y routing
    int colBase = blockIdx.y * 128;
    int aOff = 0;
    const __half* bhP = Bh_;
    float* Cout = C;
    long sCout = sC;
    int ldcL = ldc;
    const float* biasL = bias;
    int actF = actFrom;
    if (mergedSel && blockIdx.y == 2) {
        aOff = 128; bhP = B2h; colBase = 0;
        Cout = C2; sCout = sC2; ldcL = 128; biasL = nullptr; actF = 1 << 30;
    }
    bhP += (long)a * sB;

    if (fuseFinal) {
        for (int i = tid; i < HID * ACT; i += 256)
            sWc2[i] = Wc2[(long)a * HID * ACT + i];
        if (tid < 128) {
            const float* ap = actions + ((long)a * BATCH + mBase + tid) * ACT;
            float best = ap[0]; int bi = 0;
#pragma unroll
            for (int j = 1; j < ACT; j++) {
                float x = ap[j];
                if (x > best) { best = x; bi = j; }
            }
            sIdx[tid] = bi;
        }
    }

    float acc[2][8][4];
#pragma unroll
    for (int i = 0; i < 2; i++)
#pragma unroll
        for (int j = 0; j < 8; j++)
#pragma unroll
            for (int q = 0; q < 4; q++) acc[i][j][q] = 0.f;

    uint32_t smB = smem_u32(sm);
    int nChunks = Kpad / CHUNK;

    // ---- hoisted per-thread addressing ----
    // issue-side
    int is_row = tid >> 2;              // 0..63? no: 512 iters /256 thr = 2 per thread
    (void)is_row;
    // compute-side in-buffer byte offsets
    int lr16 = lane & 15, lh16 = (lane >> 4) * 8;
    int lr8 = lane & 7, lk8 = ((lane >> 3) & 1) * 8, ln8 = (lane >> 4) * 8;
    uint32_t aHoff[2], aLoff[2], bOff[4];
#pragma unroll
    for (int mi = 0; mi < 2; mi++) {
        aHoff[mi] = (uint32_t)(((wm + mi * 16 + lr16) * STRIDE + lh16) * 2);
        aLoff[mi] = aHoff[mi] + PLANE_B;
    }
#pragma unroll
    for (int ni4 = 0; ni4 < 4; ni4++)
        bOff[ni4] = (uint32_t)(((wn + ni4 * 16 + ln8 + lr8) * STRIDE + lk8) * 2) + 2 * PLANE_B;

    auto issue = [&](int c, int buf) {
        uint32_t base = smB + (uint32_t)(buf * BUF_B);
        uint32_t AhB = base, AlB = base + PLANE_B, BhB = base + 2 * PLANE_B;
        int k0 = c * CHUNK;
#pragma unroll
        for (int it = 0; it < 2; it++) {
            int i = tid + it * 256;
            int row = i >> 2, kk = (i & 3) * 8;
            int kg = k0 + kk;
            const __half *ph, *pl; int ok = 1;
            if (kg < ksplit) {
                long o = (long)a * sA0 + (mBase + row) * (long)lda0 + aOff + kg;
                ph = A0h + o; pl = A0l + o;
            } else if (kg < Kreal) {
                long o = (long)a * sA1 + (mBase + row) * (long)lda1 + (kg - ksplit);
                ph = A1h + o; pl = A1l + o;
            } else {
                ph = A0h; pl = A0l; ok = 0;
            }
            uint32_t d = (uint32_t)((row * STRIDE + kk) * 2);
            cp16p(AhB + d, ph, ok);
            cp16p(AlB + d, pl, ok);
        }
#pragma unroll
        for (int it = 0; it < 2; it++) {
            int i = tid + it * 256;
            int n = i >> 2, kk = (i & 3) * 8;
            long o = (long)(colBase + n) * Kpad + k0 + kk;
            cp16(BhB + (uint32_t)((n * STRIDE + kk) * 2), bhP + o);
        }
        cp_commit();
    };

    // prologue: fill 2 stages, make group 0 visible everywhere
    issue(0, 0);
    if (nChunks > 1) { issue(1, 1); cp_wait1(); }
    else             { cp_wait0(); }
    __syncthreads();

    int cbuf = 0;            // buffer of chunk c
    int ibuf = 2;            // buffer for chunk c+2
    for (int c = 0; c < nChunks; c++) {
        if (c + 2 < nChunks) issue(c + 2, ibuf);

        uint32_t base = smB + (uint32_t)(cbuf * BUF_B);
#pragma unroll
        for (int ks = 0; ks < CHUNK; ks += 16) {
            uint32_t ah[2][4], al[2][4];
#pragma unroll
            for (int mi = 0; mi < 2; mi++) {
                ldm_x4(ah[mi], base + aHoff[mi] + ks * 2);
                ldm_x4(al[mi], base + aLoff[mi] + ks * 2);
            }
#pragma unroll
            for (int ni4 = 0; ni4 < 4; ni4++) {
                uint32_t bh[4];
                ldm_x4(bh, base + bOff[ni4] + ks * 2);
#pragma unroll
                for (int mi = 0; mi < 2; mi++) {
                    mma_f16(acc[mi][ni4 * 2],     ah[mi], bh[0], bh[1]);
                    mma_f16(acc[mi][ni4 * 2 + 1], ah[mi], bh[2], bh[3]);
                    mma_f16(acc[mi][ni4 * 2],     al[mi], bh[0], bh[1]);
                    mma_f16(acc[mi][ni4 * 2 + 1], al[mi], bh[2], bh[3]);
                }
            }
        }

        // ensure group c+1 complete (for this thread), then barrier propagates
        if (c + 1 < nChunks) {
            if (c + 2 < nChunks) cp_wait1();
            else                 cp_wait0();
        }
        __syncthreads();

        cbuf = (cbuf == 2) ? 0 : cbuf + 1;
        ibuf = (ibuf == 2) ? 0 : ibuf + 1;
    }

    // ---- epilogue ----
    int gr = lane >> 2, tg = lane & 3;

    if (fuseFinal) {
        float p[4] = {0.f, 0.f, 0.f, 0.f};
#pragma unroll
        for (int mi = 0; mi < 2; mi++) {
            int ra = wm + mi * 16 + gr;
            int rb = ra + 8;
            int ia = sIdx[ra], ib = sIdx[rb];
#pragma unroll
            for (int ni = 0; ni < 8; ni++) {
                int col = wn + ni * 8 + tg * 2;
                const float* bp = biasL + (long)a * sBias + col;
                float b0 = bp[0], b1 = bp[1];
                float v0 = acc[mi][ni][0] + b0;
                float v1 = acc[mi][ni][1] + b1;
                float v2 = acc[mi][ni][2] + b0;
                float v3 = acc[mi][ni][3] + b1;
                v0 = v0 > 0.f ? v0 : 0.01f * v0;
                v1 = v1 > 0.f ? v1 : 0.01f * v1;
                v2 = v2 > 0.f ? v2 : 0.01f * v2;
                v3 = v3 > 0.f ? v3 : 0.01f * v3;
                p[mi * 2]     += v0 * sWc2[col * ACT + ia] + v1 * sWc2[(col + 1) * ACT + ia];
                p[mi * 2 + 1] += v2 * sWc2[col * ACT + ib] + v3 * sWc2[(col + 1) * ACT + ib];
            }
        }
#pragma unroll
        for (int q = 0; q < 4; q++) {
            p[q] += __shfl_xor_sync(0xffffffffu, p[q], 1);
            p[q] += __shfl_xor_sync(0xffffffffu, p[q], 2);
        }
        int nh = wid >> 2;
        if (tg == 0) {
            sQred[nh][wm + gr]      = p[0];
            sQred[nh][wm + gr + 8]  = p[1];
            sQred[nh][wm + gr + 16] = p[2];
            sQred[nh][wm + gr + 24] = p[3];
        }
        __syncthreads();
        if (tid < 128) {
            float q = sQred[0][tid] + sQred[1][tid] + bc2[a * ACT + sIdx[tid]];
            outq[(long)a * BATCH + mBase + tid] = q;
        }
        return;
    }

#pragma unroll
    for (int mi = 0; mi < 2; mi++) {
        long row0 = mBase + wm + mi * 16 + gr;
        long row1 = row0 + 8;
#pragma unroll
        for (int ni = 0; ni < 8; ni++) {
            int col = colBase + wn + ni * 8 + tg * 2;
            float b0 = 0.f, b1 = 0.f;
            if (biasL) {
                const float* bp = biasL + (long)a * sBias + col;
                b0 = bp[0]; b1 = bp[1];
            }
            float v0 = acc[mi][ni][0] + b0;
            float v1 = acc[mi][ni][1] + b1;
            float v2 = acc[mi][ni][2] + b0;
            float v3 = acc[mi][ni][3] + b1;
            if (col >= actF) {
                v0 = v0 > 0.f ? v0 : 0.01f * v0;
                v2 = v2 > 0.f ? v2 : 0.01f * v2;
            }
            if (col + 1 >= actF) {
                v1 = v1 > 0.f ? v1 : 0.01f * v1;
                v3 = v3 > 0.f ? v3 : 0.01f * v3;
            }
            if (outHalf) {
                long o0 = (long)a * sCout + row0 * ldcL + col;
                long o1 = (long)a * sCout + row1 * ldcL + col;
                __half h0 = __float2half_rn(v0), h1 = __float2half_rn(v1);
                __half h2 = __float2half_rn(v2), h3 = __float2half_rn(v3);
                *(uint32_t*)(Ch + o0) = (uint32_t)__half_as_ushort(h0) |
                                        ((uint32_t)__half_as_ushort(h1) << 16);
                *(uint32_t*)(Ch + o1) = (uint32_t)__half_as_ushort(h2) |
                                        ((uint32_t)__half_as_ushort(h3) << 16);
                *(uint32_t*)(Cl + o0) = pack_h2(v0 - __half2float(h0), v1 - __half2float(h1));
                *(uint32_t*)(Cl + o1) = pack_h2(v2 - __half2float(h2), v3 - __half2float(h3));
            } else {
                float* Cp = Cout + (long)a * sCout;
                *(float2*)(Cp + row0 * ldcL + col) = make_float2(v0, v1);
                *(float2*)(Cp + row1 * ldcL + col) = make_float2(v2, v3);
            }
        }
    }
}

// ---------------- attention: one warp per (head, agent_i, batch) --------------
__global__ void attn_kernel(const float* __restrict__ KV, const float* __restrict__ St,
                            __half* __restrict__ oH, __half* __restrict__ oL)
{
    int gw   = blockIdx.x * 8 + (threadIdx.x >> 5);
    int lane = threadIdx.x & 31;
    int b = gw >> 6;
    int r = gw & 63;
    int n = r >> 4;
    int i = r & 15;
    int col = n * DHEAD + lane;

    float selv = St[((long)i * BATCH + b) * HID + col];
    float lg = -3e38f;
#pragma unroll
    for (int j = 0; j < 16; j++) {
        float p = selv * KV[((long)j * BATCH + b) * 256 + col];
#pragma unroll
        for (int off = 16; off; off >>= 1) p += __shfl_xor_sync(0xffffffffu, p, off);
        if (lane == j) lg = (j == i) ? -1e9f : p * 0.17677669529663687f;
    }
    float mx = lg;
#pragma unroll
    for (int off = 16; off; off >>= 1) mx = fmaxf(mx, __shfl_xor_sync(0xffffffffu, mx, off));
    float e = (lane < 16) ? __expf(lg - mx) : 0.f;
    float den = e;
#pragma unroll
    for (int off = 16; off; off >>= 1) den += __shfl_xor_sync(0xffffffffu, den, off);
    float w = e / den;

    float acc = 0.f;
#pragma unroll
    for (int j = 0; j < 16; j++) {
        float wj = __shfl_sync(0xffffffffu, w, j);
        acc = fmaf(wj, KV[((long)j * BATCH + b) * 256 + 128 + col], acc);
    }
    long o = ((long)i * BATCH + b) * HID + col;
    __half h = __float2half_rn(acc);
    oH[o] = h;
    oL[o] = __float2half_rn(acc - __half2float(h));
}

// ---------------- launch -------------------------------------------------------
static float* symaddr(const void* sym)
{
    void* p = nullptr;
    cudaGetSymbolAddress(&p, sym);
    return (float*)p;
}
static __half* symaddr_h(const void* sym)
{
    void* p = nullptr;
    cudaGetSymbolAddress(&p, sym);
    return (__half*)p;
}

extern "C" void kernel_launch(void* const* d_in, const int* in_sizes, int n_in,
                              void* d_out, int out_size)
{
    const float* obs     = (const float*)d_in[0];
    const float* actions = (const float*)d_in[1];
    const float* W_sa    = (const float*)d_in[2];
    const float* b_sa    = (const float*)d_in[3];
    const float* W_s     = (const float*)d_in[4];
    const float* b_s     = (const float*)d_in[5];
    const float* Wk      = (const float*)d_in[6];
    const float* Wsel    = (const float*)d_in[7];
    const float* Wv      = (const float*)d_in[8];
    const float* bv      = (const float*)d_in[9];
    const float* Wc1     = (const float*)d_in[10];
    const float* bc1     = (const float*)d_in[11];
    const float* Wc2     = (const float*)d_in[12];
    const float* bc2     = (const float*)d_in[13];
    float* out = (float*)d_out;

    float* ps    = symaddr(g_ps);
    float* ps2   = symaddr(g_ps2);
    float* mean  = symaddr(g_mean);
    float* istd  = symaddr(g_istd);
    float* b1    = symaddr(g_b1);
    float* bkv   = symaddr(g_bkv);
    float* KV    = symaddr(g_KV);
    float* St    = symaddr(g_S);

    __half* w1h  = symaddr_h(w1_h);
    __half* kvh  = symaddr_h(wkv_h);
    __half* selh = symaddr_h(wsel_h);
    __half* c1h  = symaddr_h(wc1_h);
    __half* obsH = symaddr_h(g_obsH);
    __half* obsL = symaddr_h(g_obsL);
    __half* actH = symaddr_h(g_actH);
    __half* actL = symaddr_h(g_actL);
    __half* aseH = symaddr_h(g_aseH);
    __half* aseL = symaddr_h(g_aseL);
    __half* othH = symaddr_h(g_othH);
    __half* othL = symaddr_h(g_othL);

    static bool attr_set = false;
    if (!attr_set) {
        cudaFuncSetAttribute(gemm_mma, cudaFuncAttributeMaxDynamicSharedMemorySize, SMEM_TOT);
        attr_set = true;
    }

    const long sOBS = (long)BATCH * OBS;
    const long sACT = (long)BATCH * ACT;
    const long sASE = (long)BATCH * 256;
    const long sH   = (long)BATCH * HID;
    size_t smem = SMEM_TOT;   // 92160

    // 0
    bn_part_kernel<<<dim3(AGENTS, 5, 8), dim3(32, 32)>>>(obs, actions, ps, ps2,
                                                          obsH, obsL, actH, actL);
    // 1
    bn_fin_kernel<<<AGENTS, 160>>>(ps, ps2, mean, istd);
    // 2
    prep_all<<<dim3(160, 5, AGENTS), 256>>>(W_sa, b_sa, W_s, b_s, Wk, Wsel, Wv, bv,
                                            Wc1, mean, istd,
                                            w1h, kvh, selh, c1h, b1, bkv);

    // 3: ase = lrelu(bn([obs|act]) @ [W_sa|W_s] + b1)  K=144->160
    gemm_mma<<<dim3(BATCH / 128, 2, AGENTS), 256, smem>>>(
        obsH, obsL, sOBS, OBS, actH, actL, sACT, ACT, OBS, INP,
        w1h, (long)256 * 160, 160,
        b1, 256, nullptr, sASE, 256, 0,
        1, aseH, aseL,
        0, nullptr, nullptr, 0,
        0, nullptr, nullptr, nullptr, nullptr);

    // 4: merged KV + Sel.  y<2: KV = sa @ [Wk|Wv]; y==2: S = se @ Wsel
    gemm_mma<<<dim3(BATCH / 128, 3, AGENTS), 256, smem>>>(
        aseH, aseL, sASE, 256, aseH, aseL, 0, 0, 1 << 30, HID,
        kvh, 0, HID,
        bkv, 0, KV, sASE, 256, 128,
        0, nullptr, nullptr,
        1, selh, St, sH,
        0, nullptr, nullptr, nullptr, nullptr);

    // 5: attention -> other (fp16 pair)
    attn_kernel<<<(BATCH * 64) / 8, 256>>>(KV, St, othH, othL);

    // 6: q = fused( lrelu([se|other] @ Wc1 + bc1) . Wc2[:,argmax] + bc2 )  K=256
    gemm_mma<<<dim3(BATCH / 128, 1, AGENTS), 256, smem>>>(
        aseH + 128, aseL + 128, sASE, 256, othH, othL, sH, HID, HID, 2 * HID,
        c1h, (long)HID * 2 * HID, 2 * HID,
        bc1, HID, nullptr, 0, 0, 1 << 30,
        0, nullptr, nullptr,
        0, nullptr, nullptr, 0,
        1, actions, Wc2, bc2, out);
}

// round 10
// speedup vs baseline: 1.0291x; 1.0291x over previous
#include <cuda_runtime.h>
#include <cuda_fp16.h>
#include <cstdint>

#define AGENTS 16
#define BATCH  8192
#define OBS    128
#define ACT    16
#define HID    128
#define NHEAD  4
#define DHEAD  32
#define INP    (OBS + ACT)   // 144

#define CHUNK  32
#define STRIDE (CHUNK + 8)   // 40
#define PLANE_B (128 * STRIDE * 2)   // A plane bytes: 10240

// ---------------- scratch (static device globals; no runtime alloc) -----------
__device__ float g_ps [AGENTS * 160 * 8];
__device__ float g_ps2[AGENTS * 160 * 8];
__device__ float g_mean[AGENTS * INP];
__device__ float g_istd[AGENTS * INP];
__device__ float g_b1  [AGENTS * 256];       // [bsaf | bsf]
__device__ float g_bkv [256];                // [0 | bv]
// fp16 weight images (hi only), [n][Kpad] row-major (B^T)
__device__ __half w1_h [(long)AGENTS * 256 * 160];
__device__ __half wkv_h[256 * HID];
__device__ __half wsel_h[HID * HID];
__device__ __half wc1_h[(long)AGENTS * HID * 2 * HID];
// fp16 hi/lo activation planes
__device__ __half g_obsH[(long)AGENTS * BATCH * OBS];
__device__ __half g_obsL[(long)AGENTS * BATCH * OBS];
__device__ __half g_actH[(long)AGENTS * BATCH * ACT];
__device__ __half g_actL[(long)AGENTS * BATCH * ACT];
__device__ __half g_aseH[(long)AGENTS * BATCH * 256];   // [sa | se]
__device__ __half g_aseL[(long)AGENTS * BATCH * 256];
__device__ __half g_othH[(long)AGENTS * BATCH * HID];
__device__ __half g_othL[(long)AGENTS * BATCH * HID];
// fp32 buffers for attention inputs
__device__ float g_KV   [(long)AGENTS * BATCH * 256];   // [K | V]
__device__ float g_S    [(long)AGENTS * BATCH * HID];

// ---------------- helpers ------------------------------------------------------
__device__ __forceinline__ uint32_t smem_u32(const void* p) {
    uint32_t r;
    asm("{ .reg .u64 t; cvta.to.shared.u64 t, %1; cvt.u32.u64 %0, t; }" : "=r"(r) : "l"(p));
    return r;
}
__device__ __forceinline__ void ldm_x4(uint32_t* r, uint32_t addr) {
    asm volatile("ldmatrix.sync.aligned.m8n8.x4.shared.b16 {%0,%1,%2,%3}, [%4];"
                 : "=r"(r[0]), "=r"(r[1]), "=r"(r[2]), "=r"(r[3]) : "r"(addr));
}
__device__ __forceinline__ void mma_f16(float* c, const uint32_t* a, uint32_t b0, uint32_t b1) {
    asm volatile("mma.sync.aligned.m16n8k16.row.col.f32.f16.f16.f32 "
                 "{%0,%1,%2,%3}, {%4,%5,%6,%7}, {%8,%9}, {%0,%1,%2,%3};"
                 : "+f"(c[0]), "+f"(c[1]), "+f"(c[2]), "+f"(c[3])
                 : "r"(a[0]), "r"(a[1]), "r"(a[2]), "r"(a[3]), "r"(b0), "r"(b1));
}
__device__ __forceinline__ void cp16(uint32_t dst, const void* src) {
    asm volatile("cp.async.cg.shared.global [%0], [%1], 16;" :: "r"(dst), "l"(src));
}
__device__ __forceinline__ void cp16p(uint32_t dst, const void* src, int ok) {
    asm volatile("{\n\t.reg .pred p;\n\tsetp.ne.b32 p, %2, 0;\n\t"
                 "@p cp.async.cg.shared.global [%0], [%1], 16;\n\t"
                 "@!p cp.async.cg.shared.global [%0], [%1], 16, 0;\n\t}"
                 :: "r"(dst), "l"(src), "r"(ok));
}
__device__ __forceinline__ void cp_commit() { asm volatile("cp.async.commit_group;" ::: "memory"); }
__device__ __forceinline__ void cp_wait1()  { asm volatile("cp.async.wait_group 1;" ::: "memory"); }
__device__ __forceinline__ void cp_wait0()  { asm volatile("cp.async.wait_group 0;" ::: "memory"); }
__device__ __forceinline__ uint32_t pack_h2(float x, float y) {
    __half hx = __float2half_rn(x), hy = __float2half_rn(y);
    return (uint32_t)__half_as_ushort(hx) | ((uint32_t)__half_as_ushort(hy) << 16);
}

// ---------------- BN pass 1: partial sums + fp16 split planes ------------------
__global__ void bn_part_kernel(const float* __restrict__ obs,
                               const float* __restrict__ actions,
                               float* __restrict__ ps, float* __restrict__ ps2,
                               __half* __restrict__ oH, __half* __restrict__ oL,
                               __half* __restrict__ aH, __half* __restrict__ aL)
{
    int a = blockIdx.x;
    int f = blockIdx.y * 32 + threadIdx.x;
    int seg = blockIdx.z;
    float s = 0.f, s2 = 0.f;
    if (f < INP) {
        if (f < OBS) {
            long base = (long)a * BATCH * OBS + (long)seg * 1024 * OBS + f;
            const float* src = obs + base;
            for (int b = threadIdx.y; b < 1024; b += 32) {
                float x = src[(long)b * OBS]; s += x; s2 += x * x;
                __half h = __float2half_rn(x);
                oH[base + (long)b * OBS] = h;
                oL[base + (long)b * OBS] = __float2half_rn(x - __half2float(h));
            }
        } else {
            long base = (long)a * BATCH * ACT + (long)seg * 1024 * ACT + (f - OBS);
            const float* src = actions + base;
            for (int b = threadIdx.y; b < 1024; b += 32) {
                float x = src[(long)b * ACT]; s += x; s2 += x * x;
                __half h = __float2half_rn(x);
                aH[base + (long)b * ACT] = h;
                aL[base + (long)b * ACT] = __float2half_rn(x - __half2float(h));
            }
        }
    }
    __shared__ float sh1[32][33];
    __shared__ float sh2[32][33];
    sh1[threadIdx.y][threadIdx.x] = s;
    sh2[threadIdx.y][threadIdx.x] = s2;
    __syncthreads();
    for (int st = 16; st > 0; st >>= 1) {
        if (threadIdx.y < st) {
            sh1[threadIdx.y][threadIdx.x] += sh1[threadIdx.y + st][threadIdx.x];
            sh2[threadIdx.y][threadIdx.x] += sh2[threadIdx.y + st][threadIdx.x];
        }
        __syncthreads();
    }
    if (threadIdx.y == 0) {
        int fi = blockIdx.y * 32 + threadIdx.x;
        ps [(a * 160 + fi) * 8 + seg] = sh1[0][threadIdx.x];
        ps2[(a * 160 + fi) * 8 + seg] = sh2[0][threadIdx.x];
    }
}

// ---------------- BN pass 2 -----------------------------------------------------
__global__ void bn_fin_kernel(const float* __restrict__ ps, const float* __restrict__ ps2,
                              float* __restrict__ mean, float* __restrict__ istd)
{
    int a = blockIdx.x;
    int f = threadIdx.x;
    if (f >= INP) return;
    float s = 0.f, s2 = 0.f;
    for (int seg = 0; seg < 8; seg++) {
        s  += ps [(a * 160 + f) * 8 + seg];
        s2 += ps2[(a * 160 + f) * 8 + seg];
    }
    float m = s * (1.0f / BATCH);
    float v = s2 * (1.0f / BATCH) - m * m;
    mean[a * INP + f] = m;
    istd[a * INP + f] = rsqrtf(v + 1e-5f);
}

// ---------------- prep_all: BN-folded fp16 weight images + biases --------------
__global__ void prep_all(const float* __restrict__ W_sa, const float* __restrict__ b_sa,
                         const float* __restrict__ W_s,  const float* __restrict__ b_s,
                         const float* __restrict__ Wk, const float* __restrict__ Wsel,
                         const float* __restrict__ Wv, const float* __restrict__ bv,
                         const float* __restrict__ Wc1,
                         const float* __restrict__ mean, const float* __restrict__ istd,
                         __half* __restrict__ w1h, __half* __restrict__ kvh,
                         __half* __restrict__ selh, __half* __restrict__ c1h,
                         float* __restrict__ b1, float* __restrict__ bkv)
{
    int img = blockIdx.y;
    int a = blockIdx.z;
    int e = blockIdx.x * 256 + threadIdx.x;

    if (img == 0) {
        if (e >= 256 * 160) return;
        int n = e / 160, k = e - n * 160;
        float v = 0.f;
        if (n < 128) { if (k < INP) v = W_sa[((long)a * INP + k) * HID + n] * istd[a * INP + k]; }
        else         { if (k < OBS) v = W_s [((long)a * OBS + k) * HID + (n - 128)] * istd[a * INP + k]; }
        w1h[(long)a * 256 * 160 + e] = __float2half_rn(v);
    } else if (img == 1) {
        if (a != 0 || e >= 256 * 128) return;
        int n = e >> 7, k = e & 127;
        float v = (n < 128) ? Wk[(((n >> 5) * HID) + k) * DHEAD + (n & 31)]
                            : Wv[((((n - 128) >> 5) * HID) + k) * DHEAD + ((n - 128) & 31)];
        kvh[e] = __float2half_rn(v);
    } else if (img == 2) {
        if (a != 0 || e >= 128 * 128) return;
        int n = e >> 7, k = e & 127;
        selh[e] = __float2half_rn(Wsel[(((n >> 5) * HID) + k) * DHEAD + (n & 31)]);
    } else if (img == 3) {
        if (e >= 128 * 256) return;
        int n = e >> 8, k = e & 255;
        c1h[(long)a * 128 * 256 + e] = __float2half_rn(Wc1[((long)a * 2 * HID + k) * HID + n]);
    } else {
        if (blockIdx.x != 0) return;
        int n = threadIdx.x;   // 0..255
        float acc = 0.f;
        if (n < 128) {
            for (int k = 0; k < INP; k++)
                acc += mean[a * INP + k] * istd[a * INP + k] * W_sa[((long)a * INP + k) * HID + n];
            b1[a * 256 + n] = b_sa[a * HID + n] - acc;
        } else {
            for (int k = 0; k < OBS; k++)
                acc += mean[a * INP + k] * istd[a * INP + k] * W_s[((long)a * OBS + k) * HID + (n - 128)];
            b1[a * 256 + n] = b_s[a * HID + (n - 128)] - acc;
        }
        if (a == 0) bkv[n] = (n < 128) ? 0.f : bv[n - 128];
    }
}

// ---------------- tensor-core GEMM (fp16 2-term split, fp32 accum) -------------
// Template on tile-N. TN=64: 3 CTAs/SM; TN=128: fused-final variant.
// selFrom: grid.y >= selFrom switches to (A+128 cols, B2 image, C2 output).
template<int TN, int MINB>
__global__ void __launch_bounds__(256, MINB) gemm_mma(
    const __half* __restrict__ A0h, const __half* __restrict__ A0l, long sA0, int lda0,
    const __half* __restrict__ A1h, const __half* __restrict__ A1l, long sA1, int lda1,
    int ksplit, int Kreal,
    const __half* __restrict__ Bh_, long sB, int Kpad,
    const float* __restrict__ bias, long sBias,
    float* __restrict__ C, long sC, int ldc, int actFrom,
    int outHalf, __half* __restrict__ Ch, __half* __restrict__ Cl,
    int selFrom, const __half* __restrict__ B2h, float* __restrict__ C2, long sC2,
    int fuseFinal, const float* __restrict__ actions, const float* __restrict__ Wc2,
    const float* __restrict__ bc2, float* __restrict__ outq)
{
    constexpr int BPL_B = TN * STRIDE * 2;          // B plane bytes
    constexpr int BUFB  = 2 * PLANE_B + BPL_B;      // stage bytes
    constexpr int NI4   = TN / 32;                  // 16-col tiles per warp
    constexpr int WNW   = TN / 2;                   // warp n width

    extern __shared__ __half sm[];
    __shared__ float sWc2[HID * ACT];
    __shared__ int   sIdx[128];
    __shared__ float sQred[2][128];

    int tid = threadIdx.x, wid = tid >> 5, lane = tid & 31;
    int a = blockIdx.z;
    long mBase = (long)blockIdx.x * 128;
    int wm = (wid & 3) * 32;
    int wn = (wid >> 2) * WNW;

    // per-y routing
    int colBase = blockIdx.y * TN;
    int aOff = 0;
    const __half* bhP = Bh_;
    float* Cout = C;
    long sCout = sC;
    int ldcL = ldc;
    const float* biasL = bias;
    int actF = actFrom;
    if ((int)blockIdx.y >= selFrom) {
        aOff = 128; bhP = B2h; colBase = (blockIdx.y - selFrom) * TN;
        Cout = C2; sCout = sC2; ldcL = 128; biasL = nullptr; actF = 1 << 30;
    }
    bhP += (long)a * sB;

    if (fuseFinal) {
        for (int i = tid; i < HID * ACT; i += 256)
            sWc2[i] = Wc2[(long)a * HID * ACT + i];
        if (tid < 128) {
            const float* ap = actions + ((long)a * BATCH + mBase + tid) * ACT;
            float best = ap[0]; int bi = 0;
#pragma unroll
            for (int j = 1; j < ACT; j++) {
                float x = ap[j];
                if (x > best) { best = x; bi = j; }
            }
            sIdx[tid] = bi;
        }
    }

    float acc[2][2 * NI4][4];
#pragma unroll
    for (int i = 0; i < 2; i++)
#pragma unroll
        for (int j = 0; j < 2 * NI4; j++)
#pragma unroll
            for (int q = 0; q < 4; q++) acc[i][j][q] = 0.f;

    uint32_t smB = smem_u32(sm);
    int nChunks = Kpad / CHUNK;

    // hoisted compute-side in-buffer byte offsets
    int lr16 = lane & 15, lh16 = (lane >> 4) * 8;
    int lr8 = lane & 7, lk8 = ((lane >> 3) & 1) * 8, ln8 = (lane >> 4) * 8;
    uint32_t aHoff[2], bOff[NI4];
#pragma unroll
    for (int mi = 0; mi < 2; mi++)
        aHoff[mi] = (uint32_t)(((wm + mi * 16 + lr16) * STRIDE + lh16) * 2);
#pragma unroll
    for (int ni4 = 0; ni4 < NI4; ni4++)
        bOff[ni4] = (uint32_t)(((wn + ni4 * 16 + ln8 + lr8) * STRIDE + lk8) * 2) + 2 * PLANE_B;

    auto issue = [&](int c, int buf) {
        uint32_t base = smB + (uint32_t)(buf * BUFB);
        uint32_t AhB = base, AlB = base + PLANE_B, BhB = base + 2 * PLANE_B;
        int k0 = c * CHUNK;
#pragma unroll
        for (int it = 0; it < 2; it++) {
            int i = tid + it * 256;
            int row = i >> 2, kk = (i & 3) * 8;
            int kg = k0 + kk;
            const __half *ph, *pl; int ok = 1;
            if (kg < ksplit) {
                long o = (long)a * sA0 + (mBase + row) * (long)lda0 + aOff + kg;
                ph = A0h + o; pl = A0l + o;
            } else if (kg < Kreal) {
                long o = (long)a * sA1 + (mBase + row) * (long)lda1 + (kg - ksplit);
                ph = A1h + o; pl = A1l + o;
            } else {
                ph = A0h; pl = A0l; ok = 0;
            }
            uint32_t d = (uint32_t)((row * STRIDE + kk) * 2);
            cp16p(AhB + d, ph, ok);
            cp16p(AlB + d, pl, ok);
        }
        for (int i = tid; i < TN * 4; i += 256) {
            int n = i >> 2, kk = (i & 3) * 8;
            long o = (long)(colBase + n) * Kpad + k0 + kk;
            cp16(BhB + (uint32_t)((n * STRIDE + kk) * 2), bhP + o);
        }
        cp_commit();
    };

    issue(0, 0);

    for (int c = 0; c < nChunks; c++) {
        if (c + 1 < nChunks) { issue(c + 1, (c + 1) & 1); cp_wait1(); }
        else                 { cp_wait0(); }
        __syncthreads();

        uint32_t base = smB + (uint32_t)((c & 1) * BUFB);
#pragma unroll
        for (int ks = 0; ks < CHUNK; ks += 16) {
            uint32_t ah[2][4], al[2][4];
#pragma unroll
            for (int mi = 0; mi < 2; mi++) {
                ldm_x4(ah[mi], base + aHoff[mi] + ks * 2);
                ldm_x4(al[mi], base + aHoff[mi] + PLANE_B + ks * 2);
            }
#pragma unroll
            for (int ni4 = 0; ni4 < NI4; ni4++) {
                uint32_t bh[4];
                ldm_x4(bh, base + bOff[ni4] + ks * 2);
#pragma unroll
                for (int mi = 0; mi < 2; mi++) {
                    mma_f16(acc[mi][ni4 * 2],     ah[mi], bh[0], bh[1]);
                    mma_f16(acc[mi][ni4 * 2 + 1], ah[mi], bh[2], bh[3]);
                    mma_f16(acc[mi][ni4 * 2],     al[mi], bh[0], bh[1]);
                    mma_f16(acc[mi][ni4 * 2 + 1], al[mi], bh[2], bh[3]);
                }
            }
        }
        __syncthreads();
    }

    // ---- epilogue ----
    int gr = lane >> 2, tg = lane & 3;

    if constexpr (TN == 128) {
        if (fuseFinal) {
            float p[4] = {0.f, 0.f, 0.f, 0.f};
#pragma unroll
            for (int mi = 0; mi < 2; mi++) {
                int ra = wm + mi * 16 + gr;
                int rb = ra + 8;
                int ia = sIdx[ra], ib = sIdx[rb];
#pragma unroll
                for (int ni = 0; ni < 2 * NI4; ni++) {
                    int col = wn + ni * 8 + tg * 2;
                    const float* bp = biasL + (long)a * sBias + col;
                    float b0 = bp[0], b1 = bp[1];
                    float v0 = acc[mi][ni][0] + b0;
                    float v1 = acc[mi][ni][1] + b1;
                    float v2 = acc[mi][ni][2] + b0;
                    float v3 = acc[mi][ni][3] + b1;
                    v0 = v0 > 0.f ? v0 : 0.01f * v0;
                    v1 = v1 > 0.f ? v1 : 0.01f * v1;
                    v2 = v2 > 0.f ? v2 : 0.01f * v2;
                    v3 = v3 > 0.f ? v3 : 0.01f * v3;
                    p[mi * 2]     += v0 * sWc2[col * ACT + ia] + v1 * sWc2[(col + 1) * ACT + ia];
                    p[mi * 2 + 1] += v2 * sWc2[col * ACT + ib] + v3 * sWc2[(col + 1) * ACT + ib];
                }
            }
#pragma unroll
            for (int q = 0; q < 4; q++) {
                p[q] += __shfl_xor_sync(0xffffffffu, p[q], 1);
                p[q] += __shfl_xor_sync(0xffffffffu, p[q], 2);
            }
            int nh = wid >> 2;
            if (tg == 0) {
                sQred[nh][wm + gr]      = p[0];
                sQred[nh][wm + gr + 8]  = p[1];
                sQred[nh][wm + gr + 16] = p[2];
                sQred[nh][wm + gr + 24] = p[3];
            }
            __syncthreads();
            if (tid < 128) {
                float q = sQred[0][tid] + sQred[1][tid] + bc2[a * ACT + sIdx[tid]];
                outq[(long)a * BATCH + mBase + tid] = q;
            }
            return;
        }
    }

#pragma unroll
    for (int mi = 0; mi < 2; mi++) {
        long row0 = mBase + wm + mi * 16 + gr;
        long row1 = row0 + 8;
#pragma unroll
        for (int ni = 0; ni < 2 * NI4; ni++) {
            int col = colBase + wn + ni * 8 + tg * 2;
            float b0 = 0.f, b1 = 0.f;
            if (biasL) {
                const float* bp = biasL + (long)a * sBias + col;
                b0 = bp[0]; b1 = bp[1];
            }
            float v0 = acc[mi][ni][0] + b0;
            float v1 = acc[mi][ni][1] + b1;
            float v2 = acc[mi][ni][2] + b0;
            float v3 = acc[mi][ni][3] + b1;
            if (col >= actF) {
                v0 = v0 > 0.f ? v0 : 0.01f * v0;
                v2 = v2 > 0.f ? v2 : 0.01f * v2;
            }
            if (col + 1 >= actF) {
                v1 = v1 > 0.f ? v1 : 0.01f * v1;
                v3 = v3 > 0.f ? v3 : 0.01f * v3;
            }
            if (outHalf) {
                long o0 = (long)a * sCout + row0 * ldcL + col;
                long o1 = (long)a * sCout + row1 * ldcL + col;
                __half h0 = __float2half_rn(v0), h1 = __float2half_rn(v1);
                __half h2 = __float2half_rn(v2), h3 = __float2half_rn(v3);
                *(uint32_t*)(Ch + o0) = (uint32_t)__half_as_ushort(h0) |
                                        ((uint32_t)__half_as_ushort(h1) << 16);
                *(uint32_t*)(Ch + o1) = (uint32_t)__half_as_ushort(h2) |
                                        ((uint32_t)__half_as_ushort(h3) << 16);
                *(uint32_t*)(Cl + o0) = pack_h2(v0 - __half2float(h0), v1 - __half2float(h1));
                *(uint32_t*)(Cl + o1) = pack_h2(v2 - __half2float(h2), v3 - __half2float(h3));
            } else {
                float* Cp = Cout + (long)a * sCout;
                *(float2*)(Cp + row0 * ldcL + col) = make_float2(v0, v1);
                *(float2*)(Cp + row1 * ldcL + col) = make_float2(v2, v3);
            }
        }
    }
}

// ---------------- attention: one warp per (head, agent_i, batch) --------------
__global__ void attn_kernel(const float* __restrict__ KV, const float* __restrict__ St,
                            __half* __restrict__ oH, __half* __restrict__ oL)
{
    int gw   = blockIdx.x * 8 + (threadIdx.x >> 5);
    int lane = threadIdx.x & 31;
    int b = gw >> 6;
    int r = gw & 63;
    int n = r >> 4;
    int i = r & 15;
    int col = n * DHEAD + lane;

    float selv = St[((long)i * BATCH + b) * HID + col];
    float lg = -3e38f;
#pragma unroll
    for (int j = 0; j < 16; j++) {
        float p = selv * KV[((long)j * BATCH + b) * 256 + col];
#pragma unroll
        for (int off = 16; off; off >>= 1) p += __shfl_xor_sync(0xffffffffu, p, off);
        if (lane == j) lg = (j == i) ? -1e9f : p * 0.17677669529663687f;
    }
    float mx = lg;
#pragma unroll
    for (int off = 16; off; off >>= 1) mx = fmaxf(mx, __shfl_xor_sync(0xffffffffu, mx, off));
    float e = (lane < 16) ? __expf(lg - mx) : 0.f;
    float den = e;
#pragma unroll
    for (int off = 16; off; off >>= 1) den += __shfl_xor_sync(0xffffffffu, den, off);
    float w = e / den;

    float acc = 0.f;
#pragma unroll
    for (int j = 0; j < 16; j++) {
        float wj = __shfl_sync(0xffffffffu, w, j);
        acc = fmaf(wj, KV[((long)j * BATCH + b) * 256 + 128 + col], acc);
    }
    long o = ((long)i * BATCH + b) * HID + col;
    __half h = __float2half_rn(acc);
    oH[o] = h;
    oL[o] = __float2half_rn(acc - __half2float(h));
}

// ---------------- launch -------------------------------------------------------
static float* symaddr(const void* sym)
{
    void* p = nullptr;
    cudaGetSymbolAddress(&p, sym);
    return (float*)p;
}
static __half* symaddr_h(const void* sym)
{
    void* p = nullptr;
    cudaGetSymbolAddress(&p, sym);
    return (__half*)p;
}

extern "C" void kernel_launch(void* const* d_in, const int* in_sizes, int n_in,
                              void* d_out, int out_size)
{
    const float* obs     = (const float*)d_in[0];
    const float* actions = (const float*)d_in[1];
    const float* W_sa    = (const float*)d_in[2];
    const float* b_sa    = (const float*)d_in[3];
    const float* W_s     = (const float*)d_in[4];
    const float* b_s     = (const float*)d_in[5];
    const float* Wk      = (const float*)d_in[6];
    const float* Wsel    = (const float*)d_in[7];
    const float* Wv      = (const float*)d_in[8];
    const float* bv      = (const float*)d_in[9];
    const float* Wc1     = (const float*)d_in[10];
    const float* bc1     = (const float*)d_in[11];
    const float* Wc2     = (const float*)d_in[12];
    const float* bc2     = (const float*)d_in[13];
    float* out = (float*)d_out;

    float* ps    = symaddr(g_ps);
    float* ps2   = symaddr(g_ps2);
    float* mean  = symaddr(g_mean);
    float* istd  = symaddr(g_istd);
    float* b1    = symaddr(g_b1);
    float* bkv   = symaddr(g_bkv);
    float* KV    = symaddr(g_KV);
    float* St    = symaddr(g_S);

    __half* w1h  = symaddr_h(w1_h);
    __half* kvh  = symaddr_h(wkv_h);
    __half* selh = symaddr_h(wsel_h);
    __half* c1h  = symaddr_h(wc1_h);
    __half* obsH = symaddr_h(g_obsH);
    __half* obsL = symaddr_h(g_obsL);
    __half* actH = symaddr_h(g_actH);
    __half* actL = symaddr_h(g_actL);
    __half* aseH = symaddr_h(g_aseH);
    __half* aseL = symaddr_h(g_aseL);
    __half* othH = symaddr_h(g_othH);
    __half* othL = symaddr_h(g_othL);

    const size_t smem64  = 2 * (2 * PLANE_B + 64 * STRIDE * 2);    // 51200
    const size_t smem128 = 2 * (2 * PLANE_B + 128 * STRIDE * 2);   // 61440

    static bool attr_set = false;
    if (!attr_set) {
        cudaFuncSetAttribute(gemm_mma<64, 3>,  cudaFuncAttributeMaxDynamicSharedMemorySize, smem64);
        cudaFuncSetAttribute(gemm_mma<128, 2>, cudaFuncAttributeMaxDynamicSharedMemorySize, smem128);
        attr_set = true;
    }

    const long sOBS = (long)BATCH * OBS;
    const long sACT = (long)BATCH * ACT;
    const long sASE = (long)BATCH * 256;
    const long sH   = (long)BATCH * HID;

    // 0
    bn_part_kernel<<<dim3(AGENTS, 5, 8), dim3(32, 32)>>>(obs, actions, ps, ps2,
                                                          obsH, obsL, actH, actL);
    // 1
    bn_fin_kernel<<<AGENTS, 160>>>(ps, ps2, mean, istd);
    // 2
    prep_all<<<dim3(160, 5, AGENTS), 256>>>(W_sa, b_sa, W_s, b_s, Wk, Wsel, Wv, bv,
                                            Wc1, mean, istd,
                                            w1h, kvh, selh, c1h, b1, bkv);

    // 3: ase = lrelu(bn([obs|act]) @ [W_sa|W_s] + b1)  K=144->160, N=256 (4 x 64)
    gemm_mma<64, 3><<<dim3(BATCH / 128, 4, AGENTS), 256, smem64>>>(
        obsH, obsL, sOBS, OBS, actH, actL, sACT, ACT, OBS, INP,
        w1h, (long)256 * 160, 160,
        b1, 256, nullptr, sASE, 256, 0,
        1, aseH, aseL,
        1 << 28, nullptr, nullptr, 0,
        0, nullptr, nullptr, nullptr, nullptr);

    // 4: merged KV + Sel.  y<4: KV = sa @ [Wk|Wv] (N=256); y>=4: S = se @ Wsel (N=128)
    gemm_mma<64, 3><<<dim3(BATCH / 128, 6, AGENTS), 256, smem64>>>(
        aseH, aseL, sASE, 256, aseH, aseL, 0, 0, 1 << 30, HID,
        kvh, 0, HID,
        bkv, 0, KV, sASE, 256, 128,
        0, nullptr, nullptr,
        4, selh, St, sH,
        0, nullptr, nullptr, nullptr, nullptr);

    // 5: attention -> other (fp16 pair)
    attn_kernel<<<(BATCH * 64) / 8, 256>>>(KV, St, othH, othL);

    // 6: q = fused( lrelu([se|other] @ Wc1 + bc1) . Wc2[:,argmax] + bc2 )  K=256
    gemm_mma<128, 2><<<dim3(BATCH / 128, 1, AGENTS), 256, smem128>>>(
        aseH + 128, aseL + 128, sASE, 256, othH, othL, sH, HID, HID, 2 * HID,
        c1h, (long)HID * 2 * HID, 2 * HID,
        bc1, HID, nullptr, 0, 0, 1 << 30,
        0, nullptr, nullptr,
        1 << 28, nullptr, nullptr, 0,
        1, actions, Wc2, bc2, out);
}

// round 11
// speedup vs baseline: 1.1323x; 1.1003x over previous
#include <cuda_runtime.h>
#include <cuda_fp16.h>
#include <cstdint>

#define AGENTS 16
#define BATCH  8192
#define OBS    128
#define ACT    16
#define HID    128
#define NHEAD  4
#define DHEAD  32
#define INP    (OBS + ACT)   // 144

#define CHUNK  32
#define STRIDE (CHUNK + 8)   // 40
#define PLANE_B (128 * STRIDE * 2)   // A plane bytes: 10240

// ---------------- scratch (static device globals; no runtime alloc) -----------
__device__ float g_ps [AGENTS * 160 * 8];
__device__ float g_ps2[AGENTS * 160 * 8];
__device__ float g_mean[AGENTS * INP];
__device__ float g_istd[AGENTS * INP];
__device__ float g_b1  [AGENTS * 256];       // [bsaf | bsf]
__device__ float g_bkv [256];                // [0 | bv]
// fp16 weight images (hi only), [n][Kpad] row-major (B^T)
__device__ __half w1_h [(long)AGENTS * 256 * 160];
__device__ __half wkv_h[256 * HID];
__device__ __half wsel_h[HID * HID];
__device__ __half wc1_h[(long)AGENTS * HID * 2 * HID];
// fp16 hi/lo activation planes
__device__ __half g_obsH[(long)AGENTS * BATCH * OBS];
__device__ __half g_obsL[(long)AGENTS * BATCH * OBS];
__device__ __half g_actH[(long)AGENTS * BATCH * ACT];
__device__ __half g_actL[(long)AGENTS * BATCH * ACT];
__device__ __half g_aseH[(long)AGENTS * BATCH * 256];   // [sa | se]
__device__ __half g_aseL[(long)AGENTS * BATCH * 256];
__device__ __half g_othH[(long)AGENTS * BATCH * HID];
__device__ __half g_othL[(long)AGENTS * BATCH * HID];
// fp32 buffers for attention inputs
__device__ float g_KV   [(long)AGENTS * BATCH * 256];   // [K | V]
__device__ float g_S    [(long)AGENTS * BATCH * HID];

// ---------------- helpers ------------------------------------------------------
__device__ __forceinline__ uint32_t smem_u32(const void* p) {
    uint32_t r;
    asm("{ .reg .u64 t; cvta.to.shared.u64 t, %1; cvt.u32.u64 %0, t; }" : "=r"(r) : "l"(p));
    return r;
}
__device__ __forceinline__ void ldm_x4(uint32_t* r, uint32_t addr) {
    asm volatile("ldmatrix.sync.aligned.m8n8.x4.shared.b16 {%0,%1,%2,%3}, [%4];"
                 : "=r"(r[0]), "=r"(r[1]), "=r"(r[2]), "=r"(r[3]) : "r"(addr));
}
__device__ __forceinline__ void mma_f16(float* c, const uint32_t* a, uint32_t b0, uint32_t b1) {
    asm volatile("mma.sync.aligned.m16n8k16.row.col.f32.f16.f16.f32 "
                 "{%0,%1,%2,%3}, {%4,%5,%6,%7}, {%8,%9}, {%0,%1,%2,%3};"
                 : "+f"(c[0]), "+f"(c[1]), "+f"(c[2]), "+f"(c[3])
                 : "r"(a[0]), "r"(a[1]), "r"(a[2]), "r"(a[3]), "r"(b0), "r"(b1));
}
__device__ __forceinline__ void cp16(uint32_t dst, const void* src) {
    asm volatile("cp.async.cg.shared.global [%0], [%1], 16;" :: "r"(dst), "l"(src));
}
__device__ __forceinline__ void cp16p(uint32_t dst, const void* src, int ok) {
    asm volatile("{\n\t.reg .pred p;\n\tsetp.ne.b32 p, %2, 0;\n\t"
                 "@p cp.async.cg.shared.global [%0], [%1], 16;\n\t"
                 "@!p cp.async.cg.shared.global [%0], [%1], 16, 0;\n\t}"
                 :: "r"(dst), "l"(src), "r"(ok));
}
__device__ __forceinline__ void cp_commit() { asm volatile("cp.async.commit_group;" ::: "memory"); }
__device__ __forceinline__ void cp_wait1()  { asm volatile("cp.async.wait_group 1;" ::: "memory"); }
__device__ __forceinline__ void cp_wait0()  { asm volatile("cp.async.wait_group 0;" ::: "memory"); }
__device__ __forceinline__ uint32_t pack_h2(float x, float y) {
    __half hx = __float2half_rn(x), hy = __float2half_rn(y);
    return (uint32_t)__half_as_ushort(hx) | ((uint32_t)__half_as_ushort(hy) << 16);
}

// ---------------- BN pass 1: partial sums + fp16 split planes ------------------
__global__ void bn_part_kernel(const float* __restrict__ obs,
                               const float* __restrict__ actions,
                               float* __restrict__ ps, float* __restrict__ ps2,
                               __half* __restrict__ oH, __half* __restrict__ oL,
                               __half* __restrict__ aH, __half* __restrict__ aL)
{
    int a = blockIdx.x;
    int f = blockIdx.y * 32 + threadIdx.x;
    int seg = blockIdx.z;
    float s = 0.f, s2 = 0.f;
    if (f < INP) {
        if (f < OBS) {
            long base = (long)a * BATCH * OBS + (long)seg * 1024 * OBS + f;
            const float* src = obs + base;
            for (int b = threadIdx.y; b < 1024; b += 32) {
                float x = src[(long)b * OBS]; s += x; s2 += x * x;
                __half h = __float2half_rn(x);
                oH[base + (long)b * OBS] = h;
                oL[base + (long)b * OBS] = __float2half_rn(x - __half2float(h));
            }
        } else {
            long base = (long)a * BATCH * ACT + (long)seg * 1024 * ACT + (f - OBS);
            const float* src = actions + base;
            for (int b = threadIdx.y; b < 1024; b += 32) {
                float x = src[(long)b * ACT]; s += x; s2 += x * x;
                __half h = __float2half_rn(x);
                aH[base + (long)b * ACT] = h;
                aL[base + (long)b * ACT] = __float2half_rn(x - __half2float(h));
            }
        }
    }
    __shared__ float sh1[32][33];
    __shared__ float sh2[32][33];
    sh1[threadIdx.y][threadIdx.x] = s;
    sh2[threadIdx.y][threadIdx.x] = s2;
    __syncthreads();
    for (int st = 16; st > 0; st >>= 1) {
        if (threadIdx.y < st) {
            sh1[threadIdx.y][threadIdx.x] += sh1[threadIdx.y + st][threadIdx.x];
            sh2[threadIdx.y][threadIdx.x] += sh2[threadIdx.y + st][threadIdx.x];
        }
        __syncthreads();
    }
    if (threadIdx.y == 0) {
        int fi = blockIdx.y * 32 + threadIdx.x;
        ps [(a * 160 + fi) * 8 + seg] = sh1[0][threadIdx.x];
        ps2[(a * 160 + fi) * 8 + seg] = sh2[0][threadIdx.x];
    }
}

// ---------------- BN pass 2 -----------------------------------------------------
__global__ void bn_fin_kernel(const float* __restrict__ ps, const float* __restrict__ ps2,
                              float* __restrict__ mean, float* __restrict__ istd)
{
    int a = blockIdx.x;
    int f = threadIdx.x;
    if (f >= INP) return;
    float s = 0.f, s2 = 0.f;
    for (int seg = 0; seg < 8; seg++) {
        s  += ps [(a * 160 + f) * 8 + seg];
        s2 += ps2[(a * 160 + f) * 8 + seg];
    }
    float m = s * (1.0f / BATCH);
    float v = s2 * (1.0f / BATCH) - m * m;
    mean[a * INP + f] = m;
    istd[a * INP + f] = rsqrtf(v + 1e-5f);
}

// ---------------- prep_all: BN-folded fp16 weight images + biases --------------
__global__ void prep_all(const float* __restrict__ W_sa, const float* __restrict__ b_sa,
                         const float* __restrict__ W_s,  const float* __restrict__ b_s,
                         const float* __restrict__ Wk, const float* __restrict__ Wsel,
                         const float* __restrict__ Wv, const float* __restrict__ bv,
                         const float* __restrict__ Wc1,
                         const float* __restrict__ mean, const float* __restrict__ istd,
                         __half* __restrict__ w1h, __half* __restrict__ kvh,
                         __half* __restrict__ selh, __half* __restrict__ c1h,
                         float* __restrict__ b1, float* __restrict__ bkv)
{
    int img = blockIdx.y;
    int a = blockIdx.z;
    int e = blockIdx.x * 256 + threadIdx.x;

    if (img == 0) {
        if (e >= 256 * 160) return;
        int n = e / 160, k = e - n * 160;
        float v = 0.f;
        if (n < 128) { if (k < INP) v = W_sa[((long)a * INP + k) * HID + n] * istd[a * INP + k]; }
        else         { if (k < OBS) v = W_s [((long)a * OBS + k) * HID + (n - 128)] * istd[a * INP + k]; }
        w1h[(long)a * 256 * 160 + e] = __float2half_rn(v);
    } else if (img == 1) {
        if (a != 0 || e >= 256 * 128) return;
        int n = e >> 7, k = e & 127;
        float v = (n < 128) ? Wk[(((n >> 5) * HID) + k) * DHEAD + (n & 31)]
                            : Wv[((((n - 128) >> 5) * HID) + k) * DHEAD + ((n - 128) & 31)];
        kvh[e] = __float2half_rn(v);
    } else if (img == 2) {
        if (a != 0 || e >= 128 * 128) return;
        int n = e >> 7, k = e & 127;
        selh[e] = __float2half_rn(Wsel[(((n >> 5) * HID) + k) * DHEAD + (n & 31)]);
    } else if (img == 3) {
        if (e >= 128 * 256) return;
        int n = e >> 8, k = e & 255;
        c1h[(long)a * 128 * 256 + e] = __float2half_rn(Wc1[((long)a * 2 * HID + k) * HID + n]);
    } else {
        if (blockIdx.x != 0) return;
        int n = threadIdx.x;   // 0..255
        float acc = 0.f;
        if (n < 128) {
            for (int k = 0; k < INP; k++)
                acc += mean[a * INP + k] * istd[a * INP + k] * W_sa[((long)a * INP + k) * HID + n];
            b1[a * 256 + n] = b_sa[a * HID + n] - acc;
        } else {
            for (int k = 0; k < OBS; k++)
                acc += mean[a * INP + k] * istd[a * INP + k] * W_s[((long)a * OBS + k) * HID + (n - 128)];
            b1[a * 256 + n] = b_s[a * HID + (n - 128)] - acc;
        }
        if (a == 0) bkv[n] = (n < 128) ? 0.f : bv[n - 128];
    }
}

// ---------------- tensor-core GEMM (fp16 2-term split, fp32 accum) -------------
// TN=128, 2-stage cp.async pipeline (R8-proven config).
// selFrom: grid.y >= selFrom switches to (A+128 cols, B2 image, C2 output).
template<int TN, int MINB>
__global__ void __launch_bounds__(256, MINB) gemm_mma(
    const __half* __restrict__ A0h, const __half* __restrict__ A0l, long sA0, int lda0,
    const __half* __restrict__ A1h, const __half* __restrict__ A1l, long sA1, int lda1,
    int ksplit, int Kreal,
    const __half* __restrict__ Bh_, long sB, int Kpad,
    const float* __restrict__ bias, long sBias,
    float* __restrict__ C, long sC, int ldc, int actFrom,
    int outHalf, __half* __restrict__ Ch, __half* __restrict__ Cl,
    int selFrom, const __half* __restrict__ B2h, float* __restrict__ C2, long sC2,
    int fuseFinal, const float* __restrict__ actions, const float* __restrict__ Wc2,
    const float* __restrict__ bc2, float* __restrict__ outq)
{
    constexpr int BPL_B = TN * STRIDE * 2;          // B plane bytes
    constexpr int BUFB  = 2 * PLANE_B + BPL_B;      // stage bytes
    constexpr int NI4   = TN / 32;                  // 16-col tiles per warp
    constexpr int WNW   = TN / 2;                   // warp n width

    extern __shared__ __half sm[];
    __shared__ float sWc2[HID * ACT];
    __shared__ int   sIdx[128];
    __shared__ float sQred[2][128];

    int tid = threadIdx.x, wid = tid >> 5, lane = tid & 31;
    int a = blockIdx.z;
    long mBase = (long)blockIdx.x * 128;
    int wm = (wid & 3) * 32;
    int wn = (wid >> 2) * WNW;

    // per-y routing
    int colBase = blockIdx.y * TN;
    int aOff = 0;
    const __half* bhP = Bh_;
    float* Cout = C;
    long sCout = sC;
    int ldcL = ldc;
    const float* biasL = bias;
    int actF = actFrom;
    if ((int)blockIdx.y >= selFrom) {
        aOff = 128; bhP = B2h; colBase = (blockIdx.y - selFrom) * TN;
        Cout = C2; sCout = sC2; ldcL = 128; biasL = nullptr; actF = 1 << 30;
    }
    bhP += (long)a * sB;

    if (fuseFinal) {
        for (int i = tid; i < HID * ACT; i += 256)
            sWc2[i] = Wc2[(long)a * HID * ACT + i];
        if (tid < 128) {
            const float* ap = actions + ((long)a * BATCH + mBase + tid) * ACT;
            float best = ap[0]; int bi = 0;
#pragma unroll
            for (int j = 1; j < ACT; j++) {
                float x = ap[j];
                if (x > best) { best = x; bi = j; }
            }
            sIdx[tid] = bi;
        }
    }

    float acc[2][2 * NI4][4];
#pragma unroll
    for (int i = 0; i < 2; i++)
#pragma unroll
        for (int j = 0; j < 2 * NI4; j++)
#pragma unroll
            for (int q = 0; q < 4; q++) acc[i][j][q] = 0.f;

    uint32_t smB = smem_u32(sm);
    int nChunks = Kpad / CHUNK;

    // hoisted compute-side in-buffer byte offsets
    int lr16 = lane & 15, lh16 = (lane >> 4) * 8;
    int lr8 = lane & 7, lk8 = ((lane >> 3) & 1) * 8, ln8 = (lane >> 4) * 8;
    uint32_t aHoff[2], bOff[NI4];
#pragma unroll
    for (int mi = 0; mi < 2; mi++)
        aHoff[mi] = (uint32_t)(((wm + mi * 16 + lr16) * STRIDE + lh16) * 2);
#pragma unroll
    for (int ni4 = 0; ni4 < NI4; ni4++)
        bOff[ni4] = (uint32_t)(((wn + ni4 * 16 + ln8 + lr8) * STRIDE + lk8) * 2) + 2 * PLANE_B;

    auto issue = [&](int c, int buf) {
        uint32_t base = smB + (uint32_t)(buf * BUFB);
        uint32_t AhB = base, AlB = base + PLANE_B, BhB = base + 2 * PLANE_B;
        int k0 = c * CHUNK;
#pragma unroll
        for (int it = 0; it < 2; it++) {
            int i = tid + it * 256;
            int row = i >> 2, kk = (i & 3) * 8;
            int kg = k0 + kk;
            const __half *ph, *pl; int ok = 1;
            if (kg < ksplit) {
                long o = (long)a * sA0 + (mBase + row) * (long)lda0 + aOff + kg;
                ph = A0h + o; pl = A0l + o;
            } else if (kg < Kreal) {
                long o = (long)a * sA1 + (mBase + row) * (long)lda1 + (kg - ksplit);
                ph = A1h + o; pl = A1l + o;
            } else {
                ph = A0h; pl = A0l; ok = 0;
            }
            uint32_t d = (uint32_t)((row * STRIDE + kk) * 2);
            cp16p(AhB + d, ph, ok);
            cp16p(AlB + d, pl, ok);
        }
        for (int i = tid; i < TN * 4; i += 256) {
            int n = i >> 2, kk = (i & 3) * 8;
            long o = (long)(colBase + n) * Kpad + k0 + kk;
            cp16(BhB + (uint32_t)((n * STRIDE + kk) * 2), bhP + o);
        }
        cp_commit();
    };

    issue(0, 0);

    for (int c = 0; c < nChunks; c++) {
        if (c + 1 < nChunks) { issue(c + 1, (c + 1) & 1); cp_wait1(); }
        else                 { cp_wait0(); }
        __syncthreads();

        uint32_t base = smB + (uint32_t)((c & 1) * BUFB);
#pragma unroll
        for (int ks = 0; ks < CHUNK; ks += 16) {
            uint32_t ah[2][4], al[2][4];
#pragma unroll
            for (int mi = 0; mi < 2; mi++) {
                ldm_x4(ah[mi], base + aHoff[mi] + ks * 2);
                ldm_x4(al[mi], base + aHoff[mi] + PLANE_B + ks * 2);
            }
#pragma unroll
            for (int ni4 = 0; ni4 < NI4; ni4++) {
                uint32_t bh[4];
                ldm_x4(bh, base + bOff[ni4] + ks * 2);
#pragma unroll
                for (int mi = 0; mi < 2; mi++) {
                    mma_f16(acc[mi][ni4 * 2],     ah[mi], bh[0], bh[1]);
                    mma_f16(acc[mi][ni4 * 2 + 1], ah[mi], bh[2], bh[3]);
                    mma_f16(acc[mi][ni4 * 2],     al[mi], bh[0], bh[1]);
                    mma_f16(acc[mi][ni4 * 2 + 1], al[mi], bh[2], bh[3]);
                }
            }
        }
        __syncthreads();
    }

    // ---- epilogue ----
    int gr = lane >> 2, tg = lane & 3;

    if constexpr (TN == 128) {
        if (fuseFinal) {
            float p[4] = {0.f, 0.f, 0.f, 0.f};
#pragma unroll
            for (int mi = 0; mi < 2; mi++) {
                int ra = wm + mi * 16 + gr;
                int rb = ra + 8;
                int ia = sIdx[ra], ib = sIdx[rb];
#pragma unroll
                for (int ni = 0; ni < 2 * NI4; ni++) {
                    int col = wn + ni * 8 + tg * 2;
                    const float* bp = biasL + (long)a * sBias + col;
                    float b0 = bp[0], b1 = bp[1];
                    float v0 = acc[mi][ni][0] + b0;
                    float v1 = acc[mi][ni][1] + b1;
                    float v2 = acc[mi][ni][2] + b0;
                    float v3 = acc[mi][ni][3] + b1;
                    v0 = v0 > 0.f ? v0 : 0.01f * v0;
                    v1 = v1 > 0.f ? v1 : 0.01f * v1;
                    v2 = v2 > 0.f ? v2 : 0.01f * v2;
                    v3 = v3 > 0.f ? v3 : 0.01f * v3;
                    p[mi * 2]     += v0 * sWc2[col * ACT + ia] + v1 * sWc2[(col + 1) * ACT + ia];
                    p[mi * 2 + 1] += v2 * sWc2[col * ACT + ib] + v3 * sWc2[(col + 1) * ACT + ib];
                }
            }
#pragma unroll
            for (int q = 0; q < 4; q++) {
                p[q] += __shfl_xor_sync(0xffffffffu, p[q], 1);
                p[q] += __shfl_xor_sync(0xffffffffu, p[q], 2);
            }
            int nh = wid >> 2;
            if (tg == 0) {
                sQred[nh][wm + gr]      = p[0];
                sQred[nh][wm + gr + 8]  = p[1];
                sQred[nh][wm + gr + 16] = p[2];
                sQred[nh][wm + gr + 24] = p[3];
            }
            __syncthreads();
            if (tid < 128) {
                float q = sQred[0][tid] + sQred[1][tid] + bc2[a * ACT + sIdx[tid]];
                outq[(long)a * BATCH + mBase + tid] = q;
            }
            return;
        }
    }

#pragma unroll
    for (int mi = 0; mi < 2; mi++) {
        long row0 = mBase + wm + mi * 16 + gr;
        long row1 = row0 + 8;
#pragma unroll
        for (int ni = 0; ni < 2 * NI4; ni++) {
            int col = colBase + wn + ni * 8 + tg * 2;
            float b0 = 0.f, b1 = 0.f;
            if (biasL) {
                const float* bp = biasL + (long)a * sBias + col;
                b0 = bp[0]; b1 = bp[1];
            }
            float v0 = acc[mi][ni][0] + b0;
            float v1 = acc[mi][ni][1] + b1;
            float v2 = acc[mi][ni][2] + b0;
            float v3 = acc[mi][ni][3] + b1;
            if (col >= actF) {
                v0 = v0 > 0.f ? v0 : 0.01f * v0;
                v2 = v2 > 0.f ? v2 : 0.01f * v2;
            }
            if (col + 1 >= actF) {
                v1 = v1 > 0.f ? v1 : 0.01f * v1;
                v3 = v3 > 0.f ? v3 : 0.01f * v3;
            }
            if (outHalf) {
                long o0 = (long)a * sCout + row0 * ldcL + col;
                long o1 = (long)a * sCout + row1 * ldcL + col;
                __half h0 = __float2half_rn(v0), h1 = __float2half_rn(v1);
                __half h2 = __float2half_rn(v2), h3 = __float2half_rn(v3);
                *(uint32_t*)(Ch + o0) = (uint32_t)__half_as_ushort(h0) |
                                        ((uint32_t)__half_as_ushort(h1) << 16);
                *(uint32_t*)(Ch + o1) = (uint32_t)__half_as_ushort(h2) |
                                        ((uint32_t)__half_as_ushort(h3) << 16);
                *(uint32_t*)(Cl + o0) = pack_h2(v0 - __half2float(h0), v1 - __half2float(h1));
                *(uint32_t*)(Cl + o1) = pack_h2(v2 - __half2float(h2), v3 - __half2float(h3));
            } else {
                float* Cp = Cout + (long)a * sCout;
                *(float2*)(Cp + row0 * ldcL + col) = make_float2(v0, v1);
                *(float2*)(Cp + row1 * ldcL + col) = make_float2(v2, v3);
            }
        }
    }
}

// ---------------- attention: smem-tiled, one CTA per 2 batch indices ----------
// Warp = (b_local, head). K/V rows held in registers; 16 agent-i units per warp.
// Numerics identical to the previous per-warp version.
__global__ void __launch_bounds__(256) attn_kernel(
    const float* __restrict__ KV, const float* __restrict__ St,
    __half* __restrict__ oH, __half* __restrict__ oL)
{
    __shared__ float sKV[2][16][256];
    __shared__ float sS [2][16][128];

    int tid = threadIdx.x;
    long b0 = (long)blockIdx.x * 2;

    // coalesced tile loads (each element read once from L2/DRAM)
    for (int idx = tid; idx < 2048; idx += 256) {           // 2*16*64 float4
        int c4 = idx & 63;
        int row = idx >> 6;          // 0..31
        int b_l = row >> 4, j = row & 15;
        ((float4*)&sKV[b_l][j][0])[c4] =
            ((const float4*)(KV + ((long)j * BATCH + b0 + b_l) * 256))[c4];
    }
    for (int idx = tid; idx < 1024; idx += 256) {           // 2*16*32 float4
        int c4 = idx & 31;
        int row = idx >> 5;
        int b_l = row >> 4, j = row & 15;
        ((float4*)&sS[b_l][j][0])[c4] =
            ((const float4*)(St + ((long)j * BATCH + b0 + b_l) * 128))[c4];
    }
    __syncthreads();

    int wid = tid >> 5, lane = tid & 31;
    int b_l = wid >> 2, n = wid & 3;
    long b = b0 + b_l;
    int col = n * DHEAD + lane;

    float Kr[16], Vr[16];
#pragma unroll
    for (int j = 0; j < 16; j++) {
        Kr[j] = sKV[b_l][j][col];
        Vr[j] = sKV[b_l][j][128 + col];
    }

    for (int i = 0; i < 16; i++) {
        float selv = sS[b_l][i][col];
        float lg = -3e38f;
#pragma unroll
        for (int j = 0; j < 16; j++) {
            float p = selv * Kr[j];
#pragma unroll
            for (int off = 16; off; off >>= 1) p += __shfl_xor_sync(0xffffffffu, p, off);
            if (lane == j) lg = (j == i) ? -1e9f : p * 0.17677669529663687f;
        }
        float mx = lg;
#pragma unroll
        for (int off = 16; off; off >>= 1) mx = fmaxf(mx, __shfl_xor_sync(0xffffffffu, mx, off));
        float e = (lane < 16) ? __expf(lg - mx) : 0.f;
        float den = e;
#pragma unroll
        for (int off = 16; off; off >>= 1) den += __shfl_xor_sync(0xffffffffu, den, off);
        float w = e / den;

        float acc = 0.f;
#pragma unroll
        for (int j = 0; j < 16; j++) {
            float wj = __shfl_sync(0xffffffffu, w, j);
            acc = fmaf(wj, Vr[j], acc);
        }
        long o = ((long)i * BATCH + b) * HID + col;
        __half h = __float2half_rn(acc);
        oH[o] = h;
        oL[o] = __float2half_rn(acc - __half2float(h));
    }
}

// ---------------- launch -------------------------------------------------------
static float* symaddr(const void* sym)
{
    void* p = nullptr;
    cudaGetSymbolAddress(&p, sym);
    return (float*)p;
}
static __half* symaddr_h(const void* sym)
{
    void* p = nullptr;
    cudaGetSymbolAddress(&p, sym);
    return (__half*)p;
}

extern "C" void kernel_launch(void* const* d_in, const int* in_sizes, int n_in,
                              void* d_out, int out_size)
{
    const float* obs     = (const float*)d_in[0];
    const float* actions = (const float*)d_in[1];
    const float* W_sa    = (const float*)d_in[2];
    const float* b_sa    = (const float*)d_in[3];
    const float* W_s     = (const float*)d_in[4];
    const float* b_s     = (const float*)d_in[5];
    const float* Wk      = (const float*)d_in[6];
    const float* Wsel    = (const float*)d_in[7];
    const float* Wv      = (const float*)d_in[8];
    const float* bv      = (const float*)d_in[9];
    const float* Wc1     = (const float*)d_in[10];
    const float* bc1     = (const float*)d_in[11];
    const float* Wc2     = (const float*)d_in[12];
    const float* bc2     = (const float*)d_in[13];
    float* out = (float*)d_out;

    float* ps    = symaddr(g_ps);
    float* ps2   = symaddr(g_ps2);
    float* mean  = symaddr(g_mean);
    float* istd  = symaddr(g_istd);
    float* b1    = symaddr(g_b1);
    float* bkv   = symaddr(g_bkv);
    float* KV    = symaddr(g_KV);
    float* St    = symaddr(g_S);

    __half* w1h  = symaddr_h(w1_h);
    __half* kvh  = symaddr_h(wkv_h);
    __half* selh = symaddr_h(wsel_h);
    __half* c1h  = symaddr_h(wc1_h);
    __half* obsH = symaddr_h(g_obsH);
    __half* obsL = symaddr_h(g_obsL);
    __half* actH = symaddr_h(g_actH);
    __half* actL = symaddr_h(g_actL);
    __half* aseH = symaddr_h(g_aseH);
    __half* aseL = symaddr_h(g_aseL);
    __half* othH = symaddr_h(g_othH);
    __half* othL = symaddr_h(g_othL);

    const size_t smem128 = 2 * (2 * PLANE_B + 128 * STRIDE * 2);   // 61440

    static bool attr_set = false;
    if (!attr_set) {
        cudaFuncSetAttribute(gemm_mma<128, 2>, cudaFuncAttributeMaxDynamicSharedMemorySize, smem128);
        attr_set = true;
    }

    const long sOBS = (long)BATCH * OBS;
    const long sACT = (long)BATCH * ACT;
    const long sASE = (long)BATCH * 256;
    const long sH   = (long)BATCH * HID;

    // 0
    bn_part_kernel<<<dim3(AGENTS, 5, 8), dim3(32, 32)>>>(obs, actions, ps, ps2,
                                                          obsH, obsL, actH, actL);
    // 1
    bn_fin_kernel<<<AGENTS, 160>>>(ps, ps2, mean, istd);
    // 2
    prep_all<<<dim3(160, 5, AGENTS), 256>>>(W_sa, b_sa, W_s, b_s, Wk, Wsel, Wv, bv,
                                            Wc1, mean, istd,
                                            w1h, kvh, selh, c1h, b1, bkv);

    // 3: ase = lrelu(bn([obs|act]) @ [W_sa|W_s] + b1)  K=144->160, N=256 (2 x 128)
    gemm_mma<128, 2><<<dim3(BATCH / 128, 2, AGENTS), 256, smem128>>>(
        obsH, obsL, sOBS, OBS, actH, actL, sACT, ACT, OBS, INP,
        w1h, (long)256 * 160, 160,
        b1, 256, nullptr, sASE, 256, 0,
        1, aseH, aseL,
        1 << 28, nullptr, nullptr, 0,
        0, nullptr, nullptr, nullptr, nullptr);

    // 4: merged KV + Sel.  y<2: KV = sa @ [Wk|Wv] (N=256); y==2: S = se @ Wsel
    gemm_mma<128, 2><<<dim3(BATCH / 128, 3, AGENTS), 256, smem128>>>(
        aseH, aseL, sASE, 256, aseH, aseL, 0, 0, 1 << 30, HID,
        kvh, 0, HID,
        bkv, 0, KV, sASE, 256, 128,
        0, nullptr, nullptr,
        2, selh, St, sH,
        0, nullptr, nullptr, nullptr, nullptr);

    // 5: attention (smem-tiled) -> other (fp16 pair)
    attn_kernel<<<BATCH / 2, 256>>>(KV, St, othH, othL);

    // 6: q = fused( lrelu([se|other] @ Wc1 + bc1) . Wc2[:,argmax] + bc2 )  K=256
    gemm_mma<128, 2><<<dim3(BATCH / 128, 1, AGENTS), 256, smem128>>>(
        aseH + 128, aseL + 128, sASE, 256, othH, othL, sH, HID, HID, 2 * HID,
        c1h, (long)HID * 2 * HID, 2 * HID,
        bc1, HID, nullptr, 0, 0, 1 << 30,
        0, nullptr, nullptr,
        1 << 28, nullptr, nullptr, 0,
        1, actions, Wc2, bc2, out);
}

// round 12
// speedup vs baseline: 1.1350x; 1.0024x over previous
#include <cuda_runtime.h>
#include <cuda_fp16.h>
#include <cstdint>

#define AGENTS 16
#define BATCH  8192
#define OBS    128
#define ACT    16
#define HID    128
#define NHEAD  4
#define DHEAD  32
#define INP    (OBS + ACT)   // 144

#define CHUNK  32
#define STRIDE (CHUNK + 8)   // 40
#define PLANE_B (128 * STRIDE * 2)   // A plane bytes: 10240

// ---------------- scratch (static device globals; no runtime alloc) -----------
__device__ float g_ps [AGENTS * 160 * 8];
__device__ float g_ps2[AGENTS * 160 * 8];
__device__ float g_mean[AGENTS * INP];
__device__ float g_istd[AGENTS * INP];
__device__ float g_b1  [AGENTS * 256];       // [bsaf | bsf]
__device__ float g_bkv [256];                // [0 | bv]
// fp16 weight images (hi only), [n][Kpad] row-major (B^T)
__device__ __half w1_h [(long)AGENTS * 256 * 160];
__device__ __half wkv_h[256 * HID];
__device__ __half wsel_h[HID * HID];
__device__ __half wc1_h[(long)AGENTS * HID * 2 * HID];
// fp16 hi/lo activation planes
__device__ __half g_obsH[(long)AGENTS * BATCH * OBS];
__device__ __half g_obsL[(long)AGENTS * BATCH * OBS];
__device__ __half g_actH[(long)AGENTS * BATCH * ACT];
__device__ __half g_actL[(long)AGENTS * BATCH * ACT];
__device__ __half g_aseH[(long)AGENTS * BATCH * 256];   // [sa | se]
__device__ __half g_aseL[(long)AGENTS * BATCH * 256];
__device__ __half g_othH[(long)AGENTS * BATCH * HID];
__device__ __half g_othL[(long)AGENTS * BATCH * HID];
// fp32 buffers for attention inputs
__device__ float g_KV   [(long)AGENTS * BATCH * 256];   // [K | V]
__device__ float g_S    [(long)AGENTS * BATCH * HID];

// ---------------- helpers ------------------------------------------------------
__device__ __forceinline__ uint32_t smem_u32(const void* p) {
    uint32_t r;
    asm("{ .reg .u64 t; cvta.to.shared.u64 t, %1; cvt.u32.u64 %0, t; }" : "=r"(r) : "l"(p));
    return r;
}
__device__ __forceinline__ void ldm_x4(uint32_t* r, uint32_t addr) {
    asm volatile("ldmatrix.sync.aligned.m8n8.x4.shared.b16 {%0,%1,%2,%3}, [%4];"
                 : "=r"(r[0]), "=r"(r[1]), "=r"(r[2]), "=r"(r[3]) : "r"(addr));
}
__device__ __forceinline__ void mma_f16(float* c, const uint32_t* a, uint32_t b0, uint32_t b1) {
    asm volatile("mma.sync.aligned.m16n8k16.row.col.f32.f16.f16.f32 "
                 "{%0,%1,%2,%3}, {%4,%5,%6,%7}, {%8,%9}, {%0,%1,%2,%3};"
                 : "+f"(c[0]), "+f"(c[1]), "+f"(c[2]), "+f"(c[3])
                 : "r"(a[0]), "r"(a[1]), "r"(a[2]), "r"(a[3]), "r"(b0), "r"(b1));
}
__device__ __forceinline__ void cp16(uint32_t dst, const void* src) {
    asm volatile("cp.async.cg.shared.global [%0], [%1], 16;" :: "r"(dst), "l"(src));
}
__device__ __forceinline__ void cp16p(uint32_t dst, const void* src, int ok) {
    asm volatile("{\n\t.reg .pred p;\n\tsetp.ne.b32 p, %2, 0;\n\t"
                 "@p cp.async.cg.shared.global [%0], [%1], 16;\n\t"
                 "@!p cp.async.cg.shared.global [%0], [%1], 16, 0;\n\t}"
                 :: "r"(dst), "l"(src), "r"(ok));
}
__device__ __forceinline__ void cp_commit() { asm volatile("cp.async.commit_group;" ::: "memory"); }
__device__ __forceinline__ void cp_wait1()  { asm volatile("cp.async.wait_group 1;" ::: "memory"); }
__device__ __forceinline__ void cp_wait0()  { asm volatile("cp.async.wait_group 0;" ::: "memory"); }
__device__ __forceinline__ uint32_t pack_h2(float x, float y) {
    __half hx = __float2half_rn(x), hy = __float2half_rn(y);
    return (uint32_t)__half_as_ushort(hx) | ((uint32_t)__half_as_ushort(hy) << 16);
}

// ---------------- BN pass 1: partial sums + fp16 split planes ------------------
__global__ void bn_part_kernel(const float* __restrict__ obs,
                               const float* __restrict__ actions,
                               float* __restrict__ ps, float* __restrict__ ps2,
                               __half* __restrict__ oH, __half* __restrict__ oL,
                               __half* __restrict__ aH, __half* __restrict__ aL)
{
    int a = blockIdx.x;
    int f = blockIdx.y * 32 + threadIdx.x;
    int seg = blockIdx.z;
    float s = 0.f, s2 = 0.f;
    if (f < INP) {
        if (f < OBS) {
            long base = (long)a * BATCH * OBS + (long)seg * 1024 * OBS + f;
            const float* src = obs + base;
            for (int b = threadIdx.y; b < 1024; b += 32) {
                float x = src[(long)b * OBS]; s += x; s2 += x * x;
                __half h = __float2half_rn(x);
                oH[base + (long)b * OBS] = h;
                oL[base + (long)b * OBS] = __float2half_rn(x - __half2float(h));
            }
        } else {
            long base = (long)a * BATCH * ACT + (long)seg * 1024 * ACT + (f - OBS);
            const float* src = actions + base;
            for (int b = threadIdx.y; b < 1024; b += 32) {
                float x = src[(long)b * ACT]; s += x; s2 += x * x;
                __half h = __float2half_rn(x);
                aH[base + (long)b * ACT] = h;
                aL[base + (long)b * ACT] = __float2half_rn(x - __half2float(h));
            }
        }
    }
    __shared__ float sh1[32][33];
    __shared__ float sh2[32][33];
    sh1[threadIdx.y][threadIdx.x] = s;
    sh2[threadIdx.y][threadIdx.x] = s2;
    __syncthreads();
    for (int st = 16; st > 0; st >>= 1) {
        if (threadIdx.y < st) {
            sh1[threadIdx.y][threadIdx.x] += sh1[threadIdx.y + st][threadIdx.x];
            sh2[threadIdx.y][threadIdx.x] += sh2[threadIdx.y + st][threadIdx.x];
        }
        __syncthreads();
    }
    if (threadIdx.y == 0) {
        int fi = blockIdx.y * 32 + threadIdx.x;
        ps [(a * 160 + fi) * 8 + seg] = sh1[0][threadIdx.x];
        ps2[(a * 160 + fi) * 8 + seg] = sh2[0][threadIdx.x];
    }
}

// ---------------- BN pass 2 -----------------------------------------------------
__global__ void bn_fin_kernel(const float* __restrict__ ps, const float* __restrict__ ps2,
                              float* __restrict__ mean, float* __restrict__ istd)
{
    int a = blockIdx.x;
    int f = threadIdx.x;
    if (f >= INP) return;
    float s = 0.f, s2 = 0.f;
    for (int seg = 0; seg < 8; seg++) {
        s  += ps [(a * 160 + f) * 8 + seg];
        s2 += ps2[(a * 160 + f) * 8 + seg];
    }
    float m = s * (1.0f / BATCH);
    float v = s2 * (1.0f / BATCH) - m * m;
    mean[a * INP + f] = m;
    istd[a * INP + f] = rsqrtf(v + 1e-5f);
}

// ---------------- prep_all: BN-folded fp16 weight images + biases --------------
__global__ void prep_all(const float* __restrict__ W_sa, const float* __restrict__ b_sa,
                         const float* __restrict__ W_s,  const float* __restrict__ b_s,
                         const float* __restrict__ Wk, const float* __restrict__ Wsel,
                         const float* __restrict__ Wv, const float* __restrict__ bv,
                         const float* __restrict__ Wc1,
                         const float* __restrict__ mean, const float* __restrict__ istd,
                         __half* __restrict__ w1h, __half* __restrict__ kvh,
                         __half* __restrict__ selh, __half* __restrict__ c1h,
                         float* __restrict__ b1, float* __restrict__ bkv)
{
    int img = blockIdx.y;
    int a = blockIdx.z;
    int e = blockIdx.x * 256 + threadIdx.x;

    if (img == 0) {
        if (e >= 256 * 160) return;
        int n = e / 160, k = e - n * 160;
        float v = 0.f;
        if (n < 128) { if (k < INP) v = W_sa[((long)a * INP + k) * HID + n] * istd[a * INP + k]; }
        else         { if (k < OBS) v = W_s [((long)a * OBS + k) * HID + (n - 128)] * istd[a * INP + k]; }
        w1h[(long)a * 256 * 160 + e] = __float2half_rn(v);
    } else if (img == 1) {
        if (a != 0 || e >= 256 * 128) return;
        int n = e >> 7, k = e & 127;
        float v = (n < 128) ? Wk[(((n >> 5) * HID) + k) * DHEAD + (n & 31)]
                            : Wv[((((n - 128) >> 5) * HID) + k) * DHEAD + ((n - 128) & 31)];
        kvh[e] = __float2half_rn(v);
    } else if (img == 2) {
        if (a != 0 || e >= 128 * 128) return;
        int n = e >> 7, k = e & 127;
        selh[e] = __float2half_rn(Wsel[(((n >> 5) * HID) + k) * DHEAD + (n & 31)]);
    } else if (img == 3) {
        if (e >= 128 * 256) return;
        int n = e >> 8, k = e & 255;
        c1h[(long)a * 128 * 256 + e] = __float2half_rn(Wc1[((long)a * 2 * HID + k) * HID + n]);
    } else {
        if (blockIdx.x != 0) return;
        int n = threadIdx.x;   // 0..255
        float acc = 0.f;
        if (n < 128) {
            for (int k = 0; k < INP; k++)
                acc += mean[a * INP + k] * istd[a * INP + k] * W_sa[((long)a * INP + k) * HID + n];
            b1[a * 256 + n] = b_sa[a * HID + n] - acc;
        } else {
            for (int k = 0; k < OBS; k++)
                acc += mean[a * INP + k] * istd[a * INP + k] * W_s[((long)a * OBS + k) * HID + (n - 128)];
            b1[a * 256 + n] = b_s[a * HID + (n - 128)] - acc;
        }
        if (a == 0) bkv[n] = (n < 128) ? 0.f : bv[n - 128];
    }
}

// ---------------- tensor-core GEMM (fp16 2-term split, fp32 accum) -------------
// TN=128, 2-stage cp.async pipeline. MMA issue order: per half-pass, all hi MMAs
// (8 distinct accumulators) then all lo MMAs -> per-accumulator RAW distance 8.
template<int TN, int MINB>
__global__ void __launch_bounds__(256, MINB) gemm_mma(
    const __half* __restrict__ A0h, const __half* __restrict__ A0l, long sA0, int lda0,
    const __half* __restrict__ A1h, const __half* __restrict__ A1l, long sA1, int lda1,
    int ksplit, int Kreal,
    const __half* __restrict__ Bh_, long sB, int Kpad,
    const float* __restrict__ bias, long sBias,
    float* __restrict__ C, long sC, int ldc, int actFrom,
    int outHalf, __half* __restrict__ Ch, __half* __restrict__ Cl,
    int selFrom, const __half* __restrict__ B2h, float* __restrict__ C2, long sC2,
    int fuseFinal, const float* __restrict__ actions, const float* __restrict__ Wc2,
    const float* __restrict__ bc2, float* __restrict__ outq)
{
    constexpr int BPL_B = TN * STRIDE * 2;          // B plane bytes
    constexpr int BUFB  = 2 * PLANE_B + BPL_B;      // stage bytes
    constexpr int NI4   = TN / 32;                  // 16-col tiles per warp
    constexpr int WNW   = TN / 2;                   // warp n width

    extern __shared__ __half sm[];
    __shared__ float sWc2[HID * ACT];
    __shared__ int   sIdx[128];
    __shared__ float sQred[2][128];

    int tid = threadIdx.x, wid = tid >> 5, lane = tid & 31;
    int a = blockIdx.z;
    long mBase = (long)blockIdx.x * 128;
    int wm = (wid & 3) * 32;
    int wn = (wid >> 2) * WNW;

    // per-y routing
    int colBase = blockIdx.y * TN;
    int aOff = 0;
    const __half* bhP = Bh_;
    float* Cout = C;
    long sCout = sC;
    int ldcL = ldc;
    const float* biasL = bias;
    int actF = actFrom;
    if ((int)blockIdx.y >= selFrom) {
        aOff = 128; bhP = B2h; colBase = (blockIdx.y - selFrom) * TN;
        Cout = C2; sCout = sC2; ldcL = 128; biasL = nullptr; actF = 1 << 30;
    }
    bhP += (long)a * sB;

    if (fuseFinal) {
        for (int i = tid; i < HID * ACT; i += 256)
            sWc2[i] = Wc2[(long)a * HID * ACT + i];
        if (tid < 128) {
            const float* ap = actions + ((long)a * BATCH + mBase + tid) * ACT;
            float best = ap[0]; int bi = 0;
#pragma unroll
            for (int j = 1; j < ACT; j++) {
                float x = ap[j];
                if (x > best) { best = x; bi = j; }
            }
            sIdx[tid] = bi;
        }
    }

    float acc[2][2 * NI4][4];
#pragma unroll
    for (int i = 0; i < 2; i++)
#pragma unroll
        for (int j = 0; j < 2 * NI4; j++)
#pragma unroll
            for (int q = 0; q < 4; q++) acc[i][j][q] = 0.f;

    uint32_t smB = smem_u32(sm);
    int nChunks = Kpad / CHUNK;

    // hoisted compute-side in-buffer byte offsets
    int lr16 = lane & 15, lh16 = (lane >> 4) * 8;
    int lr8 = lane & 7, lk8 = ((lane >> 3) & 1) * 8, ln8 = (lane >> 4) * 8;
    uint32_t aHoff[2], bOff[NI4];
#pragma unroll
    for (int mi = 0; mi < 2; mi++)
        aHoff[mi] = (uint32_t)(((wm + mi * 16 + lr16) * STRIDE + lh16) * 2);
#pragma unroll
    for (int ni4 = 0; ni4 < NI4; ni4++)
        bOff[ni4] = (uint32_t)(((wn + ni4 * 16 + ln8 + lr8) * STRIDE + lk8) * 2) + 2 * PLANE_B;

    auto issue = [&](int c, int buf) {
        uint32_t base = smB + (uint32_t)(buf * BUFB);
        uint32_t AhB = base, AlB = base + PLANE_B, BhB = base + 2 * PLANE_B;
        int k0 = c * CHUNK;
#pragma unroll
        for (int it = 0; it < 2; it++) {
            int i = tid + it * 256;
            int row = i >> 2, kk = (i & 3) * 8;
            int kg = k0 + kk;
            const __half *ph, *pl; int ok = 1;
            if (kg < ksplit) {
                long o = (long)a * sA0 + (mBase + row) * (long)lda0 + aOff + kg;
                ph = A0h + o; pl = A0l + o;
            } else if (kg < Kreal) {
                long o = (long)a * sA1 + (mBase + row) * (long)lda1 + (kg - ksplit);
                ph = A1h + o; pl = A1l + o;
            } else {
                ph = A0h; pl = A0l; ok = 0;
            }
            uint32_t d = (uint32_t)((row * STRIDE + kk) * 2);
            cp16p(AhB + d, ph, ok);
            cp16p(AlB + d, pl, ok);
        }
        for (int i = tid; i < TN * 4; i += 256) {
            int n = i >> 2, kk = (i & 3) * 8;
            long o = (long)(colBase + n) * Kpad + k0 + kk;
            cp16(BhB + (uint32_t)((n * STRIDE + kk) * 2), bhP + o);
        }
        cp_commit();
    };

    issue(0, 0);

    for (int c = 0; c < nChunks; c++) {
        if (c + 1 < nChunks) { issue(c + 1, (c + 1) & 1); cp_wait1(); }
        else                 { cp_wait0(); }
        __syncthreads();

        uint32_t base = smB + (uint32_t)((c & 1) * BUFB);
#pragma unroll
        for (int ks = 0; ks < CHUNK; ks += 16) {
            uint32_t ah[2][4], al[2][4];
#pragma unroll
            for (int mi = 0; mi < 2; mi++) {
                ldm_x4(ah[mi], base + aHoff[mi] + ks * 2);
                ldm_x4(al[mi], base + aHoff[mi] + PLANE_B + ks * 2);
            }
#pragma unroll
            for (int half = 0; half < NI4 / 2; half++) {
                uint32_t bh[2][4];
                ldm_x4(bh[0], base + bOff[half * 2]     + ks * 2);
                ldm_x4(bh[1], base + bOff[half * 2 + 1] + ks * 2);
                // hi pass: 8 MMAs, 8 distinct accumulators
#pragma unroll
                for (int q = 0; q < 2; q++) {
                    int nb = (half * 2 + q) * 2;
#pragma unroll
                    for (int mi = 0; mi < 2; mi++) {
                        mma_f16(acc[mi][nb],     ah[mi], bh[q][0], bh[q][1]);
                        mma_f16(acc[mi][nb + 1], ah[mi], bh[q][2], bh[q][3]);
                    }
                }
                // lo pass: same accumulators, distance 8 from their hi use
#pragma unroll
                for (int q = 0; q < 2; q++) {
                    int nb = (half * 2 + q) * 2;
#pragma unroll
                    for (int mi = 0; mi < 2; mi++) {
                        mma_f16(acc[mi][nb],     al[mi], bh[q][0], bh[q][1]);
                        mma_f16(acc[mi][nb + 1], al[mi], bh[q][2], bh[q][3]);
                    }
                }
            }
        }
        __syncthreads();
    }

    // ---- epilogue ----
    int gr = lane >> 2, tg = lane & 3;

    if constexpr (TN == 128) {
        if (fuseFinal) {
            float p[4] = {0.f, 0.f, 0.f, 0.f};
#pragma unroll
            for (int mi = 0; mi < 2; mi++) {
                int ra = wm + mi * 16 + gr;
                int rb = ra + 8;
                int ia = sIdx[ra], ib = sIdx[rb];
#pragma unroll
                for (int ni = 0; ni < 2 * NI4; ni++) {
                    int col = wn + ni * 8 + tg * 2;
                    const float* bp = biasL + (long)a * sBias + col;
                    float b0 = bp[0], b1 = bp[1];
                    float v0 = acc[mi][ni][0] + b0;
                    float v1 = acc[mi][ni][1] + b1;
                    float v2 = acc[mi][ni][2] + b0;
                    float v3 = acc[mi][ni][3] + b1;
                    v0 = v0 > 0.f ? v0 : 0.01f * v0;
                    v1 = v1 > 0.f ? v1 : 0.01f * v1;
                    v2 = v2 > 0.f ? v2 : 0.01f * v2;
                    v3 = v3 > 0.f ? v3 : 0.01f * v3;
                    p[mi * 2]     += v0 * sWc2[col * ACT + ia] + v1 * sWc2[(col + 1) * ACT + ia];
                    p[mi * 2 + 1] += v2 * sWc2[col * ACT + ib] + v3 * sWc2[(col + 1) * ACT + ib];
                }
            }
#pragma unroll
            for (int q = 0; q < 4; q++) {
                p[q] += __shfl_xor_sync(0xffffffffu, p[q], 1);
                p[q] += __shfl_xor_sync(0xffffffffu, p[q], 2);
            }
            int nh = wid >> 2;
            if (tg == 0) {
                sQred[nh][wm + gr]      = p[0];
                sQred[nh][wm + gr + 8]  = p[1];
                sQred[nh][wm + gr + 16] = p[2];
                sQred[nh][wm + gr + 24] = p[3];
            }
            __syncthreads();
            if (tid < 128) {
                float q = sQred[0][tid] + sQred[1][tid] + bc2[a * ACT + sIdx[tid]];
                outq[(long)a * BATCH + mBase + tid] = q;
            }
            return;
        }
    }

#pragma unroll
    for (int mi = 0; mi < 2; mi++) {
        long row0 = mBase + wm + mi * 16 + gr;
        long row1 = row0 + 8;
#pragma unroll
        for (int ni = 0; ni < 2 * NI4; ni++) {
            int col = colBase + wn + ni * 8 + tg * 2;
            float b0 = 0.f, b1 = 0.f;
            if (biasL) {
                const float* bp = biasL + (long)a * sBias + col;
                b0 = bp[0]; b1 = bp[1];
            }
            float v0 = acc[mi][ni][0] + b0;
            float v1 = acc[mi][ni][1] + b1;
            float v2 = acc[mi][ni][2] + b0;
            float v3 = acc[mi][ni][3] + b1;
            if (col >= actF) {
                v0 = v0 > 0.f ? v0 : 0.01f * v0;
                v2 = v2 > 0.f ? v2 : 0.01f * v2;
            }
            if (col + 1 >= actF) {
                v1 = v1 > 0.f ? v1 : 0.01f * v1;
                v3 = v3 > 0.f ? v3 : 0.01f * v3;
            }
            if (outHalf) {
                long o0 = (long)a * sCout + row0 * ldcL + col;
                long o1 = (long)a * sCout + row1 * ldcL + col;
                __half h0 = __float2half_rn(v0), h1 = __float2half_rn(v1);
                __half h2 = __float2half_rn(v2), h3 = __float2half_rn(v3);
                *(uint32_t*)(Ch + o0) = (uint32_t)__half_as_ushort(h0) |
                                        ((uint32_t)__half_as_ushort(h1) << 16);
                *(uint32_t*)(Ch + o1) = (uint32_t)__half_as_ushort(h2) |
                                        ((uint32_t)__half_as_ushort(h3) << 16);
                *(uint32_t*)(Cl + o0) = pack_h2(v0 - __half2float(h0), v1 - __half2float(h1));
                *(uint32_t*)(Cl + o1) = pack_h2(v2 - __half2float(h2), v3 - __half2float(h3));
            } else {
                float* Cp = Cout + (long)a * sCout;
                *(float2*)(Cp + row0 * ldcL + col) = make_float2(v0, v1);
                *(float2*)(Cp + row1 * ldcL + col) = make_float2(v2, v3);
            }
        }
    }
}

// ---------------- attention: smem-tiled, one CTA per 2 batch indices ----------
__global__ void __launch_bounds__(256) attn_kernel(
    const float* __restrict__ KV, const float* __restrict__ St,
    __half* __restrict__ oH, __half* __restrict__ oL)
{
    __shared__ float sKV[2][16][256];
    __shared__ float sS [2][16][128];

    int tid = threadIdx.x;
    long b0 = (long)blockIdx.x * 2;

    for (int idx = tid; idx < 2048; idx += 256) {
        int c4 = idx & 63;
        int row = idx >> 6;
        int b_l = row >> 4, j = row & 15;
        ((float4*)&sKV[b_l][j][0])[c4] =
            ((const float4*)(KV + ((long)j * BATCH + b0 + b_l) * 256))[c4];
    }
    for (int idx = tid; idx < 1024; idx += 256) {
        int c4 = idx & 31;
        int row = idx >> 5;
        int b_l = row >> 4, j = row & 15;
        ((float4*)&sS[b_l][j][0])[c4] =
            ((const float4*)(St + ((long)j * BATCH + b0 + b_l) * 128))[c4];
    }
    __syncthreads();

    int wid = tid >> 5, lane = tid & 31;
    int b_l = wid >> 2, n = wid & 3;
    long b = b0 + b_l;
    int col = n * DHEAD + lane;

    float Kr[16], Vr[16];
#pragma unroll
    for (int j = 0; j < 16; j++) {
        Kr[j] = sKV[b_l][j][col];
        Vr[j] = sKV[b_l][j][128 + col];
    }

    for (int i = 0; i < 16; i++) {
        float selv = sS[b_l][i][col];
        float lg = -3e38f;
#pragma unroll
        for (int j = 0; j < 16; j++) {
            float p = selv * Kr[j];
#pragma unroll
            for (int off = 16; off; off >>= 1) p += __shfl_xor_sync(0xffffffffu, p, off);
            if (lane == j) lg = (j == i) ? -1e9f : p * 0.17677669529663687f;
        }
        float mx = lg;
#pragma unroll
        for (int off = 16; off; off >>= 1) mx = fmaxf(mx, __shfl_xor_sync(0xffffffffu, mx, off));
        float e = (lane < 16) ? __expf(lg - mx) : 0.f;
        float den = e;
#pragma unroll
        for (int off = 16; off; off >>= 1) den += __shfl_xor_sync(0xffffffffu, den, off);
        float w = e / den;

        float acc = 0.f;
#pragma unroll
        for (int j = 0; j < 16; j++) {
            float wj = __shfl_sync(0xffffffffu, w, j);
            acc = fmaf(wj, Vr[j], acc);
        }
        long o = ((long)i * BATCH + b) * HID + col;
        __half h = __float2half_rn(acc);
        oH[o] = h;
        oL[o] = __float2half_rn(acc - __half2float(h));
    }
}

// ---------------- launch -------------------------------------------------------
static float* symaddr(const void* sym)
{
    void* p = nullptr;
    cudaGetSymbolAddress(&p, sym);
    return (float*)p;
}
static __half* symaddr_h(const void* sym)
{
    void* p = nullptr;
    cudaGetSymbolAddress(&p, sym);
    return (__half*)p;
}

extern "C" void kernel_launch(void* const* d_in, const int* in_sizes, int n_in,
                              void* d_out, int out_size)
{
    const float* obs     = (const float*)d_in[0];
    const float* actions = (const float*)d_in[1];
    const float* W_sa    = (const float*)d_in[2];
    const float* b_sa    = (const float*)d_in[3];
    const float* W_s     = (const float*)d_in[4];
    const float* b_s     = (const float*)d_in[5];
    const float* Wk      = (const float*)d_in[6];
    const float* Wsel    = (const float*)d_in[7];
    const float* Wv      = (const float*)d_in[8];
    const float* bv      = (const float*)d_in[9];
    const float* Wc1     = (const float*)d_in[10];
    const float* bc1     = (const float*)d_in[11];
    const float* Wc2     = (const float*)d_in[12];
    const float* bc2     = (const float*)d_in[13];
    float* out = (float*)d_out;

    float* ps    = symaddr(g_ps);
    float* ps2   = symaddr(g_ps2);
    float* mean  = symaddr(g_mean);
    float* istd  = symaddr(g_istd);
    float* b1    = symaddr(g_b1);
    float* bkv   = symaddr(g_bkv);
    float* KV    = symaddr(g_KV);
    float* St    = symaddr(g_S);

    __half* w1h  = symaddr_h(w1_h);
    __half* kvh  = symaddr_h(wkv_h);
    __half* selh = symaddr_h(wsel_h);
    __half* c1h  = symaddr_h(wc1_h);
    __half* obsH = symaddr_h(g_obsH);
    __half* obsL = symaddr_h(g_obsL);
    __half* actH = symaddr_h(g_actH);
    __half* actL = symaddr_h(g_actL);
    __half* aseH = symaddr_h(g_aseH);
    __half* aseL = symaddr_h(g_aseL);
    __half* othH = symaddr_h(g_othH);
    __half* othL = symaddr_h(g_othL);

    const size_t smem128 = 2 * (2 * PLANE_B + 128 * STRIDE * 2);   // 61440

    static bool attr_set = false;
    if (!attr_set) {
        cudaFuncSetAttribute(gemm_mma<128, 2>, cudaFuncAttributeMaxDynamicSharedMemorySize, smem128);
        attr_set = true;
    }

    const long sOBS = (long)BATCH * OBS;
    const long sACT = (long)BATCH * ACT;
    const long sASE = (long)BATCH * 256;
    const long sH   = (long)BATCH * HID;

    // 0
    bn_part_kernel<<<dim3(AGENTS, 5, 8), dim3(32, 32)>>>(obs, actions, ps, ps2,
                                                          obsH, obsL, actH, actL);
    // 1
    bn_fin_kernel<<<AGENTS, 160>>>(ps, ps2, mean, istd);
    // 2
    prep_all<<<dim3(160, 5, AGENTS), 256>>>(W_sa, b_sa, W_s, b_s, Wk, Wsel, Wv, bv,
                                            Wc1, mean, istd,
                                            w1h, kvh, selh, c1h, b1, bkv);

    // 3: ase = lrelu(bn([obs|act]) @ [W_sa|W_s] + b1)  K=144->160, N=256 (2 x 128)
    gemm_mma<128, 2><<<dim3(BATCH / 128, 2, AGENTS), 256, smem128>>>(
        obsH, obsL, sOBS, OBS, actH, actL, sACT, ACT, OBS, INP,
        w1h, (long)256 * 160, 160,
        b1, 256, nullptr, sASE, 256, 0,
        1, aseH, aseL,
        1 << 28, nullptr, nullptr, 0,
        0, nullptr, nullptr, nullptr, nullptr);

    // 4: merged KV + Sel.  y<2: KV = sa @ [Wk|Wv] (N=256); y==2: S = se @ Wsel
    gemm_mma<128, 2><<<dim3(BATCH / 128, 3, AGENTS), 256, smem128>>>(
        aseH, aseL, sASE, 256, aseH, aseL, 0, 0, 1 << 30, HID,
        kvh, 0, HID,
        bkv, 0, KV, sASE, 256, 128,
        0, nullptr, nullptr,
        2, selh, St, sH,
        0, nullptr, nullptr, nullptr, nullptr);

    // 5: attention (smem-tiled) -> other (fp16 pair)
    attn_kernel<<<BATCH / 2, 256>>>(KV, St, othH, othL);

    // 6: q = fused( lrelu([se|other] @ Wc1 + bc1) . Wc2[:,argmax] + bc2 )  K=256
    gemm_mma<128, 2><<<dim3(BATCH / 128, 1, AGENTS), 256, smem128>>>(
        aseH + 128, aseL + 128, sASE, 256, othH, othL, sH, HID, HID, 2 * HID,
        c1h, (long)HID * 2 * HID, 2 * HID,
        bc1, HID, nullptr, 0, 0, 1 << 30,
        0, nullptr, nullptr,
        1 << 28, nullptr, nullptr, 0,
        1, actions, Wc2, bc2, out);
}

// round 13
// speedup vs baseline: 1.1662x; 1.0275x over previous
#include <cuda_runtime.h>
#include <cuda_fp16.h>
#include <cstdint>

#define AGENTS 16
#define BATCH  8192
#define OBS    128
#define ACT    16
#define HID    128
#define NHEAD  4
#define DHEAD  32
#define INP    (OBS + ACT)   // 144

#define CHUNK  32
#define STRIDE (CHUNK + 8)   // 40
#define PLANE_B (128 * STRIDE * 2)   // A plane bytes: 10240

// ---------------- scratch (static device globals; no runtime alloc) -----------
__device__ float g_ps [AGENTS * 160 * 8];
__device__ float g_ps2[AGENTS * 160 * 8];
__device__ float g_mean[AGENTS * INP];
__device__ float g_istd[AGENTS * INP];
__device__ float g_b1  [AGENTS * 256];       // [bsaf | bsf]
__device__ float g_bkv [256];                // [0 | bv]
// fp16 weight images (hi only), [n][Kpad] row-major (B^T)
__device__ __half w1_h [(long)AGENTS * 256 * 160];
__device__ __half wkv_h[256 * HID];
__device__ __half wsel_h[HID * HID];
__device__ __half wc1_h[(long)AGENTS * HID * 2 * HID];
// fp16 hi/lo activation planes
__device__ __half g_obsH[(long)AGENTS * BATCH * OBS];
__device__ __half g_obsL[(long)AGENTS * BATCH * OBS];
__device__ __half g_actH[(long)AGENTS * BATCH * ACT];
__device__ __half g_actL[(long)AGENTS * BATCH * ACT];
__device__ __half g_aseH[(long)AGENTS * BATCH * 256];   // [sa | se]
__device__ __half g_aseL[(long)AGENTS * BATCH * 256];
__device__ __half g_othH[(long)AGENTS * BATCH * HID];
__device__ __half g_othL[(long)AGENTS * BATCH * HID];
// fp32 buffers for attention inputs
__device__ float g_KV   [(long)AGENTS * BATCH * 256];   // [K | V]
__device__ float g_S    [(long)AGENTS * BATCH * HID];

// ---------------- helpers ------------------------------------------------------
__device__ __forceinline__ uint32_t smem_u32(const void* p) {
    uint32_t r;
    asm("{ .reg .u64 t; cvta.to.shared.u64 t, %1; cvt.u32.u64 %0, t; }" : "=r"(r) : "l"(p));
    return r;
}
__device__ __forceinline__ void ldm_x4(uint32_t* r, uint32_t addr) {
    asm volatile("ldmatrix.sync.aligned.m8n8.x4.shared.b16 {%0,%1,%2,%3}, [%4];"
                 : "=r"(r[0]), "=r"(r[1]), "=r"(r[2]), "=r"(r[3]) : "r"(addr));
}
__device__ __forceinline__ void mma_f16(float* c, const uint32_t* a, uint32_t b0, uint32_t b1) {
    asm volatile("mma.sync.aligned.m16n8k16.row.col.f32.f16.f16.f32 "
                 "{%0,%1,%2,%3}, {%4,%5,%6,%7}, {%8,%9}, {%0,%1,%2,%3};"
                 : "+f"(c[0]), "+f"(c[1]), "+f"(c[2]), "+f"(c[3])
                 : "r"(a[0]), "r"(a[1]), "r"(a[2]), "r"(a[3]), "r"(b0), "r"(b1));
}
__device__ __forceinline__ void cp16(uint32_t dst, const void* src) {
    asm volatile("cp.async.cg.shared.global [%0], [%1], 16;" :: "r"(dst), "l"(src));
}
__device__ __forceinline__ void cp16p(uint32_t dst, const void* src, int ok) {
    asm volatile("{\n\t.reg .pred p;\n\tsetp.ne.b32 p, %2, 0;\n\t"
                 "@p cp.async.cg.shared.global [%0], [%1], 16;\n\t"
                 "@!p cp.async.cg.shared.global [%0], [%1], 16, 0;\n\t}"
                 :: "r"(dst), "l"(src), "r"(ok));
}
__device__ __forceinline__ void cp_commit() { asm volatile("cp.async.commit_group;" ::: "memory"); }
__device__ __forceinline__ void cp_wait1()  { asm volatile("cp.async.wait_group 1;" ::: "memory"); }
__device__ __forceinline__ void cp_wait0()  { asm volatile("cp.async.wait_group 0;" ::: "memory"); }
__device__ __forceinline__ uint32_t pack_h2(float x, float y) {
    __half hx = __float2half_rn(x), hy = __float2half_rn(y);
    return (uint32_t)__half_as_ushort(hx) | ((uint32_t)__half_as_ushort(hy) << 16);
}

// ---------------- BN pass 1: partial sums + fp16 split planes ------------------
__global__ void bn_part_kernel(const float* __restrict__ obs,
                               const float* __restrict__ actions,
                               float* __restrict__ ps, float* __restrict__ ps2,
                               __half* __restrict__ oH, __half* __restrict__ oL,
                               __half* __restrict__ aH, __half* __restrict__ aL)
{
    int a = blockIdx.x;
    int f = blockIdx.y * 32 + threadIdx.x;
    int seg = blockIdx.z;
    float s = 0.f, s2 = 0.f;
    if (f < INP) {
        if (f < OBS) {
            long base = (long)a * BATCH * OBS + (long)seg * 1024 * OBS + f;
            const float* src = obs + base;
            for (int b = threadIdx.y; b < 1024; b += 32) {
                float x = src[(long)b * OBS]; s += x; s2 += x * x;
                __half h = __float2half_rn(x);
                oH[base + (long)b * OBS] = h;
                oL[base + (long)b * OBS] = __float2half_rn(x - __half2float(h));
            }
        } else {
            long base = (long)a * BATCH * ACT + (long)seg * 1024 * ACT + (f - OBS);
            const float* src = actions + base;
            for (int b = threadIdx.y; b < 1024; b += 32) {
                float x = src[(long)b * ACT]; s += x; s2 += x * x;
                __half h = __float2half_rn(x);
                aH[base + (long)b * ACT] = h;
                aL[base + (long)b * ACT] = __float2half_rn(x - __half2float(h));
            }
        }
    }
    __shared__ float sh1[32][33];
    __shared__ float sh2[32][33];
    sh1[threadIdx.y][threadIdx.x] = s;
    sh2[threadIdx.y][threadIdx.x] = s2;
    __syncthreads();
    for (int st = 16; st > 0; st >>= 1) {
        if (threadIdx.y < st) {
            sh1[threadIdx.y][threadIdx.x] += sh1[threadIdx.y + st][threadIdx.x];
            sh2[threadIdx.y][threadIdx.x] += sh2[threadIdx.y + st][threadIdx.x];
        }
        __syncthreads();
    }
    if (threadIdx.y == 0) {
        int fi = blockIdx.y * 32 + threadIdx.x;
        ps [(a * 160 + fi) * 8 + seg] = sh1[0][threadIdx.x];
        ps2[(a * 160 + fi) * 8 + seg] = sh2[0][threadIdx.x];
    }
}

// ---------------- BN pass 2 -----------------------------------------------------
__global__ void bn_fin_kernel(const float* __restrict__ ps, const float* __restrict__ ps2,
                              float* __restrict__ mean, float* __restrict__ istd)
{
    int a = blockIdx.x;
    int f = threadIdx.x;
    if (f >= INP) return;
    float s = 0.f, s2 = 0.f;
    for (int seg = 0; seg < 8; seg++) {
        s  += ps [(a * 160 + f) * 8 + seg];
        s2 += ps2[(a * 160 + f) * 8 + seg];
    }
    float m = s * (1.0f / BATCH);
    float v = s2 * (1.0f / BATCH) - m * m;
    mean[a * INP + f] = m;
    istd[a * INP + f] = rsqrtf(v + 1e-5f);
}

// ---------------- prep_all: BN-folded fp16 weight images + biases --------------
__global__ void prep_all(const float* __restrict__ W_sa, const float* __restrict__ b_sa,
                         const float* __restrict__ W_s,  const float* __restrict__ b_s,
                         const float* __restrict__ Wk, const float* __restrict__ Wsel,
                         const float* __restrict__ Wv, const float* __restrict__ bv,
                         const float* __restrict__ Wc1,
                         const float* __restrict__ mean, const float* __restrict__ istd,
                         __half* __restrict__ w1h, __half* __restrict__ kvh,
                         __half* __restrict__ selh, __half* __restrict__ c1h,
                         float* __restrict__ b1, float* __restrict__ bkv)
{
    int img = blockIdx.y;
    int a = blockIdx.z;
    int e = blockIdx.x * 256 + threadIdx.x;

    if (img == 0) {
        if (e >= 256 * 160) return;
        int n = e / 160, k = e - n * 160;
        float v = 0.f;
        if (n < 128) { if (k < INP) v = W_sa[((long)a * INP + k) * HID + n] * istd[a * INP + k]; }
        else         { if (k < OBS) v = W_s [((long)a * OBS + k) * HID + (n - 128)] * istd[a * INP + k]; }
        w1h[(long)a * 256 * 160 + e] = __float2half_rn(v);
    } else if (img == 1) {
        if (a != 0 || e >= 256 * 128) return;
        int n = e >> 7, k = e & 127;
        float v = (n < 128) ? Wk[(((n >> 5) * HID) + k) * DHEAD + (n & 31)]
                            : Wv[((((n - 128) >> 5) * HID) + k) * DHEAD + ((n - 128) & 31)];
        kvh[e] = __float2half_rn(v);
    } else if (img == 2) {
        if (a != 0 || e >= 128 * 128) return;
        int n = e >> 7, k = e & 127;
        selh[e] = __float2half_rn(Wsel[(((n >> 5) * HID) + k) * DHEAD + (n & 31)]);
    } else if (img == 3) {
        if (e >= 128 * 256) return;
        int n = e >> 8, k = e & 255;
        c1h[(long)a * 128 * 256 + e] = __float2half_rn(Wc1[((long)a * 2 * HID + k) * HID + n]);
    } else {
        if (blockIdx.x != 0) return;
        int n = threadIdx.x;   // 0..255
        float acc = 0.f;
        if (n < 128) {
            for (int k = 0; k < INP; k++)
                acc += mean[a * INP + k] * istd[a * INP + k] * W_sa[((long)a * INP + k) * HID + n];
            b1[a * 256 + n] = b_sa[a * HID + n] - acc;
        } else {
            for (int k = 0; k < OBS; k++)
                acc += mean[a * INP + k] * istd[a * INP + k] * W_s[((long)a * OBS + k) * HID + (n - 128)];
            b1[a * 256 + n] = b_s[a * HID + (n - 128)] - acc;
        }
        if (a == 0) bkv[n] = (n < 128) ? 0.f : bv[n - 128];
    }
}

// ---------------- tensor-core GEMM (fp16 2-term split, fp32 accum) -------------
// 3-stage cp.async pipeline, ONE barrier per chunk, issue placed AFTER compute.
// Hoisted per-thread issue pointers.
template<int TN, int MINB>
__global__ void __launch_bounds__(256, MINB) gemm_mma(
    const __half* __restrict__ A0h, const __half* __restrict__ A0l, long sA0, int lda0,
    const __half* __restrict__ A1h, const __half* __restrict__ A1l, long sA1, int lda1,
    int ksplit, int Kreal,
    const __half* __restrict__ Bh_, long sB, int Kpad,
    const float* __restrict__ bias, long sBias,
    float* __restrict__ C, long sC, int ldc, int actFrom,
    int outHalf, __half* __restrict__ Ch, __half* __restrict__ Cl,
    int selFrom, const __half* __restrict__ B2h, float* __restrict__ C2, long sC2,
    int fuseFinal, const float* __restrict__ actions, const float* __restrict__ Wc2,
    const float* __restrict__ bc2, float* __restrict__ outq)
{
    constexpr int BPL_B = TN * STRIDE * 2;          // B plane bytes
    constexpr int BUFB  = 2 * PLANE_B + BPL_B;      // stage bytes
    constexpr int NI4   = TN / 32;                  // 16-col tiles per warp
    constexpr int WNW   = TN / 2;                   // warp n width
    constexpr int BITS  = TN * 4 / 256;             // B-load iterations per thread

    extern __shared__ __half sm[];
    __shared__ float sWc2[HID * ACT];
    __shared__ int   sIdx[128];
    __shared__ float sQred[2][128];

    int tid = threadIdx.x, wid = tid >> 5, lane = tid & 31;
    int a = blockIdx.z;
    long mBase = (long)blockIdx.x * 128;
    int wm = (wid & 3) * 32;
    int wn = (wid >> 2) * WNW;

    // per-y routing
    int colBase = blockIdx.y * TN;
    int aOff = 0;
    const __half* bhP = Bh_;
    float* Cout = C;
    long sCout = sC;
    int ldcL = ldc;
    const float* biasL = bias;
    int actF = actFrom;
    if ((int)blockIdx.y >= selFrom) {
        aOff = 128; bhP = B2h; colBase = (blockIdx.y - selFrom) * TN;
        Cout = C2; sCout = sC2; ldcL = 128; biasL = nullptr; actF = 1 << 30;
    }
    bhP += (long)a * sB;

    if (fuseFinal) {
        for (int i = tid; i < HID * ACT; i += 256)
            sWc2[i] = Wc2[(long)a * HID * ACT + i];
        if (tid < 128) {
            const float* ap = actions + ((long)a * BATCH + mBase + tid) * ACT;
            float best = ap[0]; int bi = 0;
#pragma unroll
            for (int j = 1; j < ACT; j++) {
                float x = ap[j];
                if (x > best) { best = x; bi = j; }
            }
            sIdx[tid] = bi;
        }
    }

    float acc[2][2 * NI4][4];
#pragma unroll
    for (int i = 0; i < 2; i++)
#pragma unroll
        for (int j = 0; j < 2 * NI4; j++)
#pragma unroll
            for (int q = 0; q < 4; q++) acc[i][j][q] = 0.f;

    uint32_t smB = smem_u32(sm);
    int nChunks = Kpad / CHUNK;

    // ---- hoisted issue-side addressing (per thread, per 'it') ----
    int aKK[2];
    uint32_t aD[2];
    const __half *aP0h[2], *aP0l[2], *aP1h[2], *aP1l[2];
#pragma unroll
    for (int it = 0; it < 2; it++) {
        int i = tid + it * 256;
        int row = i >> 2, kk = (i & 3) * 8;
        aKK[it] = kk;
        aD[it] = (uint32_t)((row * STRIDE + kk) * 2);
        long o0 = (long)a * sA0 + (mBase + row) * (long)lda0 + aOff + kk;
        aP0h[it] = A0h + o0;
        aP0l[it] = A0l + o0;
        long o1 = (A1h ? ((long)a * sA1 + (mBase + row) * (long)lda1 + (kk - ksplit)) : 0);
        aP1h[it] = A1h ? A1h + o1 : A0h;
        aP1l[it] = A1l ? A1l + o1 : A0l;
    }
    uint32_t bD[BITS];
    const __half* bP[BITS];
#pragma unroll
    for (int it = 0; it < BITS; it++) {
        int i = tid + it * 256;
        int n = i >> 2, kk = (i & 3) * 8;
        bD[it] = (uint32_t)((n * STRIDE + kk) * 2);
        bP[it] = bhP + (long)(colBase + n) * Kpad + kk;
    }

    auto issue = [&](int c, int buf) {
        uint32_t base = smB + (uint32_t)(buf * BUFB);
        int k0 = c * CHUNK;
#pragma unroll
        for (int it = 0; it < 2; it++) {
            int kg = k0 + aKK[it];
            const __half *ph, *pl;
            int ok = (kg < Kreal);
            if (kg < ksplit) { ph = aP0h[it] + k0; pl = aP0l[it] + k0; }
            else             { ph = aP1h[it] + k0; pl = aP1l[it] + k0; }
            if (!ok) { ph = A0h; pl = A0l; }
            cp16p(base + aD[it], ph, ok);
            cp16p(base + PLANE_B + aD[it], pl, ok);
        }
#pragma unroll
        for (int it = 0; it < BITS; it++)
            cp16(base + 2 * PLANE_B + bD[it], bP[it] + k0);
        cp_commit();
    };

    // hoisted compute-side in-buffer byte offsets
    int lr16 = lane & 15, lh16 = (lane >> 4) * 8;
    int lr8 = lane & 7, lk8 = ((lane >> 3) & 1) * 8, ln8 = (lane >> 4) * 8;
    uint32_t aHoff[2], bOff[NI4];
#pragma unroll
    for (int mi = 0; mi < 2; mi++)
        aHoff[mi] = (uint32_t)(((wm + mi * 16 + lr16) * STRIDE + lh16) * 2);
#pragma unroll
    for (int ni4 = 0; ni4 < NI4; ni4++)
        bOff[ni4] = (uint32_t)(((wn + ni4 * 16 + ln8 + lr8) * STRIDE + lk8) * 2) + 2 * PLANE_B;

    // prologue: 2 chunks in flight
    issue(0, 0);
    if (nChunks > 1) issue(1, 1);

    int cbuf = 0;
    for (int c = 0; c < nChunks; c++) {
        if (c + 1 < nChunks) cp_wait1();   // chunk c complete (c+1 still pending)
        else                 cp_wait0();
        __syncthreads();

        uint32_t base = smB + (uint32_t)(cbuf * BUFB);
#pragma unroll
        for (int ks = 0; ks < CHUNK; ks += 16) {
            uint32_t ah[2][4], al[2][4];
#pragma unroll
            for (int mi = 0; mi < 2; mi++) {
                ldm_x4(ah[mi], base + aHoff[mi] + ks * 2);
                ldm_x4(al[mi], base + aHoff[mi] + PLANE_B + ks * 2);
            }
#pragma unroll
            for (int half = 0; half < NI4 / 2; half++) {
                uint32_t bh[2][4];
                ldm_x4(bh[0], base + bOff[half * 2]     + ks * 2);
                ldm_x4(bh[1], base + bOff[half * 2 + 1] + ks * 2);
#pragma unroll
                for (int q = 0; q < 2; q++) {
                    int nb = (half * 2 + q) * 2;
#pragma unroll
                    for (int mi = 0; mi < 2; mi++) {
                        mma_f16(acc[mi][nb],     ah[mi], bh[q][0], bh[q][1]);
                        mma_f16(acc[mi][nb + 1], ah[mi], bh[q][2], bh[q][3]);
                    }
                }
#pragma unroll
                for (int q = 0; q < 2; q++) {
                    int nb = (half * 2 + q) * 2;
#pragma unroll
                    for (int mi = 0; mi < 2; mi++) {
                        mma_f16(acc[mi][nb],     al[mi], bh[q][0], bh[q][1]);
                        mma_f16(acc[mi][nb + 1], al[mi], bh[q][2], bh[q][3]);
                    }
                }
            }
        }

        // prefetch chunk c+2 into buffer (c+2)%3 = (c-1)%3: all threads finished
        // reading it (compute(c-1)) before this iteration's barrier.
        if (c + 2 < nChunks) issue(c + 2, (cbuf + 2 > 2) ? cbuf - 1 : cbuf + 2);
        cbuf = (cbuf == 2) ? 0 : cbuf + 1;
    }

    // ---- epilogue ----
    int gr = lane >> 2, tg = lane & 3;

    if constexpr (TN == 128) {
        if (fuseFinal) {
            float p[4] = {0.f, 0.f, 0.f, 0.f};
#pragma unroll
            for (int mi = 0; mi < 2; mi++) {
                int ra = wm + mi * 16 + gr;
                int rb = ra + 8;
                int ia = sIdx[ra], ib = sIdx[rb];
#pragma unroll
                for (int ni = 0; ni < 2 * NI4; ni++) {
                    int col = wn + ni * 8 + tg * 2;
                    const float* bp = biasL + (long)a * sBias + col;
                    float b0 = bp[0], b1 = bp[1];
                    float v0 = acc[mi][ni][0] + b0;
                    float v1 = acc[mi][ni][1] + b1;
                    float v2 = acc[mi][ni][2] + b0;
                    float v3 = acc[mi][ni][3] + b1;
                    v0 = v0 > 0.f ? v0 : 0.01f * v0;
                    v1 = v1 > 0.f ? v1 : 0.01f * v1;
                    v2 = v2 > 0.f ? v2 : 0.01f * v2;
                    v3 = v3 > 0.f ? v3 : 0.01f * v3;
                    p[mi * 2]     += v0 * sWc2[col * ACT + ia] + v1 * sWc2[(col + 1) * ACT + ia];
                    p[mi * 2 + 1] += v2 * sWc2[col * ACT + ib] + v3 * sWc2[(col + 1) * ACT + ib];
                }
            }
#pragma unroll
            for (int q = 0; q < 4; q++) {
                p[q] += __shfl_xor_sync(0xffffffffu, p[q], 1);
                p[q] += __shfl_xor_sync(0xffffffffu, p[q], 2);
            }
            int nh = wid >> 2;
            if (tg == 0) {
                sQred[nh][wm + gr]      = p[0];
                sQred[nh][wm + gr + 8]  = p[1];
                sQred[nh][wm + gr + 16] = p[2];
                sQred[nh][wm + gr + 24] = p[3];
            }
            __syncthreads();
            if (tid < 128) {
                float q = sQred[0][tid] + sQred[1][tid] + bc2[a * ACT + sIdx[tid]];
                outq[(long)a * BATCH + mBase + tid] = q;
            }
            return;
        }
    }

#pragma unroll
    for (int mi = 0; mi < 2; mi++) {
        long row0 = mBase + wm + mi * 16 + gr;
        long row1 = row0 + 8;
#pragma unroll
        for (int ni = 0; ni < 2 * NI4; ni++) {
            int col = colBase + wn + ni * 8 + tg * 2;
            float b0 = 0.f, b1 = 0.f;
            if (biasL) {
                const float* bp = biasL + (long)a * sBias + col;
                b0 = bp[0]; b1 = bp[1];
            }
            float v0 = acc[mi][ni][0] + b0;
            float v1 = acc[mi][ni][1] + b1;
            float v2 = acc[mi][ni][2] + b0;
            float v3 = acc[mi][ni][3] + b1;
            if (col >= actF) {
                v0 = v0 > 0.f ? v0 : 0.01f * v0;
                v2 = v2 > 0.f ? v2 : 0.01f * v2;
            }
            if (col + 1 >= actF) {
                v1 = v1 > 0.f ? v1 : 0.01f * v1;
                v3 = v3 > 0.f ? v3 : 0.01f * v3;
            }
            if (outHalf) {
                long o0 = (long)a * sCout + row0 * ldcL + col;
                long o1 = (long)a * sCout + row1 * ldcL + col;
                __half h0 = __float2half_rn(v0), h1 = __float2half_rn(v1);
                __half h2 = __float2half_rn(v2), h3 = __float2half_rn(v3);
                *(uint32_t*)(Ch + o0) = (uint32_t)__half_as_ushort(h0) |
                                        ((uint32_t)__half_as_ushort(h1) << 16);
                *(uint32_t*)(Ch + o1) = (uint32_t)__half_as_ushort(h2) |
                                        ((uint32_t)__half_as_ushort(h3) << 16);
                *(uint32_t*)(Cl + o0) = pack_h2(v0 - __half2float(h0), v1 - __half2float(h1));
                *(uint32_t*)(Cl + o1) = pack_h2(v2 - __half2float(h2), v3 - __half2float(h3));
            } else {
                float* Cp = Cout + (long)a * sCout;
                *(float2*)(Cp + row0 * ldcL + col) = make_float2(v0, v1);
                *(float2*)(Cp + row1 * ldcL + col) = make_float2(v2, v3);
            }
        }
    }
}

// ---------------- attention: smem-tiled, one CTA per 2 batch indices ----------
__global__ void __launch_bounds__(256) attn_kernel(
    const float* __restrict__ KV, const float* __restrict__ St,
    __half* __restrict__ oH, __half* __restrict__ oL)
{
    __shared__ float sKV[2][16][256];
    __shared__ float sS [2][16][128];

    int tid = threadIdx.x;
    long b0 = (long)blockIdx.x * 2;

    for (int idx = tid; idx < 2048; idx += 256) {
        int c4 = idx & 63;
        int row = idx >> 6;
        int b_l = row >> 4, j = row & 15;
        ((float4*)&sKV[b_l][j][0])[c4] =
            ((const float4*)(KV + ((long)j * BATCH + b0 + b_l) * 256))[c4];
    }
    for (int idx = tid; idx < 1024; idx += 256) {
        int c4 = idx & 31;
        int row = idx >> 5;
        int b_l = row >> 4, j = row & 15;
        ((float4*)&sS[b_l][j][0])[c4] =
            ((const float4*)(St + ((long)j * BATCH + b0 + b_l) * 128))[c4];
    }
    __syncthreads();

    int wid = tid >> 5, lane = tid & 31;
    int b_l = wid >> 2, n = wid & 3;
    long b = b0 + b_l;
    int col = n * DHEAD + lane;

    float Kr[16], Vr[16];
#pragma unroll
    for (int j = 0; j < 16; j++) {
        Kr[j] = sKV[b_l][j][col];
        Vr[j] = sKV[b_l][j][128 + col];
    }

    for (int i = 0; i < 16; i++) {
        float selv = sS[b_l][i][col];
        float lg = -3e38f;
#pragma unroll
        for (int j = 0; j < 16; j++) {
            float p = selv * Kr[j];
#pragma unroll
            for (int off = 16; off; off >>= 1) p += __shfl_xor_sync(0xffffffffu, p, off);
            if (lane == j) lg = (j == i) ? -1e9f : p * 0.17677669529663687f;
        }
        float mx = lg;
#pragma unroll
        for (int off = 16; off; off >>= 1) mx = fmaxf(mx, __shfl_xor_sync(0xffffffffu, mx, off));
        float e = (lane < 16) ? __expf(lg - mx) : 0.f;
        float den = e;
#pragma unroll
        for (int off = 16; off; off >>= 1) den += __shfl_xor_sync(0xffffffffu, den, off);
        float w = e / den;

        float acc = 0.f;
#pragma unroll
        for (int j = 0; j < 16; j++) {
            float wj = __shfl_sync(0xffffffffu, w, j);
            acc = fmaf(wj, Vr[j], acc);
        }
        long o = ((long)i * BATCH + b) * HID + col;
        __half h = __float2half_rn(acc);
        oH[o] = h;
        oL[o] = __float2half_rn(acc - __half2float(h));
    }
}

// ---------------- launch -------------------------------------------------------
static float* symaddr(const void* sym)
{
    void* p = nullptr;
    cudaGetSymbolAddress(&p, sym);
    return (float*)p;
}
static __half* symaddr_h(const void* sym)
{
    void* p = nullptr;
    cudaGetSymbolAddress(&p, sym);
    return (__half*)p;
}

extern "C" void kernel_launch(void* const* d_in, const int* in_sizes, int n_in,
                              void* d_out, int out_size)
{
    const float* obs     = (const float*)d_in[0];
    const float* actions = (const float*)d_in[1];
    const float* W_sa    = (const float*)d_in[2];
    const float* b_sa    = (const float*)d_in[3];
    const float* W_s     = (const float*)d_in[4];
    const float* b_s     = (const float*)d_in[5];
    const float* Wk      = (const float*)d_in[6];
    const float* Wsel    = (const float*)d_in[7];
    const float* Wv      = (const float*)d_in[8];
    const float* bv      = (const float*)d_in[9];
    const float* Wc1     = (const float*)d_in[10];
    const float* bc1     = (const float*)d_in[11];
    const float* Wc2     = (const float*)d_in[12];
    const float* bc2     = (const float*)d_in[13];
    float* out = (float*)d_out;

    float* ps    = symaddr(g_ps);
    float* ps2   = symaddr(g_ps2);
    float* mean  = symaddr(g_mean);
    float* istd  = symaddr(g_istd);
    float* b1    = symaddr(g_b1);
    float* bkv   = symaddr(g_bkv);
    float* KV    = symaddr(g_KV);
    float* St    = symaddr(g_S);

    __half* w1h  = symaddr_h(w1_h);
    __half* kvh  = symaddr_h(wkv_h);
    __half* selh = symaddr_h(wsel_h);
    __half* c1h  = symaddr_h(wc1_h);
    __half* obsH = symaddr_h(g_obsH);
    __half* obsL = symaddr_h(g_obsL);
    __half* actH = symaddr_h(g_actH);
    __half* actL = symaddr_h(g_actL);
    __half* aseH = symaddr_h(g_aseH);
    __half* aseL = symaddr_h(g_aseL);
    __half* othH = symaddr_h(g_othH);
    __half* othL = symaddr_h(g_othL);

    const size_t smem128 = 3 * (2 * PLANE_B + 128 * STRIDE * 2);   // 92160

    static bool attr_set = false;
    if (!attr_set) {
        cudaFuncSetAttribute(gemm_mma<128, 2>, cudaFuncAttributeMaxDynamicSharedMemorySize, smem128);
        attr_set = true;
    }

    const long sOBS = (long)BATCH * OBS;
    const long sACT = (long)BATCH * ACT;
    const long sASE = (long)BATCH * 256;
    const long sH   = (long)BATCH * HID;

    // 0
    bn_part_kernel<<<dim3(AGENTS, 5, 8), dim3(32, 32)>>>(obs, actions, ps, ps2,
                                                          obsH, obsL, actH, actL);
    // 1
    bn_fin_kernel<<<AGENTS, 160>>>(ps, ps2, mean, istd);
    // 2
    prep_all<<<dim3(160, 5, AGENTS), 256>>>(W_sa, b_sa, W_s, b_s, Wk, Wsel, Wv, bv,
                                            Wc1, mean, istd,
                                            w1h, kvh, selh, c1h, b1, bkv);

    // 3: ase = lrelu(bn([obs|act]) @ [W_sa|W_s] + b1)  K=144->160, N=256 (2 x 128)
    gemm_mma<128, 2><<<dim3(BATCH / 128, 2, AGENTS), 256, smem128>>>(
        obsH, obsL, sOBS, OBS, actH, actL, sACT, ACT, OBS, INP,
        w1h, (long)256 * 160, 160,
        b1, 256, nullptr, sASE, 256, 0,
        1, aseH, aseL,
        1 << 28, nullptr, nullptr, 0,
        0, nullptr, nullptr, nullptr, nullptr);

    // 4: merged KV + Sel.  y<2: KV = sa @ [Wk|Wv] (N=256); y==2: S = se @ Wsel
    gemm_mma<128, 2><<<dim3(BATCH / 128, 3, AGENTS), 256, smem128>>>(
        aseH, aseL, sASE, 256, aseH, aseL, 0, 0, 1 << 30, HID,
        kvh, 0, HID,
        bkv, 0, KV, sASE, 256, 128,
        0, nullptr, nullptr,
        2, selh, St, sH,
        0, nullptr, nullptr, nullptr, nullptr);

    // 5: attention (smem-tiled) -> other (fp16 pair)
    attn_kernel<<<BATCH / 2, 256>>>(KV, St, othH, othL);

    // 6: q = fused( lrelu([se|other] @ Wc1 + bc1) . Wc2[:,argmax] + bc2 )  K=256
    gemm_mma<128, 2><<<dim3(BATCH / 128, 1, AGENTS), 256, smem128>>>(
        aseH + 128, aseL + 128, sASE, 256, othH, othL, sH, HID, HID, 2 * HID,
        c1h, (long)HID * 2 * HID, 2 * HID,
        bc1, HID, nullptr, 0, 0, 1 << 30,
        0, nullptr, nullptr,
        1 << 28, nullptr, nullptr, 0,
        1, actions, Wc2, bc2, out);
}

// round 15
// speedup vs baseline: 1.3779x; 1.1815x over previous
#include <cuda_runtime.h>
#include <cuda_fp16.h>
#include <cstdint>

#define AGENTS 16
#define BATCH  8192
#define OBS    128
#define ACT    16
#define HID    128
#define NHEAD  4
#define DHEAD  32
#define INP    (OBS + ACT)   // 144

#define CHUNK  32
#define STRIDE (CHUNK + 8)   // 40
#define PLANE_B (128 * STRIDE * 2)   // A plane bytes: 10240

// ---------------- scratch (static device globals; no runtime alloc) -----------
__device__ float g_ps [AGENTS * 160 * 8];
__device__ float g_ps2[AGENTS * 160 * 8];
__device__ float g_mean[AGENTS * INP];
__device__ float g_istd[AGENTS * INP];
__device__ float g_b1  [AGENTS * 256];       // [bsaf | bsf]
__device__ float g_bkv [256];                // [0 | bv]
// fp16 weight images, [n][Kpad] row-major (B^T)
__device__ __half w1_h [(long)AGENTS * 256 * 160];
__device__ __half wkv_h[256 * HID];
__device__ __half wsel_h[HID * HID];
__device__ __half wc1_h[(long)AGENTS * HID * 2 * HID];
// fp16 activation planes
__device__ __half g_obsH[(long)AGENTS * BATCH * OBS];
__device__ __half g_actH[(long)AGENTS * BATCH * ACT];
__device__ __half g_aseH[(long)AGENTS * BATCH * 256];   // [sa | se]
__device__ __half g_othH[(long)AGENTS * BATCH * HID];
// fp32 buffers for attention inputs
__device__ float g_KV   [(long)AGENTS * BATCH * 256];   // [K | V]
__device__ float g_S    [(long)AGENTS * BATCH * HID];

// ---------------- helpers ------------------------------------------------------
__device__ __forceinline__ uint32_t smem_u32(const void* p) {
    uint32_t r;
    asm("{ .reg .u64 t; cvta.to.shared.u64 t, %1; cvt.u32.u64 %0, t; }" : "=r"(r) : "l"(p));
    return r;
}
__device__ __forceinline__ void ldm_x4(uint32_t* r, uint32_t addr) {
    asm volatile("ldmatrix.sync.aligned.m8n8.x4.shared.b16 {%0,%1,%2,%3}, [%4];"
                 : "=r"(r[0]), "=r"(r[1]), "=r"(r[2]), "=r"(r[3]) : "r"(addr));
}
__device__ __forceinline__ void mma_f16(float* c, const uint32_t* a, uint32_t b0, uint32_t b1) {
    asm volatile("mma.sync.aligned.m16n8k16.row.col.f32.f16.f16.f32 "
                 "{%0,%1,%2,%3}, {%4,%5,%6,%7}, {%8,%9}, {%0,%1,%2,%3};"
                 : "+f"(c[0]), "+f"(c[1]), "+f"(c[2]), "+f"(c[3])
                 : "r"(a[0]), "r"(a[1]), "r"(a[2]), "r"(a[3]), "r"(b0), "r"(b1));
}
__device__ __forceinline__ void cp16(uint32_t dst, const void* src) {
    asm volatile("cp.async.cg.shared.global [%0], [%1], 16;" :: "r"(dst), "l"(src));
}
__device__ __forceinline__ void cp16p(uint32_t dst, const void* src, int ok) {
    asm volatile("{\n\t.reg .pred p;\n\tsetp.ne.b32 p, %2, 0;\n\t"
                 "@p cp.async.cg.shared.global [%0], [%1], 16;\n\t"
                 "@!p cp.async.cg.shared.global [%0], [%1], 16, 0;\n\t}"
                 :: "r"(dst), "l"(src), "r"(ok));
}
__device__ __forceinline__ void cp_commit() { asm volatile("cp.async.commit_group;" ::: "memory"); }
__device__ __forceinline__ void cp_wait1()  { asm volatile("cp.async.wait_group 1;" ::: "memory"); }
__device__ __forceinline__ void cp_wait0()  { asm volatile("cp.async.wait_group 0;" ::: "memory"); }

// ---------------- BN pass 1: partial sums + fp16 planes ------------------------
__global__ void bn_part_kernel(const float* __restrict__ obs,
                               const float* __restrict__ actions,
                               float* __restrict__ ps, float* __restrict__ ps2,
                               __half* __restrict__ oH, __half* __restrict__ aH)
{
    int a = blockIdx.x;
    int f = blockIdx.y * 32 + threadIdx.x;
    int seg = blockIdx.z;
    float s = 0.f, s2 = 0.f;
    if (f < INP) {
        if (f < OBS) {
            long base = (long)a * BATCH * OBS + (long)seg * 1024 * OBS + f;
            const float* src = obs + base;
            for (int b = threadIdx.y; b < 1024; b += 32) {
                float x = src[(long)b * OBS]; s += x; s2 += x * x;
                oH[base + (long)b * OBS] = __float2half_rn(x);
            }
        } else {
            long base = (long)a * BATCH * ACT + (long)seg * 1024 * ACT + (f - OBS);
            const float* src = actions + base;
            for (int b = threadIdx.y; b < 1024; b += 32) {
                float x = src[(long)b * ACT]; s += x; s2 += x * x;
                aH[base + (long)b * ACT] = __float2half_rn(x);
            }
        }
    }
    __shared__ float sh1[32][33];
    __shared__ float sh2[32][33];
    sh1[threadIdx.y][threadIdx.x] = s;
    sh2[threadIdx.y][threadIdx.x] = s2;
    __syncthreads();
    for (int st = 16; st > 0; st >>= 1) {
        if (threadIdx.y < st) {
            sh1[threadIdx.y][threadIdx.x] += sh1[threadIdx.y + st][threadIdx.x];
            sh2[threadIdx.y][threadIdx.x] += sh2[threadIdx.y + st][threadIdx.x];
        }
        __syncthreads();
    }
    if (threadIdx.y == 0) {
        int fi = blockIdx.y * 32 + threadIdx.x;
        ps [(a * 160 + fi) * 8 + seg] = sh1[0][threadIdx.x];
        ps2[(a * 160 + fi) * 8 + seg] = sh2[0][threadIdx.x];
    }
}

// ---------------- BN pass 2 -----------------------------------------------------
__global__ void bn_fin_kernel(const float* __restrict__ ps, const float* __restrict__ ps2,
                              float* __restrict__ mean, float* __restrict__ istd)
{
    int a = blockIdx.x;
    int f = threadIdx.x;
    if (f >= INP) return;
    float s = 0.f, s2 = 0.f;
    for (int seg = 0; seg < 8; seg++) {
        s  += ps [(a * 160 + f) * 8 + seg];
        s2 += ps2[(a * 160 + f) * 8 + seg];
    }
    float m = s * (1.0f / BATCH);
    float v = s2 * (1.0f / BATCH) - m * m;
    mean[a * INP + f] = m;
    istd[a * INP + f] = rsqrtf(v + 1e-5f);
}

// ---------------- prep_all: BN-folded fp16 weight images + biases --------------
__global__ void prep_all(const float* __restrict__ W_sa, const float* __restrict__ b_sa,
                         const float* __restrict__ W_s,  const float* __restrict__ b_s,
                         const float* __restrict__ Wk, const float* __restrict__ Wsel,
                         const float* __restrict__ Wv, const float* __restrict__ bv,
                         const float* __restrict__ Wc1,
                         const float* __restrict__ mean, const float* __restrict__ istd,
                         __half* __restrict__ w1h, __half* __restrict__ kvh,
                         __half* __restrict__ selh, __half* __restrict__ c1h,
                         float* __restrict__ b1, float* __restrict__ bkv)
{
    int img = blockIdx.y;
    int a = blockIdx.z;
    int e = blockIdx.x * 256 + threadIdx.x;

    if (img == 0) {
        if (e >= 256 * 160) return;
        int n = e / 160, k = e - n * 160;
        float v = 0.f;
        if (n < 128) { if (k < INP) v = W_sa[((long)a * INP + k) * HID + n] * istd[a * INP + k]; }
        else         { if (k < OBS) v = W_s [((long)a * OBS + k) * HID + (n - 128)] * istd[a * INP + k]; }
        w1h[(long)a * 256 * 160 + e] = __float2half_rn(v);
    } else if (img == 1) {
        if (a != 0 || e >= 256 * 128) return;
        int n = e >> 7, k = e & 127;
        float v = (n < 128) ? Wk[(((n >> 5) * HID) + k) * DHEAD + (n & 31)]
                            : Wv[((((n - 128) >> 5) * HID) + k) * DHEAD + ((n - 128) & 31)];
        kvh[e] = __float2half_rn(v);
    } else if (img == 2) {
        if (a != 0 || e >= 128 * 128) return;
        int n = e >> 7, k = e & 127;
        selh[e] = __float2half_rn(Wsel[(((n >> 5) * HID) + k) * DHEAD + (n & 31)]);
    } else if (img == 3) {
        if (e >= 128 * 256) return;
        int n = e >> 8, k = e & 255;
        c1h[(long)a * 128 * 256 + e] = __float2half_rn(Wc1[((long)a * 2 * HID + k) * HID + n]);
    } else {
        if (blockIdx.x != 0) return;
        int n = threadIdx.x;   // 0..255
        float acc = 0.f;
        if (n < 128) {
            for (int k = 0; k < INP; k++)
                acc += mean[a * INP + k] * istd[a * INP + k] * W_sa[((long)a * INP + k) * HID + n];
            b1[a * 256 + n] = b_sa[a * HID + n] - acc;
        } else {
            for (int k = 0; k < OBS; k++)
                acc += mean[a * INP + k] * istd[a * INP + k] * W_s[((long)a * OBS + k) * HID + (n - 128)];
            b1[a * 256 + n] = b_s[a * HID + (n - 128)] - acc;
        }
        if (a == 0) bkv[n] = (n < 128) ? 0.f : bv[n - 128];
    }
}

// ---------------- tensor-core GEMM (plain fp16, fp32 accum) --------------------
// 3-stage cp.async pipeline, one barrier per chunk, issue after compute.
template<int TN, int MINB>
__global__ void __launch_bounds__(256, MINB) gemm_mma(
    const __half* __restrict__ A0h, long sA0, int lda0,
    const __half* __restrict__ A1h, long sA1, int lda1,
    int ksplit, int Kreal,
    const __half* __restrict__ Bh_, long sB, int Kpad,
    const float* __restrict__ bias, long sBias,
    float* __restrict__ C, long sC, int ldc, int actFrom,
    int outHalf, __half* __restrict__ Ch,
    int selFrom, const __half* __restrict__ B2h, float* __restrict__ C2, long sC2,
    int fuseFinal, const float* __restrict__ actions, const float* __restrict__ Wc2,
    const float* __restrict__ bc2, float* __restrict__ outq)
{
    constexpr int BPL_B = TN * STRIDE * 2;      // B plane bytes
    constexpr int BUFB  = PLANE_B + BPL_B;      // stage bytes
    constexpr int NI4   = TN / 32;
    constexpr int WNW   = TN / 2;
    constexpr int BITS  = TN * 4 / 256;

    extern __shared__ __half sm[];
    __shared__ float sWc2[HID * ACT];
    __shared__ int   sIdx[128];
    __shared__ float sQred[2][128];

    int tid = threadIdx.x, wid = tid >> 5, lane = tid & 31;
    int a = blockIdx.z;
    long mBase = (long)blockIdx.x * 128;
    int wm = (wid & 3) * 32;
    int wn = (wid >> 2) * WNW;

    // per-y routing
    int colBase = blockIdx.y * TN;
    int aOff = 0;
    const __half* bhP = Bh_;
    float* Cout = C;
    long sCout = sC;
    int ldcL = ldc;
    const float* biasL = bias;
    int actF = actFrom;
    if ((int)blockIdx.y >= selFrom) {
        aOff = 128; bhP = B2h; colBase = (blockIdx.y - selFrom) * TN;
        Cout = C2; sCout = sC2; ldcL = 128; biasL = nullptr; actF = 1 << 30;
    }
    bhP += (long)a * sB;

    if (fuseFinal) {
        for (int i = tid; i < HID * ACT; i += 256)
            sWc2[i] = Wc2[(long)a * HID * ACT + i];
        if (tid < 128) {
            const float* ap = actions + ((long)a * BATCH + mBase + tid) * ACT;
            float best = ap[0]; int bi = 0;
#pragma unroll
            for (int j = 1; j < ACT; j++) {
                float x = ap[j];
                if (x > best) { best = x; bi = j; }
            }
            sIdx[tid] = bi;
        }
    }

    float acc[2][2 * NI4][4];
#pragma unroll
    for (int i = 0; i < 2; i++)
#pragma unroll
        for (int j = 0; j < 2 * NI4; j++)
#pragma unroll
            for (int q = 0; q < 4; q++) acc[i][j][q] = 0.f;

    uint32_t smB = smem_u32(sm);
    int nChunks = Kpad / CHUNK;

    // ---- hoisted issue-side addressing ----
    int aKK[2];
    uint32_t aD[2];
    const __half *aP0[2], *aP1[2];
#pragma unroll
    for (int it = 0; it < 2; it++) {
        int i = tid + it * 256;
        int row = i >> 2, kk = (i & 3) * 8;
        aKK[it] = kk;
        aD[it] = (uint32_t)((row * STRIDE + kk) * 2);
        aP0[it] = A0h + (long)a * sA0 + (mBase + row) * (long)lda0 + aOff + kk;
        aP1[it] = A1h ? A1h + (long)a * sA1 + (mBase + row) * (long)lda1 + (kk - ksplit) : A0h;
    }
    uint32_t bD[BITS];
    const __half* bP[BITS];
#pragma unroll
    for (int it = 0; it < BITS; it++) {
        int i = tid + it * 256;
        int n = i >> 2, kk = (i & 3) * 8;
        bD[it] = (uint32_t)((n * STRIDE + kk) * 2);
        bP[it] = bhP + (long)(colBase + n) * Kpad + kk;
    }

    auto issue = [&](int c, int buf) {
        uint32_t base = smB + (uint32_t)(buf * BUFB);
        int k0 = c * CHUNK;
#pragma unroll
        for (int it = 0; it < 2; it++) {
            int kg = k0 + aKK[it];
            const __half* ph = (kg < ksplit) ? aP0[it] + k0 : aP1[it] + k0;
            int ok = (kg < Kreal);
            if (!ok) ph = A0h;
            cp16p(base + aD[it], ph, ok);
        }
#pragma unroll
        for (int it = 0; it < BITS; it++)
            cp16(base + PLANE_B + bD[it], bP[it] + k0);
        cp_commit();
    };

    // hoisted compute-side in-buffer byte offsets
    int lr16 = lane & 15, lh16 = (lane >> 4) * 8;
    int lr8 = lane & 7, lk8 = ((lane >> 3) & 1) * 8, ln8 = (lane >> 4) * 8;
    uint32_t aHoff[2], bOff[NI4];
#pragma unroll
    for (int mi = 0; mi < 2; mi++)
        aHoff[mi] = (uint32_t)(((wm + mi * 16 + lr16) * STRIDE + lh16) * 2);
#pragma unroll
    for (int ni4 = 0; ni4 < NI4; ni4++)
        bOff[ni4] = (uint32_t)(((wn + ni4 * 16 + ln8 + lr8) * STRIDE + lk8) * 2) + PLANE_B;

    issue(0, 0);
    if (nChunks > 1) issue(1, 1);

    int cbuf = 0;
    for (int c = 0; c < nChunks; c++) {
        if (c + 1 < nChunks) cp_wait1();
        else                 cp_wait0();
        __syncthreads();

        uint32_t base = smB + (uint32_t)(cbuf * BUFB);
#pragma unroll
        for (int ks = 0; ks < CHUNK; ks += 16) {
            uint32_t ah[2][4];
#pragma unroll
            for (int mi = 0; mi < 2; mi++)
                ldm_x4(ah[mi], base + aHoff[mi] + ks * 2);
#pragma unroll
            for (int ni4 = 0; ni4 < NI4; ni4++) {
                uint32_t bh[4];
                ldm_x4(bh, base + bOff[ni4] + ks * 2);
#pragma unroll
                for (int mi = 0; mi < 2; mi++) {
                    mma_f16(acc[mi][ni4 * 2],     ah[mi], bh[0], bh[1]);
                    mma_f16(acc[mi][ni4 * 2 + 1], ah[mi], bh[2], bh[3]);
                }
            }
        }

        if (c + 2 < nChunks) issue(c + 2, (cbuf + 2 > 2) ? cbuf - 1 : cbuf + 2);
        cbuf = (cbuf == 2) ? 0 : cbuf + 1;
    }

    // ---- epilogue ----
    int gr = lane >> 2, tg = lane & 3;

    if constexpr (TN == 128) {
        if (fuseFinal) {
            float p[4] = {0.f, 0.f, 0.f, 0.f};
#pragma unroll
            for (int mi = 0; mi < 2; mi++) {
                int ra = wm + mi * 16 + gr;
                int rb = ra + 8;
                int ia = sIdx[ra], ib = sIdx[rb];
#pragma unroll
                for (int ni = 0; ni < 2 * NI4; ni++) {
                    int col = wn + ni * 8 + tg * 2;
                    const float* bp = biasL + (long)a * sBias + col;
                    float b0 = bp[0], b1 = bp[1];
                    float v0 = acc[mi][ni][0] + b0;
                    float v1 = acc[mi][ni][1] + b1;
                    float v2 = acc[mi][ni][2] + b0;
                    float v3 = acc[mi][ni][3] + b1;
                    v0 = v0 > 0.f ? v0 : 0.01f * v0;
                    v1 = v1 > 0.f ? v1 : 0.01f * v1;
                    v2 = v2 > 0.f ? v2 : 0.01f * v2;
                    v3 = v3 > 0.f ? v3 : 0.01f * v3;
                    p[mi * 2]     += v0 * sWc2[col * ACT + ia] + v1 * sWc2[(col + 1) * ACT + ia];
                    p[mi * 2 + 1] += v2 * sWc2[col * ACT + ib] + v3 * sWc2[(col + 1) * ACT + ib];
                }
            }
#pragma unroll
            for (int q = 0; q < 4; q++) {
                p[q] += __shfl_xor_sync(0xffffffffu, p[q], 1);
                p[q] += __shfl_xor_sync(0xffffffffu, p[q], 2);
            }
            int nh = wid >> 2;
            if (tg == 0) {
                sQred[nh][wm + gr]      = p[0];
                sQred[nh][wm + gr + 8]  = p[1];
                sQred[nh][wm + gr + 16] = p[2];
                sQred[nh][wm + gr + 24] = p[3];
            }
            __syncthreads();
            if (tid < 128) {
                float q = sQred[0][tid] + sQred[1][tid] + bc2[a * ACT + sIdx[tid]];
                outq[(long)a * BATCH + mBase + tid] = q;
            }
            return;
        }
    }

#pragma unroll
    for (int mi = 0; mi < 2; mi++) {
        long row0 = mBase + wm + mi * 16 + gr;
        long row1 = row0 + 8;
#pragma unroll
        for (int ni = 0; ni < 2 * NI4; ni++) {
            int col = colBase + wn + ni * 8 + tg * 2;
            float b0 = 0.f, b1 = 0.f;
            if (biasL) {
                const float* bp = biasL + (long)a * sBias + col;
                b0 = bp[0]; b1 = bp[1];
            }
            float v0 = acc[mi][ni][0] + b0;
            float v1 = acc[mi][ni][1] + b1;
            float v2 = acc[mi][ni][2] + b0;
            float v3 = acc[mi][ni][3] + b1;
            if (col >= actF) {
                v0 = v0 > 0.f ? v0 : 0.01f * v0;
                v2 = v2 > 0.f ? v2 : 0.01f * v2;
            }
            if (col + 1 >= actF) {
                v1 = v1 > 0.f ? v1 : 0.01f * v1;
                v3 = v3 > 0.f ? v3 : 0.01f * v3;
            }
            if (outHalf) {
                long o0 = (long)a * sCout + row0 * ldcL + col;
                long o1 = (long)a * sCout + row1 * ldcL + col;
                __half h0 = __float2half_rn(v0), h1 = __float2half_rn(v1);
                __half h2 = __float2half_rn(v2), h3 = __float2half_rn(v3);
                *(uint32_t*)(Ch + o0) = (uint32_t)__half_as_ushort(h0) |
                                        ((uint32_t)__half_as_ushort(h1) << 16);
                *(uint32_t*)(Ch + o1) = (uint32_t)__half_as_ushort(h2) |
                                        ((uint32_t)__half_as_ushort(h3) << 16);
            } else {
                float* Cp = Cout + (long)a * sCout;
                *(float2*)(Cp + row0 * ldcL + col) = make_float2(v0, v1);
                *(float2*)(Cp + row1 * ldcL + col) = make_float2(v2, v3);
            }
        }
    }
}

// ---------------- attention: smem-tiled, one CTA per 2 batch indices ----------
__global__ void __launch_bounds__(256) attn_kernel(
    const float* __restrict__ KV, const float* __restrict__ St,
    __half* __restrict__ oH)
{
    __shared__ float sKV[2][16][256];
    __shared__ float sS [2][16][128];

    int tid = threadIdx.x;
    long b0 = (long)blockIdx.x * 2;

    for (int idx = tid; idx < 2048; idx += 256) {
        int c4 = idx & 63;
        int row = idx >> 6;
        int b_l = row >> 4, j = row & 15;
        ((float4*)&sKV[b_l][j][0])[c4] =
            ((const float4*)(KV + ((long)j * BATCH + b0 + b_l) * 256))[c4];
    }
    for (int idx = tid; idx < 1024; idx += 256) {
        int c4 = idx & 31;
        int row = idx >> 5;
        int b_l = row >> 4, j = row & 15;
        ((float4*)&sS[b_l][j][0])[c4] =
            ((const float4*)(St + ((long)j * BATCH + b0 + b_l) * 128))[c4];
    }
    __syncthreads();

    int wid = tid >> 5, lane = tid & 31;
    int b_l = wid >> 2, n = wid & 3;
    long b = b0 + b_l;
    int col = n * DHEAD + lane;

    float Kr[16], Vr[16];
#pragma unroll
    for (int j = 0; j < 16; j++) {
        Kr[j] = sKV[b_l][j][col];
        Vr[j] = sKV[b_l][j][128 + col];
    }

    for (int i = 0; i < 16; i++) {
        float selv = sS[b_l][i][col];
        float lg = -3e38f;
#pragma unroll
        for (int j = 0; j < 16; j++) {
            float p = selv * Kr[j];
#pragma unroll
            for (int off = 16; off; off >>= 1) p += __shfl_xor_sync(0xffffffffu, p, off);
            if (lane == j) lg = (j == i) ? -1e9f : p * 0.17677669529663687f;
        }
        float mx = lg;
#pragma unroll
        for (int off = 16; off; off >>= 1) mx = fmaxf(mx, __shfl_xor_sync(0xffffffffu, mx, off));
        float e = (lane < 16) ? __expf(lg - mx) : 0.f;
        float den = e;
#pragma unroll
        for (int off = 16; off; off >>= 1) den += __shfl_xor_sync(0xffffffffu, den, off);
        float w = e / den;

        float acc = 0.f;
#pragma unroll
        for (int j = 0; j < 16; j++) {
            float wj = __shfl_sync(0xffffffffu, w, j);
            acc = fmaf(wj, Vr[j], acc);
        }
        oH[((long)i * BATCH + b) * HID + col] = __float2half_rn(acc);
    }
}

// ---------------- launch -------------------------------------------------------
static float* symaddr(const void* sym)
{
    void* p = nullptr;
    cudaGetSymbolAddress(&p, sym);
    return (float*)p;
}
static __half* symaddr_h(const void* sym)
{
    void* p = nullptr;
    cudaGetSymbolAddress(&p, sym);
    return (__half*)p;
}

extern "C" void kernel_launch(void* const* d_in, const int* in_sizes, int n_in,
                              void* d_out, int out_size)
{
    const float* obs     = (const float*)d_in[0];
    const float* actions = (const float*)d_in[1];
    const float* W_sa    = (const float*)d_in[2];
    const float* b_sa    = (const float*)d_in[3];
    const float* W_s     = (const float*)d_in[4];
    const float* b_s     = (const float*)d_in[5];
    const float* Wk      = (const float*)d_in[6];
    const float* Wsel    = (const float*)d_in[7];
    const float* Wv      = (const float*)d_in[8];
    const float* bv      = (const float*)d_in[9];
    const float* Wc1     = (const float*)d_in[10];
    const float* bc1     = (const float*)d_in[11];
    const float* Wc2     = (const float*)d_in[12];
    const float* bc2     = (const float*)d_in[13];
    float* out = (float*)d_out;

    float* ps    = symaddr(g_ps);
    float* ps2   = symaddr(g_ps2);
    float* mean  = symaddr(g_mean);
    float* istd  = symaddr(g_istd);
    float* b1    = symaddr(g_b1);
    float* bkv   = symaddr(g_bkv);
    float* KV    = symaddr(g_KV);
    float* St    = symaddr(g_S);

    __half* w1h  = symaddr_h(w1_h);
    __half* kvh  = symaddr_h(wkv_h);
    __half* selh = symaddr_h(wsel_h);
    __half* c1h  = symaddr_h(wc1_h);
    __half* obsH = symaddr_h(g_obsH);
    __half* actH = symaddr_h(g_actH);
    __half* aseH = symaddr_h(g_aseH);
    __half* othH = symaddr_h(g_othH);

    const size_t smem128 = 3 * (PLANE_B + 128 * STRIDE * 2);   // 61440

    static bool attr_set = false;
    if (!attr_set) {
        cudaFuncSetAttribute(gemm_mma<128, 2>, cudaFuncAttributeMaxDynamicSharedMemorySize, smem128);
        attr_set = true;
    }

    const long sOBS = (long)BATCH * OBS;
    const long sACT = (long)BATCH * ACT;
    const long sASE = (long)BATCH * 256;
    const long sH   = (long)BATCH * HID;

    // 0
    bn_part_kernel<<<dim3(AGENTS, 5, 8), dim3(32, 32)>>>(obs, actions, ps, ps2, obsH, actH);
    // 1
    bn_fin_kernel<<<AGENTS, 160>>>(ps, ps2, mean, istd);
    // 2
    prep_all<<<dim3(160, 5, AGENTS), 256>>>(W_sa, b_sa, W_s, b_s, Wk, Wsel, Wv, bv,
                                            Wc1, mean, istd,
                                            w1h, kvh, selh, c1h, b1, bkv);

    // 3: ase = lrelu(bn([obs|act]) @ [W_sa|W_s] + b1)  K=144->160, N=256 (2 x 128)
    gemm_mma<128, 2><<<dim3(BATCH / 128, 2, AGENTS), 256, smem128>>>(
        obsH, sOBS, OBS, actH, sACT, ACT, OBS, INP,
        w1h, (long)256 * 160, 160,
        b1, 256, nullptr, sASE, 256, 0,
        1, aseH,
        1 << 28, nullptr, nullptr, 0,
        0, nullptr, nullptr, nullptr, nullptr);

    // 4: merged KV + Sel.  y<2: KV = sa @ [Wk|Wv] (N=256); y==2: S = se @ Wsel
    gemm_mma<128, 2><<<dim3(BATCH / 128, 3, AGENTS), 256, smem128>>>(
        aseH, sASE, 256, aseH, 0, 0, 1 << 30, HID,
        kvh, 0, HID,
        bkv, 0, KV, sASE, 256, 128,
        0, nullptr,
        2, selh, St, sH,
        0, nullptr, nullptr, nullptr, nullptr);

    // 5: attention (smem-tiled) -> other (fp16)
    attn_kernel<<<BATCH / 2, 256>>>(KV, St, othH);

    // 6: q = fused( lrelu([se|other] @ Wc1 + bc1) . Wc2[:,argmax] + bc2 )  K=256
    gemm_mma<128, 2><<<dim3(BATCH / 128, 1, AGENTS), 256, smem128>>>(
        aseH + 128, sASE, 256, othH, sH, HID, HID, 2 * HID,
        c1h, (long)HID * 2 * HID, 2 * HID,
        bc1, HID, nullptr, 0, 0, 1 << 30,
        0, nullptr,
        1 << 28, nullptr, nullptr, 0,
        1, actions, Wc2, bc2, out);
}

// round 16
// speedup vs baseline: 1.3863x; 1.0061x over previous
#include <cuda_runtime.h>
#include <cuda_fp16.h>
#include <cstdint>

#define AGENTS 16
#define BATCH  8192
#define OBS    128
#define ACT    16
#define HID    128
#define NHEAD  4
#define DHEAD  32
#define INP    (OBS + ACT)   // 144

#define CHUNK  32
#define STRIDE (CHUNK + 8)   // 40
#define PLANE_B (128 * STRIDE * 2)   // A plane bytes: 10240

// ---------------- scratch (static device globals; no runtime alloc) -----------
__device__ float g_ps [AGENTS * 160 * 8];
__device__ float g_ps2[AGENTS * 160 * 8];
__device__ float g_mean[AGENTS * INP];
__device__ float g_istd[AGENTS * INP];
__device__ float g_b1  [AGENTS * 256];       // [bsaf | bsf]
__device__ float g_bkv [256];                // [0 | bv]
// fp16 weight images, [n][Kpad] row-major (B^T)
__device__ __half w1_h [(long)AGENTS * 256 * 160];
__device__ __half wkv_h[256 * HID];
__device__ __half wsel_h[HID * HID];
__device__ __half wc1_h[(long)AGENTS * HID * 2 * HID];
// fp16 activation planes
__device__ __half g_obsH[(long)AGENTS * BATCH * OBS];
__device__ __half g_actH[(long)AGENTS * BATCH * ACT];
__device__ __half g_aseH[(long)AGENTS * BATCH * 256];   // [sa | se]
__device__ __half g_othH[(long)AGENTS * BATCH * HID];
// fp32 buffers for attention inputs
__device__ float g_KV   [(long)AGENTS * BATCH * 256];   // [K | V]
__device__ float g_S    [(long)AGENTS * BATCH * HID];

// ---------------- helpers ------------------------------------------------------
__device__ __forceinline__ uint32_t smem_u32(const void* p) {
    uint32_t r;
    asm("{ .reg .u64 t; cvta.to.shared.u64 t, %1; cvt.u32.u64 %0, t; }" : "=r"(r) : "l"(p));
    return r;
}
__device__ __forceinline__ void ldm_x4(uint32_t* r, uint32_t addr) {
    asm volatile("ldmatrix.sync.aligned.m8n8.x4.shared.b16 {%0,%1,%2,%3}, [%4];"
                 : "=r"(r[0]), "=r"(r[1]), "=r"(r[2]), "=r"(r[3]) : "r"(addr));
}
__device__ __forceinline__ void mma_f16(float* c, const uint32_t* a, uint32_t b0, uint32_t b1) {
    asm volatile("mma.sync.aligned.m16n8k16.row.col.f32.f16.f16.f32 "
                 "{%0,%1,%2,%3}, {%4,%5,%6,%7}, {%8,%9}, {%0,%1,%2,%3};"
                 : "+f"(c[0]), "+f"(c[1]), "+f"(c[2]), "+f"(c[3])
                 : "r"(a[0]), "r"(a[1]), "r"(a[2]), "r"(a[3]), "r"(b0), "r"(b1));
}
__device__ __forceinline__ void cp16(uint32_t dst, const void* src) {
    asm volatile("cp.async.cg.shared.global [%0], [%1], 16;" :: "r"(dst), "l"(src));
}
__device__ __forceinline__ void cp16p(uint32_t dst, const void* src, int ok) {
    asm volatile("{\n\t.reg .pred p;\n\tsetp.ne.b32 p, %2, 0;\n\t"
                 "@p cp.async.cg.shared.global [%0], [%1], 16;\n\t"
                 "@!p cp.async.cg.shared.global [%0], [%1], 16, 0;\n\t}"
                 :: "r"(dst), "l"(src), "r"(ok));
}
__device__ __forceinline__ void cp_commit() { asm volatile("cp.async.commit_group;" ::: "memory"); }
__device__ __forceinline__ void cp_wait2()  { asm volatile("cp.async.wait_group 2;" ::: "memory"); }
__device__ __forceinline__ void cp_wait1()  { asm volatile("cp.async.wait_group 1;" ::: "memory"); }
__device__ __forceinline__ void cp_wait0()  { asm volatile("cp.async.wait_group 0;" ::: "memory"); }

// ---------------- BN pass 1: partial sums + fp16 planes ------------------------
__global__ void bn_part_kernel(const float* __restrict__ obs,
                               const float* __restrict__ actions,
                               float* __restrict__ ps, float* __restrict__ ps2,
                               __half* __restrict__ oH, __half* __restrict__ aH)
{
    int a = blockIdx.x;
    int f = blockIdx.y * 32 + threadIdx.x;
    int seg = blockIdx.z;
    float s = 0.f, s2 = 0.f;
    if (f < INP) {
        if (f < OBS) {
            long base = (long)a * BATCH * OBS + (long)seg * 1024 * OBS + f;
            const float* src = obs + base;
            for (int b = threadIdx.y; b < 1024; b += 32) {
                float x = src[(long)b * OBS]; s += x; s2 += x * x;
                oH[base + (long)b * OBS] = __float2half_rn(x);
            }
        } else {
            long base = (long)a * BATCH * ACT + (long)seg * 1024 * ACT + (f - OBS);
            const float* src = actions + base;
            for (int b = threadIdx.y; b < 1024; b += 32) {
                float x = src[(long)b * ACT]; s += x; s2 += x * x;
                aH[base + (long)b * ACT] = __float2half_rn(x);
            }
        }
    }
    __shared__ float sh1[32][33];
    __shared__ float sh2[32][33];
    sh1[threadIdx.y][threadIdx.x] = s;
    sh2[threadIdx.y][threadIdx.x] = s2;
    __syncthreads();
    for (int st = 16; st > 0; st >>= 1) {
        if (threadIdx.y < st) {
            sh1[threadIdx.y][threadIdx.x] += sh1[threadIdx.y + st][threadIdx.x];
            sh2[threadIdx.y][threadIdx.x] += sh2[threadIdx.y + st][threadIdx.x];
        }
        __syncthreads();
    }
    if (threadIdx.y == 0) {
        int fi = blockIdx.y * 32 + threadIdx.x;
        ps [(a * 160 + fi) * 8 + seg] = sh1[0][threadIdx.x];
        ps2[(a * 160 + fi) * 8 + seg] = sh2[0][threadIdx.x];
    }
}

// ---------------- BN pass 2 -----------------------------------------------------
__global__ void bn_fin_kernel(const float* __restrict__ ps, const float* __restrict__ ps2,
                              float* __restrict__ mean, float* __restrict__ istd)
{
    int a = blockIdx.x;
    int f = threadIdx.x;
    if (f >= INP) return;
    float s = 0.f, s2 = 0.f;
    for (int seg = 0; seg < 8; seg++) {
        s  += ps [(a * 160 + f) * 8 + seg];
        s2 += ps2[(a * 160 + f) * 8 + seg];
    }
    float m = s * (1.0f / BATCH);
    float v = s2 * (1.0f / BATCH) - m * m;
    mean[a * INP + f] = m;
    istd[a * INP + f] = rsqrtf(v + 1e-5f);
}

// ---------------- prep_all: BN-folded fp16 weight images + biases --------------
__global__ void prep_all(const float* __restrict__ W_sa, const float* __restrict__ b_sa,
                         const float* __restrict__ W_s,  const float* __restrict__ b_s,
                         const float* __restrict__ Wk, const float* __restrict__ Wsel,
                         const float* __restrict__ Wv, const float* __restrict__ bv,
                         const float* __restrict__ Wc1,
                         const float* __restrict__ mean, const float* __restrict__ istd,
                         __half* __restrict__ w1h, __half* __restrict__ kvh,
                         __half* __restrict__ selh, __half* __restrict__ c1h,
                         float* __restrict__ b1, float* __restrict__ bkv)
{
    int img = blockIdx.y;
    int a = blockIdx.z;
    int e = blockIdx.x * 256 + threadIdx.x;

    if (img == 0) {
        if (e >= 256 * 160) return;
        int n = e / 160, k = e - n * 160;
        float v = 0.f;
        if (n < 128) { if (k < INP) v = W_sa[((long)a * INP + k) * HID + n] * istd[a * INP + k]; }
        else         { if (k < OBS) v = W_s [((long)a * OBS + k) * HID + (n - 128)] * istd[a * INP + k]; }
        w1h[(long)a * 256 * 160 + e] = __float2half_rn(v);
    } else if (img == 1) {
        if (a != 0 || e >= 256 * 128) return;
        int n = e >> 7, k = e & 127;
        float v = (n < 128) ? Wk[(((n >> 5) * HID) + k) * DHEAD + (n & 31)]
                            : Wv[((((n - 128) >> 5) * HID) + k) * DHEAD + ((n - 128) & 31)];
        kvh[e] = __float2half_rn(v);
    } else if (img == 2) {
        if (a != 0 || e >= 128 * 128) return;
        int n = e >> 7, k = e & 127;
        selh[e] = __float2half_rn(Wsel[(((n >> 5) * HID) + k) * DHEAD + (n & 31)]);
    } else if (img == 3) {
        if (e >= 128 * 256) return;
        int n = e >> 8, k = e & 255;
        c1h[(long)a * 128 * 256 + e] = __float2half_rn(Wc1[((long)a * 2 * HID + k) * HID + n]);
    } else {
        if (blockIdx.x != 0) return;
        int n = threadIdx.x;   // 0..255
        float acc = 0.f;
        if (n < 128) {
            for (int k = 0; k < INP; k++)
                acc += mean[a * INP + k] * istd[a * INP + k] * W_sa[((long)a * INP + k) * HID + n];
            b1[a * 256 + n] = b_sa[a * HID + n] - acc;
        } else {
            for (int k = 0; k < OBS; k++)
                acc += mean[a * INP + k] * istd[a * INP + k] * W_s[((long)a * OBS + k) * HID + (n - 128)];
            b1[a * 256 + n] = b_s[a * HID + (n - 128)] - acc;
        }
        if (a == 0) bkv[n] = (n < 128) ? 0.f : bv[n - 128];
    }
}

// ---------------- tensor-core GEMM (plain fp16, fp32 accum) --------------------
// 4-stage cp.async pipeline (2 outstanding groups allowed), one barrier/chunk,
// issue after compute.
template<int TN, int MINB>
__global__ void __launch_bounds__(256, MINB) gemm_mma(
    const __half* __restrict__ A0h, long sA0, int lda0,
    const __half* __restrict__ A1h, long sA1, int lda1,
    int ksplit, int Kreal,
    const __half* __restrict__ Bh_, long sB, int Kpad,
    const float* __restrict__ bias, long sBias,
    float* __restrict__ C, long sC, int ldc, int actFrom,
    int outHalf, __half* __restrict__ Ch,
    int selFrom, const __half* __restrict__ B2h, float* __restrict__ C2, long sC2,
    int fuseFinal, const float* __restrict__ actions, const float* __restrict__ Wc2,
    const float* __restrict__ bc2, float* __restrict__ outq)
{
    constexpr int BPL_B = TN * STRIDE * 2;      // B plane bytes
    constexpr int BUFB  = PLANE_B + BPL_B;      // stage bytes
    constexpr int NI4   = TN / 32;
    constexpr int WNW   = TN / 2;
    constexpr int BITS  = TN * 4 / 256;

    extern __shared__ __half sm[];
    __shared__ float sWc2[HID * ACT];
    __shared__ int   sIdx[128];
    __shared__ float sQred[2][128];

    int tid = threadIdx.x, wid = tid >> 5, lane = tid & 31;
    int a = blockIdx.z;
    long mBase = (long)blockIdx.x * 128;
    int wm = (wid & 3) * 32;
    int wn = (wid >> 2) * WNW;

    // per-y routing
    int colBase = blockIdx.y * TN;
    int aOff = 0;
    const __half* bhP = Bh_;
    float* Cout = C;
    long sCout = sC;
    int ldcL = ldc;
    const float* biasL = bias;
    int actF = actFrom;
    if ((int)blockIdx.y >= selFrom) {
        aOff = 128; bhP = B2h; colBase = (blockIdx.y - selFrom) * TN;
        Cout = C2; sCout = sC2; ldcL = 128; biasL = nullptr; actF = 1 << 30;
    }
    bhP += (long)a * sB;

    if (fuseFinal) {
        for (int i = tid; i < HID * ACT; i += 256)
            sWc2[i] = Wc2[(long)a * HID * ACT + i];
        if (tid < 128) {
            const float* ap = actions + ((long)a * BATCH + mBase + tid) * ACT;
            float best = ap[0]; int bi = 0;
#pragma unroll
            for (int j = 1; j < ACT; j++) {
                float x = ap[j];
                if (x > best) { best = x; bi = j; }
            }
            sIdx[tid] = bi;
        }
    }

    float acc[2][2 * NI4][4];
#pragma unroll
    for (int i = 0; i < 2; i++)
#pragma unroll
        for (int j = 0; j < 2 * NI4; j++)
#pragma unroll
            for (int q = 0; q < 4; q++) acc[i][j][q] = 0.f;

    uint32_t smB = smem_u32(sm);
    int nChunks = Kpad / CHUNK;

    // ---- hoisted issue-side addressing ----
    int aKK[2];
    uint32_t aD[2];
    const __half *aP0[2], *aP1[2];
#pragma unroll
    for (int it = 0; it < 2; it++) {
        int i = tid + it * 256;
        int row = i >> 2, kk = (i & 3) * 8;
        aKK[it] = kk;
        aD[it] = (uint32_t)((row * STRIDE + kk) * 2);
        aP0[it] = A0h + (long)a * sA0 + (mBase + row) * (long)lda0 + aOff + kk;
        aP1[it] = A1h ? A1h + (long)a * sA1 + (mBase + row) * (long)lda1 + (kk - ksplit) : A0h;
    }
    uint32_t bD[BITS];
    const __half* bP[BITS];
#pragma unroll
    for (int it = 0; it < BITS; it++) {
        int i = tid + it * 256;
        int n = i >> 2, kk = (i & 3) * 8;
        bD[it] = (uint32_t)((n * STRIDE + kk) * 2);
        bP[it] = bhP + (long)(colBase + n) * Kpad + kk;
    }

    auto issue = [&](int c, int buf) {
        uint32_t base = smB + (uint32_t)(buf * BUFB);
        int k0 = c * CHUNK;
#pragma unroll
        for (int it = 0; it < 2; it++) {
            int kg = k0 + aKK[it];
            const __half* ph = (kg < ksplit) ? aP0[it] + k0 : aP1[it] + k0;
            int ok = (kg < Kreal);
            if (!ok) ph = A0h;
            cp16p(base + aD[it], ph, ok);
        }
#pragma unroll
        for (int it = 0; it < BITS; it++)
            cp16(base + PLANE_B + bD[it], bP[it] + k0);
        cp_commit();
    };

    // hoisted compute-side in-buffer byte offsets
    int lr16 = lane & 15, lh16 = (lane >> 4) * 8;
    int lr8 = lane & 7, lk8 = ((lane >> 3) & 1) * 8, ln8 = (lane >> 4) * 8;
    uint32_t aHoff[2], bOff[NI4];
#pragma unroll
    for (int mi = 0; mi < 2; mi++)
        aHoff[mi] = (uint32_t)(((wm + mi * 16 + lr16) * STRIDE + lh16) * 2);
#pragma unroll
    for (int ni4 = 0; ni4 < NI4; ni4++)
        bOff[ni4] = (uint32_t)(((wn + ni4 * 16 + ln8 + lr8) * STRIDE + lk8) * 2) + PLANE_B;

    // prologue: up to 3 chunks in flight
    int issued = 0;
    for (; issued < 3 && issued < nChunks; issued++) issue(issued, issued);

    for (int c = 0; c < nChunks; c++) {
        int pending = issued - c;          // groups c .. issued-1 outstanding
        if (pending >= 3)      cp_wait2(); // chunk c complete, 2 still pending
        else if (pending == 2) cp_wait1();
        else                   cp_wait0();
        __syncthreads();

        uint32_t base = smB + (uint32_t)((c & 3) * BUFB);
#pragma unroll
        for (int ks = 0; ks < CHUNK; ks += 16) {
            uint32_t ah[2][4];
#pragma unroll
            for (int mi = 0; mi < 2; mi++)
                ldm_x4(ah[mi], base + aHoff[mi] + ks * 2);
#pragma unroll
            for (int ni4 = 0; ni4 < NI4; ni4++) {
                uint32_t bh[4];
                ldm_x4(bh, base + bOff[ni4] + ks * 2);
#pragma unroll
                for (int mi = 0; mi < 2; mi++) {
                    mma_f16(acc[mi][ni4 * 2],     ah[mi], bh[0], bh[1]);
                    mma_f16(acc[mi][ni4 * 2 + 1], ah[mi], bh[2], bh[3]);
                }
            }
        }

        // prefetch into buffer (c+3)&3 = (c-1)&3: last read at compute(c-1),
        // all threads passed this iteration's barrier since then.
        if (issued < nChunks) { issue(issued, issued & 3); issued++; }
    }

    // ---- epilogue ----
    int gr = lane >> 2, tg = lane & 3;

    if constexpr (TN == 128) {
        if (fuseFinal) {
            float p[4] = {0.f, 0.f, 0.f, 0.f};
#pragma unroll
            for (int mi = 0; mi < 2; mi++) {
                int ra = wm + mi * 16 + gr;
                int rb = ra + 8;
                int ia = sIdx[ra], ib = sIdx[rb];
#pragma unroll
                for (int ni = 0; ni < 2 * NI4; ni++) {
                    int col = wn + ni * 8 + tg * 2;
                    const float* bp = biasL + (long)a * sBias + col;
                    float b0 = bp[0], b1 = bp[1];
                    float v0 = acc[mi][ni][0] + b0;
                    float v1 = acc[mi][ni][1] + b1;
                    float v2 = acc[mi][ni][2] + b0;
                    float v3 = acc[mi][ni][3] + b1;
                    v0 = v0 > 0.f ? v0 : 0.01f * v0;
                    v1 = v1 > 0.f ? v1 : 0.01f * v1;
                    v2 = v2 > 0.f ? v2 : 0.01f * v2;
                    v3 = v3 > 0.f ? v3 : 0.01f * v3;
                    p[mi * 2]     += v0 * sWc2[col * ACT + ia] + v1 * sWc2[(col + 1) * ACT + ia];
                    p[mi * 2 + 1] += v2 * sWc2[col * ACT + ib] + v3 * sWc2[(col + 1) * ACT + ib];
                }
            }
#pragma unroll
            for (int q = 0; q < 4; q++) {
                p[q] += __shfl_xor_sync(0xffffffffu, p[q], 1);
                p[q] += __shfl_xor_sync(0xffffffffu, p[q], 2);
            }
            int nh = wid >> 2;
            if (tg == 0) {
                sQred[nh][wm + gr]      = p[0];
                sQred[nh][wm + gr + 8]  = p[1];
                sQred[nh][wm + gr + 16] = p[2];
                sQred[nh][wm + gr + 24] = p[3];
            }
            __syncthreads();
            if (tid < 128) {
                float q = sQred[0][tid] + sQred[1][tid] + bc2[a * ACT + sIdx[tid]];
                outq[(long)a * BATCH + mBase + tid] = q;
            }
            return;
        }
    }

#pragma unroll
    for (int mi = 0; mi < 2; mi++) {
        long row0 = mBase + wm + mi * 16 + gr;
        long row1 = row0 + 8;
#pragma unroll
        for (int ni = 0; ni < 2 * NI4; ni++) {
            int col = colBase + wn + ni * 8 + tg * 2;
            float b0 = 0.f, b1 = 0.f;
            if (biasL) {
                const float* bp = biasL + (long)a * sBias + col;
                b0 = bp[0]; b1 = bp[1];
            }
            float v0 = acc[mi][ni][0] + b0;
            float v1 = acc[mi][ni][1] + b1;
            float v2 = acc[mi][ni][2] + b0;
            float v3 = acc[mi][ni][3] + b1;
            if (col >= actF) {
                v0 = v0 > 0.f ? v0 : 0.01f * v0;
                v2 = v2 > 0.f ? v2 : 0.01f * v2;
            }
            if (col + 1 >= actF) {
                v1 = v1 > 0.f ? v1 : 0.01f * v1;
                v3 = v3 > 0.f ? v3 : 0.01f * v3;
            }
            if (outHalf) {
                long o0 = (long)a * sCout + row0 * ldcL + col;
                long o1 = (long)a * sCout + row1 * ldcL + col;
                __half h0 = __float2half_rn(v0), h1 = __float2half_rn(v1);
                __half h2 = __float2half_rn(v2), h3 = __float2half_rn(v3);
                *(uint32_t*)(Ch + o0) = (uint32_t)__half_as_ushort(h0) |
                                        ((uint32_t)__half_as_ushort(h1) << 16);
                *(uint32_t*)(Ch + o1) = (uint32_t)__half_as_ushort(h2) |
                                        ((uint32_t)__half_as_ushort(h3) << 16);
            } else {
                float* Cp = Cout + (long)a * sCout;
                *(float2*)(Cp + row0 * ldcL + col) = make_float2(v0, v1);
                *(float2*)(Cp + row1 * ldcL + col) = make_float2(v2, v3);
            }
        }
    }
}

// ---------------- attention: smem-tiled, one CTA per 2 batch indices ----------
__global__ void __launch_bounds__(256) attn_kernel(
    const float* __restrict__ KV, const float* __restrict__ St,
    __half* __restrict__ oH)
{
    __shared__ float sKV[2][16][256];
    __shared__ float sS [2][16][128];

    int tid = threadIdx.x;
    long b0 = (long)blockIdx.x * 2;

    for (int idx = tid; idx < 2048; idx += 256) {
        int c4 = idx & 63;
        int row = idx >> 6;
        int b_l = row >> 4, j = row & 15;
        ((float4*)&sKV[b_l][j][0])[c4] =
            ((const float4*)(KV + ((long)j * BATCH + b0 + b_l) * 256))[c4];
    }
    for (int idx = tid; idx < 1024; idx += 256) {
        int c4 = idx & 31;
        int row = idx >> 5;
        int b_l = row >> 4, j = row & 15;
        ((float4*)&sS[b_l][j][0])[c4] =
            ((const float4*)(St + ((long)j * BATCH + b0 + b_l) * 128))[c4];
    }
    __syncthreads();

    int wid = tid >> 5, lane = tid & 31;
    int b_l = wid >> 2, n = wid & 3;
    long b = b0 + b_l;
    int col = n * DHEAD + lane;

    float Kr[16], Vr[16];
#pragma unroll
    for (int j = 0; j < 16; j++) {
        Kr[j] = sKV[b_l][j][col];
        Vr[j] = sKV[b_l][j][128 + col];
    }

    for (int i = 0; i < 16; i++) {
        float selv = sS[b_l][i][col];
        float lg = -3e38f;
#pragma unroll
        for (int j = 0; j < 16; j++) {
            float p = selv * Kr[j];
#pragma unroll
            for (int off = 16; off; off >>= 1) p += __shfl_xor_sync(0xffffffffu, p, off);
            if (lane == j) lg = (j == i) ? -1e9f : p * 0.17677669529663687f;
        }
        float mx = lg;
#pragma unroll
        for (int off = 16; off; off >>= 1) mx = fmaxf(mx, __shfl_xor_sync(0xffffffffu, mx, off));
        float e = (lane < 16) ? __expf(lg - mx) : 0.f;
        float den = e;
#pragma unroll
        for (int off = 16; off; off >>= 1) den += __shfl_xor_sync(0xffffffffu, den, off);
        float w = e / den;

        float acc = 0.f;
#pragma unroll
        for (int j = 0; j < 16; j++) {
            float wj = __shfl_sync(0xffffffffu, w, j);
            acc = fmaf(wj, Vr[j], acc);
        }
        oH[((long)i * BATCH + b) * HID + col] = __float2half_rn(acc);
    }
}

// ---------------- launch -------------------------------------------------------
static float* symaddr(const void* sym)
{
    void* p = nullptr;
    cudaGetSymbolAddress(&p, sym);
    return (float*)p;
}
static __half* symaddr_h(const void* sym)
{
    void* p = nullptr;
    cudaGetSymbolAddress(&p, sym);
    return (__half*)p;
}

extern "C" void kernel_launch(void* const* d_in, const int* in_sizes, int n_in,
                              void* d_out, int out_size)
{
    const float* obs     = (const float*)d_in[0];
    const float* actions = (const float*)d_in[1];
    const float* W_sa    = (const float*)d_in[2];
    const float* b_sa    = (const float*)d_in[3];
    const float* W_s     = (const float*)d_in[4];
    const float* b_s     = (const float*)d_in[5];
    const float* Wk      = (const float*)d_in[6];
    const float* Wsel    = (const float*)d_in[7];
    const float* Wv      = (const float*)d_in[8];
    const float* bv      = (const float*)d_in[9];
    const float* Wc1     = (const float*)d_in[10];
    const float* bc1     = (const float*)d_in[11];
    const float* Wc2     = (const float*)d_in[12];
    const float* bc2     = (const float*)d_in[13];
    float* out = (float*)d_out;

    float* ps    = symaddr(g_ps);
    float* ps2   = symaddr(g_ps2);
    float* mean  = symaddr(g_mean);
    float* istd  = symaddr(g_istd);
    float* b1    = symaddr(g_b1);
    float* bkv   = symaddr(g_bkv);
    float* KV    = symaddr(g_KV);
    float* St    = symaddr(g_S);

    __half* w1h  = symaddr_h(w1_h);
    __half* kvh  = symaddr_h(wkv_h);
    __half* selh = symaddr_h(wsel_h);
    __half* c1h  = symaddr_h(wc1_h);
    __half* obsH = symaddr_h(g_obsH);
    __half* actH = symaddr_h(g_actH);
    __half* aseH = symaddr_h(g_aseH);
    __half* othH = symaddr_h(g_othH);

    const size_t smem128 = 4 * (PLANE_B + 128 * STRIDE * 2);   // 81920

    static bool attr_set = false;
    if (!attr_set) {
        cudaFuncSetAttribute(gemm_mma<128, 2>, cudaFuncAttributeMaxDynamicSharedMemorySize, smem128);
        attr_set = true;
    }

    const long sOBS = (long)BATCH * OBS;
    const long sACT = (long)BATCH * ACT;
    const long sASE = (long)BATCH * 256;
    const long sH   = (long)BATCH * HID;

    // 0
    bn_part_kernel<<<dim3(AGENTS, 5, 8), dim3(32, 32)>>>(obs, actions, ps, ps2, obsH, actH);
    // 1
    bn_fin_kernel<<<AGENTS, 160>>>(ps, ps2, mean, istd);
    // 2
    prep_all<<<dim3(160, 5, AGENTS), 256>>>(W_sa, b_sa, W_s, b_s, Wk, Wsel, Wv, bv,
                                            Wc1, mean, istd,
                                            w1h, kvh, selh, c1h, b1, bkv);

    // 3: ase = lrelu(bn([obs|act]) @ [W_sa|W_s] + b1)  K=144->160, N=256 (2 x 128)
    gemm_mma<128, 2><<<dim3(BATCH / 128, 2, AGENTS), 256, smem128>>>(
        obsH, sOBS, OBS, actH, sACT, ACT, OBS, INP,
        w1h, (long)256 * 160, 160,
        b1, 256, nullptr, sASE, 256, 0,
        1, aseH,
        1 << 28, nullptr, nullptr, 0,
        0, nullptr, nullptr, nullptr, nullptr);

    // 4: merged KV + Sel.  y<2: KV = sa @ [Wk|Wv] (N=256); y==2: S = se @ Wsel
    gemm_mma<128, 2><<<dim3(BATCH / 128, 3, AGENTS), 256, smem128>>>(
        aseH, sASE, 256, aseH, 0, 0, 1 << 30, HID,
        kvh, 0, HID,
        bkv, 0, KV, sASE, 256, 128,
        0, nullptr,
        2, selh, St, sH,
        0, nullptr, nullptr, nullptr, nullptr);

    // 5: attention (smem-tiled) -> other (fp16)
    attn_kernel<<<BATCH / 2, 256>>>(KV, St, othH);

    // 6: q = fused( lrelu([se|other] @ Wc1 + bc1) . Wc2[:,argmax] + bc2 )  K=256
    gemm_mma<128, 2><<<dim3(BATCH / 128, 1, AGENTS), 256, smem128>>>(
        aseH + 128, sASE, 256, othH, sH, HID, HID, 2 * HID,
        c1h, (long)HID * 2 * HID, 2 * HID,
        bc1, HID, nullptr, 0, 0, 1 << 30,
        0, nullptr,
        1 << 28, nullptr, nullptr, 0,
        1, actions, Wc2, bc2, out);
}

// round 17
// speedup vs baseline: 1.4139x; 1.0199x over previous
#include <cuda_runtime.h>
#include <cuda_fp16.h>
#include <cstdint>

#define AGENTS 16
#define BATCH  8192
#define OBS    128
#define ACT    16
#define HID    128
#define NHEAD  4
#define DHEAD  32
#define INP    (OBS + ACT)   // 144

// ---------------- scratch (static device globals; no runtime alloc) -----------
__device__ float g_ps [AGENTS * 160 * 8];
__device__ float g_ps2[AGENTS * 160 * 8];
__device__ float g_mean[AGENTS * INP];
__device__ float g_istd[AGENTS * INP];
__device__ float g_b1  [AGENTS * 256];       // [bsaf | bsf]
__device__ float g_bkv [256];                // [0 | bv]
// fp16 weight images, [n][Kpad] row-major (B^T)
__device__ __half w1_h [(long)AGENTS * 256 * 160];
__device__ __half wkv_h[256 * HID];
__device__ __half wsel_h[HID * HID];
__device__ __half wc1_h[(long)AGENTS * HID * 2 * HID];
// fp16 activation planes
__device__ __half g_obsH[(long)AGENTS * BATCH * OBS];
__device__ __half g_actH[(long)AGENTS * BATCH * ACT];
__device__ __half g_aseH[(long)AGENTS * BATCH * 256];   // [sa | se]
__device__ __half g_othH[(long)AGENTS * BATCH * HID];
__device__ __half g_KVh [(long)AGENTS * BATCH * 256];   // [K | V] fp16
// fp32 buffer for sel (precision-sensitive logits input)
__device__ float g_S    [(long)AGENTS * BATCH * HID];

// ---------------- helpers ------------------------------------------------------
__device__ __forceinline__ uint32_t smem_u32(const void* p) {
    uint32_t r;
    asm("{ .reg .u64 t; cvta.to.shared.u64 t, %1; cvt.u32.u64 %0, t; }" : "=r"(r) : "l"(p));
    return r;
}
__device__ __forceinline__ void ldm_x4(uint32_t* r, uint32_t addr) {
    asm volatile("ldmatrix.sync.aligned.m8n8.x4.shared.b16 {%0,%1,%2,%3}, [%4];"
                 : "=r"(r[0]), "=r"(r[1]), "=r"(r[2]), "=r"(r[3]) : "r"(addr));
}
__device__ __forceinline__ void mma_f16(float* c, const uint32_t* a, uint32_t b0, uint32_t b1) {
    asm volatile("mma.sync.aligned.m16n8k16.row.col.f32.f16.f16.f32 "
                 "{%0,%1,%2,%3}, {%4,%5,%6,%7}, {%8,%9}, {%0,%1,%2,%3};"
                 : "+f"(c[0]), "+f"(c[1]), "+f"(c[2]), "+f"(c[3])
                 : "r"(a[0]), "r"(a[1]), "r"(a[2]), "r"(a[3]), "r"(b0), "r"(b1));
}
__device__ __forceinline__ void cp16(uint32_t dst, const void* src) {
    asm volatile("cp.async.cg.shared.global [%0], [%1], 16;" :: "r"(dst), "l"(src));
}
__device__ __forceinline__ void cp16p(uint32_t dst, const void* src, int ok) {
    asm volatile("{\n\t.reg .pred p;\n\tsetp.ne.b32 p, %2, 0;\n\t"
                 "@p cp.async.cg.shared.global [%0], [%1], 16;\n\t"
                 "@!p cp.async.cg.shared.global [%0], [%1], 16, 0;\n\t}"
                 :: "r"(dst), "l"(src), "r"(ok));
}
__device__ __forceinline__ void cp_commit() { asm volatile("cp.async.commit_group;" ::: "memory"); }
__device__ __forceinline__ void cp_wait2()  { asm volatile("cp.async.wait_group 2;" ::: "memory"); }
__device__ __forceinline__ void cp_wait1()  { asm volatile("cp.async.wait_group 1;" ::: "memory"); }
__device__ __forceinline__ void cp_wait0()  { asm volatile("cp.async.wait_group 0;" ::: "memory"); }

// ---------------- BN pass 1: partial sums + fp16 planes ------------------------
__global__ void bn_part_kernel(const float* __restrict__ obs,
                               const float* __restrict__ actions,
                               float* __restrict__ ps, float* __restrict__ ps2,
                               __half* __restrict__ oH, __half* __restrict__ aH)
{
    int a = blockIdx.x;
    int f = blockIdx.y * 32 + threadIdx.x;
    int seg = blockIdx.z;
    float s = 0.f, s2 = 0.f;
    if (f < INP) {
        if (f < OBS) {
            long base = (long)a * BATCH * OBS + (long)seg * 1024 * OBS + f;
            const float* src = obs + base;
            for (int b = threadIdx.y; b < 1024; b += 32) {
                float x = src[(long)b * OBS]; s += x; s2 += x * x;
                oH[base + (long)b * OBS] = __float2half_rn(x);
            }
        } else {
            long base = (long)a * BATCH * ACT + (long)seg * 1024 * ACT + (f - OBS);
            const float* src = actions + base;
            for (int b = threadIdx.y; b < 1024; b += 32) {
                float x = src[(long)b * ACT]; s += x; s2 += x * x;
                aH[base + (long)b * ACT] = __float2half_rn(x);
            }
        }
    }
    __shared__ float sh1[32][33];
    __shared__ float sh2[32][33];
    sh1[threadIdx.y][threadIdx.x] = s;
    sh2[threadIdx.y][threadIdx.x] = s2;
    __syncthreads();
    for (int st = 16; st > 0; st >>= 1) {
        if (threadIdx.y < st) {
            sh1[threadIdx.y][threadIdx.x] += sh1[threadIdx.y + st][threadIdx.x];
            sh2[threadIdx.y][threadIdx.x] += sh2[threadIdx.y + st][threadIdx.x];
        }
        __syncthreads();
    }
    if (threadIdx.y == 0) {
        int fi = blockIdx.y * 32 + threadIdx.x;
        ps [(a * 160 + fi) * 8 + seg] = sh1[0][threadIdx.x];
        ps2[(a * 160 + fi) * 8 + seg] = sh2[0][threadIdx.x];
    }
}

// ---------------- BN pass 2 -----------------------------------------------------
__global__ void bn_fin_kernel(const float* __restrict__ ps, const float* __restrict__ ps2,
                              float* __restrict__ mean, float* __restrict__ istd)
{
    int a = blockIdx.x;
    int f = threadIdx.x;
    if (f >= INP) return;
    float s = 0.f, s2 = 0.f;
    for (int seg = 0; seg < 8; seg++) {
        s  += ps [(a * 160 + f) * 8 + seg];
        s2 += ps2[(a * 160 + f) * 8 + seg];
    }
    float m = s * (1.0f / BATCH);
    float v = s2 * (1.0f / BATCH) - m * m;
    mean[a * INP + f] = m;
    istd[a * INP + f] = rsqrtf(v + 1e-5f);
}

// ---------------- prep_all: BN-folded fp16 weight images + biases --------------
__global__ void prep_all(const float* __restrict__ W_sa, const float* __restrict__ b_sa,
                         const float* __restrict__ W_s,  const float* __restrict__ b_s,
                         const float* __restrict__ Wk, const float* __restrict__ Wsel,
                         const float* __restrict__ Wv, const float* __restrict__ bv,
                         const float* __restrict__ Wc1,
                         const float* __restrict__ mean, const float* __restrict__ istd,
                         __half* __restrict__ w1h, __half* __restrict__ kvh,
                         __half* __restrict__ selh, __half* __restrict__ c1h,
                         float* __restrict__ b1, float* __restrict__ bkv)
{
    int img = blockIdx.y;
    int a = blockIdx.z;
    int e = blockIdx.x * 256 + threadIdx.x;

    if (img == 0) {
        if (e >= 256 * 160) return;
        int n = e / 160, k = e - n * 160;
        float v = 0.f;
        if (n < 128) { if (k < INP) v = W_sa[((long)a * INP + k) * HID + n] * istd[a * INP + k]; }
        else         { if (k < OBS) v = W_s [((long)a * OBS + k) * HID + (n - 128)] * istd[a * INP + k]; }
        w1h[(long)a * 256 * 160 + e] = __float2half_rn(v);
    } else if (img == 1) {
        if (a != 0 || e >= 256 * 128) return;
        int n = e >> 7, k = e & 127;
        float v = (n < 128) ? Wk[(((n >> 5) * HID) + k) * DHEAD + (n & 31)]
                            : Wv[((((n - 128) >> 5) * HID) + k) * DHEAD + ((n - 128) & 31)];
        kvh[e] = __float2half_rn(v);
    } else if (img == 2) {
        if (a != 0 || e >= 128 * 128) return;
        int n = e >> 7, k = e & 127;
        selh[e] = __float2half_rn(Wsel[(((n >> 5) * HID) + k) * DHEAD + (n & 31)]);
    } else if (img == 3) {
        if (e >= 128 * 256) return;
        int n = e >> 8, k = e & 255;
        c1h[(long)a * 128 * 256 + e] = __float2half_rn(Wc1[((long)a * 2 * HID + k) * HID + n]);
    } else {
        if (blockIdx.x != 0) return;
        int n = threadIdx.x;   // 0..255
        float acc = 0.f;
        if (n < 128) {
            for (int k = 0; k < INP; k++)
                acc += mean[a * INP + k] * istd[a * INP + k] * W_sa[((long)a * INP + k) * HID + n];
            b1[a * 256 + n] = b_sa[a * HID + n] - acc;
        } else {
            for (int k = 0; k < OBS; k++)
                acc += mean[a * INP + k] * istd[a * INP + k] * W_s[((long)a * OBS + k) * HID + (n - 128)];
            b1[a * 256 + n] = b_s[a * HID + (n - 128)] - acc;
        }
        if (a == 0) bkv[n] = (n < 128) ? 0.f : bv[n - 128];
    }
}

// ---------------- tensor-core GEMM (plain fp16, fp32 accum) --------------------
// Template: TN tile-N, KCH chunk size, STAGES pipeline buffers.
// Routing: y >= selFrom -> (A+128, B2 image, C2 fp32 out).
template<int TN, int KCH, int STAGES>
__global__ void __launch_bounds__(256, 2) gemm_mma(
    const __half* __restrict__ A0h, long sA0, int lda0,
    const __half* __restrict__ A1h, long sA1, int lda1,
    int ksplit, int Kreal,
    const __half* __restrict__ Bh_, long sB, int Kpad,
    const float* __restrict__ bias, long sBias,
    float* __restrict__ C, long sC, int ldc, int actFrom,
    int outHalf, __half* __restrict__ Ch,
    int selFrom, const __half* __restrict__ B2h, float* __restrict__ C2, long sC2,
    int fuseFinal, const float* __restrict__ actions, const float* __restrict__ Wc2,
    const float* __restrict__ bc2, float* __restrict__ outq)
{
    constexpr int STR   = KCH + 8;
    constexpr int APL   = 128 * STR * 2;        // A plane bytes
    constexpr int BPL   = TN * STR * 2;         // B plane bytes
    constexpr int BUFB  = APL + BPL;
    constexpr int NI4   = TN / 32;
    constexpr int WNW   = TN / 2;
    constexpr int QR    = KCH / 8;              // 8-elem quads per row
    constexpr int AITS  = 128 * QR / 256;
    constexpr int BITS  = TN * QR / 256;
    constexpr int PRE   = STAGES - 1;

    extern __shared__ __half sm[];
    __shared__ float sWc2[HID * ACT];
    __shared__ int   sIdx[128];
    __shared__ float sQred[2][128];

    int tid = threadIdx.x, wid = tid >> 5, lane = tid & 31;
    int a = blockIdx.z;
    long mBase = (long)blockIdx.x * 128;
    int wm = (wid & 3) * 32;
    int wn = (wid >> 2) * WNW;

    // per-y routing
    int colBase = blockIdx.y * TN;
    int aOff = 0;
    const __half* bhP = Bh_;
    float* Cout = C;
    long sCout = sC;
    int ldcL = ldc;
    const float* biasL = bias;
    int actF = actFrom;
    int outH = outHalf;
    if ((int)blockIdx.y >= selFrom) {
        aOff = 128; bhP = B2h; colBase = (blockIdx.y - selFrom) * TN;
        Cout = C2; sCout = sC2; ldcL = 128; biasL = nullptr; actF = 1 << 30; outH = 0;
    }
    bhP += (long)a * sB;

    if (fuseFinal) {
        for (int i = tid; i < HID * ACT; i += 256)
            sWc2[i] = Wc2[(long)a * HID * ACT + i];
        if (tid < 128) {
            const float* ap = actions + ((long)a * BATCH + mBase + tid) * ACT;
            float best = ap[0]; int bi = 0;
#pragma unroll
            for (int j = 1; j < ACT; j++) {
                float x = ap[j];
                if (x > best) { best = x; bi = j; }
            }
            sIdx[tid] = bi;
        }
    }

    float acc[2][2 * NI4][4];
#pragma unroll
    for (int i = 0; i < 2; i++)
#pragma unroll
        for (int j = 0; j < 2 * NI4; j++)
#pragma unroll
            for (int q = 0; q < 4; q++) acc[i][j][q] = 0.f;

    uint32_t smB = smem_u32(sm);
    int nChunks = Kpad / KCH;

    // ---- hoisted issue-side addressing ----
    int aKK[AITS];
    uint32_t aD[AITS];
    const __half *aP0[AITS], *aP1[AITS];
#pragma unroll
    for (int it = 0; it < AITS; it++) {
        int i = tid + it * 256;
        int row = i / QR, kk = (i % QR) * 8;
        aKK[it] = kk;
        aD[it] = (uint32_t)((row * STR + kk) * 2);
        aP0[it] = A0h + (long)a * sA0 + (mBase + row) * (long)lda0 + aOff + kk;
        aP1[it] = A1h ? A1h + (long)a * sA1 + (mBase + row) * (long)lda1 + (kk - ksplit) : A0h;
    }
    uint32_t bD[BITS];
    const __half* bP[BITS];
#pragma unroll
    for (int it = 0; it < BITS; it++) {
        int i = tid + it * 256;
        int n = i / QR, kk = (i % QR) * 8;
        bD[it] = (uint32_t)((n * STR + kk) * 2);
        bP[it] = bhP + (long)(colBase + n) * Kpad + kk;
    }

    auto issue = [&](int c, int buf) {
        uint32_t base = smB + (uint32_t)(buf * BUFB);
        int k0 = c * KCH;
#pragma unroll
        for (int it = 0; it < AITS; it++) {
            int kg = k0 + aKK[it];
            const __half* ph = (kg < ksplit) ? aP0[it] + k0 : aP1[it] + k0;
            int ok = (kg < Kreal);
            if (!ok) ph = A0h;
            cp16p(base + aD[it], ph, ok);
        }
#pragma unroll
        for (int it = 0; it < BITS; it++)
            cp16(base + APL + bD[it], bP[it] + k0);
        cp_commit();
    };

    // hoisted compute-side in-buffer byte offsets
    int lr16 = lane & 15, lh16 = (lane >> 4) * 8;
    int lr8 = lane & 7, lk8 = ((lane >> 3) & 1) * 8, ln8 = (lane >> 4) * 8;
    uint32_t aHoff[2], bOff[NI4];
#pragma unroll
    for (int mi = 0; mi < 2; mi++)
        aHoff[mi] = (uint32_t)(((wm + mi * 16 + lr16) * STR + lh16) * 2);
#pragma unroll
    for (int ni4 = 0; ni4 < NI4; ni4++)
        bOff[ni4] = (uint32_t)(((wn + ni4 * 16 + ln8 + lr8) * STR + lk8) * 2) + APL;

    // prologue
    int issued = 0;
    for (; issued < PRE && issued < nChunks; issued++) issue(issued, issued % STAGES);

    for (int c = 0; c < nChunks; c++) {
        int pending = issued - c;
        if (pending >= 3)      cp_wait2();
        else if (pending == 2) cp_wait1();
        else                   cp_wait0();
        __syncthreads();

        uint32_t base = smB + (uint32_t)((c % STAGES) * BUFB);
#pragma unroll
        for (int ks = 0; ks < KCH; ks += 16) {
            uint32_t ah[2][4];
#pragma unroll
            for (int mi = 0; mi < 2; mi++)
                ldm_x4(ah[mi], base + aHoff[mi] + ks * 2);
#pragma unroll
            for (int ni4 = 0; ni4 < NI4; ni4++) {
                uint32_t bh[4];
                ldm_x4(bh, base + bOff[ni4] + ks * 2);
#pragma unroll
                for (int mi = 0; mi < 2; mi++) {
                    mma_f16(acc[mi][ni4 * 2],     ah[mi], bh[0], bh[1]);
                    mma_f16(acc[mi][ni4 * 2 + 1], ah[mi], bh[2], bh[3]);
                }
            }
        }

        if (issued < nChunks) { issue(issued, issued % STAGES); issued++; }
    }

    // ---- epilogue ----
    int gr = lane >> 2, tg = lane & 3;

    if constexpr (TN == 128) {
        if (fuseFinal) {
            float p[4] = {0.f, 0.f, 0.f, 0.f};
#pragma unroll
            for (int mi = 0; mi < 2; mi++) {
                int ra = wm + mi * 16 + gr;
                int rb = ra + 8;
                int ia = sIdx[ra], ib = sIdx[rb];
#pragma unroll
                for (int ni = 0; ni < 2 * NI4; ni++) {
                    int col = wn + ni * 8 + tg * 2;
                    const float* bp = biasL + (long)a * sBias + col;
                    float b0 = bp[0], b1 = bp[1];
                    float v0 = acc[mi][ni][0] + b0;
                    float v1 = acc[mi][ni][1] + b1;
                    float v2 = acc[mi][ni][2] + b0;
                    float v3 = acc[mi][ni][3] + b1;
                    v0 = v0 > 0.f ? v0 : 0.01f * v0;
                    v1 = v1 > 0.f ? v1 : 0.01f * v1;
                    v2 = v2 > 0.f ? v2 : 0.01f * v2;
                    v3 = v3 > 0.f ? v3 : 0.01f * v3;
                    p[mi * 2]     += v0 * sWc2[col * ACT + ia] + v1 * sWc2[(col + 1) * ACT + ia];
                    p[mi * 2 + 1] += v2 * sWc2[col * ACT + ib] + v3 * sWc2[(col + 1) * ACT + ib];
                }
            }
#pragma unroll
            for (int q = 0; q < 4; q++) {
                p[q] += __shfl_xor_sync(0xffffffffu, p[q], 1);
                p[q] += __shfl_xor_sync(0xffffffffu, p[q], 2);
            }
            int nh = wid >> 2;
            if (tg == 0) {
                sQred[nh][wm + gr]      = p[0];
                sQred[nh][wm + gr + 8]  = p[1];
                sQred[nh][wm + gr + 16] = p[2];
                sQred[nh][wm + gr + 24] = p[3];
            }
            __syncthreads();
            if (tid < 128) {
                float q = sQred[0][tid] + sQred[1][tid] + bc2[a * ACT + sIdx[tid]];
                outq[(long)a * BATCH + mBase + tid] = q;
            }
            return;
        }
    }

#pragma unroll
    for (int mi = 0; mi < 2; mi++) {
        long row0 = mBase + wm + mi * 16 + gr;
        long row1 = row0 + 8;
#pragma unroll
        for (int ni = 0; ni < 2 * NI4; ni++) {
            int col = colBase + wn + ni * 8 + tg * 2;
            float b0 = 0.f, b1 = 0.f;
            if (biasL) {
                const float* bp = biasL + (long)a * sBias + col;
                b0 = bp[0]; b1 = bp[1];
            }
            float v0 = acc[mi][ni][0] + b0;
            float v1 = acc[mi][ni][1] + b1;
            float v2 = acc[mi][ni][2] + b0;
            float v3 = acc[mi][ni][3] + b1;
            if (col >= actF) {
                v0 = v0 > 0.f ? v0 : 0.01f * v0;
                v2 = v2 > 0.f ? v2 : 0.01f * v2;
            }
            if (col + 1 >= actF) {
                v1 = v1 > 0.f ? v1 : 0.01f * v1;
                v3 = v3 > 0.f ? v3 : 0.01f * v3;
            }
            if (outH) {
                long o0 = (long)a * sCout + row0 * ldcL + col;
                long o1 = (long)a * sCout + row1 * ldcL + col;
                __half h0 = __float2half_rn(v0), h1 = __float2half_rn(v1);
                __half h2 = __float2half_rn(v2), h3 = __float2half_rn(v3);
                *(uint32_t*)(Ch + o0) = (uint32_t)__half_as_ushort(h0) |
                                        ((uint32_t)__half_as_ushort(h1) << 16);
                *(uint32_t*)(Ch + o1) = (uint32_t)__half_as_ushort(h2) |
                                        ((uint32_t)__half_as_ushort(h3) << 16);
            } else {
                float* Cp = Cout + (long)a * sCout;
                *(float2*)(Cp + row0 * ldcL + col) = make_float2(v0, v1);
                *(float2*)(Cp + row1 * ldcL + col) = make_float2(v2, v3);
            }
        }
    }
}

// ---------------- attention: smem-tiled, KV fp16, S fp32 ----------------------
__global__ void __launch_bounds__(256) attn_kernel(
    const __half* __restrict__ KV, const float* __restrict__ St,
    __half* __restrict__ oH)
{
    __shared__ __half sKV[2][16][256];
    __shared__ float  sS [2][16][128];

    int tid = threadIdx.x;
    long b0 = (long)blockIdx.x * 2;

    // KV: 2*16*256 halves = 1024 uint4
    for (int idx = tid; idx < 1024; idx += 256) {
        int c8 = idx & 31;                 // 32 uint4 per row
        int row = idx >> 5;                // 0..31
        int b_l = row >> 4, j = row & 15;
        ((uint4*)&sKV[b_l][j][0])[c8] =
            ((const uint4*)(KV + ((long)j * BATCH + b0 + b_l) * 256))[c8];
    }
    for (int idx = tid; idx < 1024; idx += 256) {
        int c4 = idx & 31;
        int row = idx >> 5;
        int b_l = row >> 4, j = row & 15;
        ((float4*)&sS[b_l][j][0])[c4] =
            ((const float4*)(St + ((long)j * BATCH + b0 + b_l) * 128))[c4];
    }
    __syncthreads();

    int wid = tid >> 5, lane = tid & 31;
    int b_l = wid >> 2, n = wid & 3;
    long b = b0 + b_l;
    int col = n * DHEAD + lane;

    float Kr[16], Vr[16];
#pragma unroll
    for (int j = 0; j < 16; j++) {
        Kr[j] = __half2float(sKV[b_l][j][col]);
        Vr[j] = __half2float(sKV[b_l][j][128 + col]);
    }

    for (int i = 0; i < 16; i++) {
        float selv = sS[b_l][i][col];
        float lg = -3e38f;
#pragma unroll
        for (int j = 0; j < 16; j++) {
            float p = selv * Kr[j];
#pragma unroll
            for (int off = 16; off; off >>= 1) p += __shfl_xor_sync(0xffffffffu, p, off);
            if (lane == j) lg = (j == i) ? -1e9f : p * 0.17677669529663687f;
        }
        float mx = lg;
#pragma unroll
        for (int off = 16; off; off >>= 1) mx = fmaxf(mx, __shfl_xor_sync(0xffffffffu, mx, off));
        float e = (lane < 16) ? __expf(lg - mx) : 0.f;
        float den = e;
#pragma unroll
        for (int off = 16; off; off >>= 1) den += __shfl_xor_sync(0xffffffffu, den, off);
        float w = e / den;

        float acc = 0.f;
#pragma unroll
        for (int j = 0; j < 16; j++) {
            float wj = __shfl_sync(0xffffffffu, w, j);
            acc = fmaf(wj, Vr[j], acc);
        }
        oH[((long)i * BATCH + b) * HID + col] = __float2half_rn(acc);
    }
}

// ---------------- launch -------------------------------------------------------
static float* symaddr(const void* sym)
{
    void* p = nullptr;
    cudaGetSymbolAddress(&p, sym);
    return (float*)p;
}
static __half* symaddr_h(const void* sym)
{
    void* p = nullptr;
    cudaGetSymbolAddress(&p, sym);
    return (__half*)p;
}

extern "C" void kernel_launch(void* const* d_in, const int* in_sizes, int n_in,
                              void* d_out, int out_size)
{
    const float* obs     = (const float*)d_in[0];
    const float* actions = (const float*)d_in[1];
    const float* W_sa    = (const float*)d_in[2];
    const float* b_sa    = (const float*)d_in[3];
    const float* W_s     = (const float*)d_in[4];
    const float* b_s     = (const float*)d_in[5];
    const float* Wk      = (const float*)d_in[6];
    const float* Wsel    = (const float*)d_in[7];
    const float* Wv      = (const float*)d_in[8];
    const float* bv      = (const float*)d_in[9];
    const float* Wc1     = (const float*)d_in[10];
    const float* bc1     = (const float*)d_in[11];
    const float* Wc2     = (const float*)d_in[12];
    const float* bc2     = (const float*)d_in[13];
    float* out = (float*)d_out;

    float* ps    = symaddr(g_ps);
    float* ps2   = symaddr(g_ps2);
    float* mean  = symaddr(g_mean);
    float* istd  = symaddr(g_istd);
    float* b1    = symaddr(g_b1);
    float* bkv   = symaddr(g_bkv);
    float* St    = symaddr(g_S);

    __half* w1h  = symaddr_h(w1_h);
    __half* kvh  = symaddr_h(wkv_h);
    __half* selh = symaddr_h(wsel_h);
    __half* c1h  = symaddr_h(wc1_h);
    __half* obsH = symaddr_h(g_obsH);
    __half* actH = symaddr_h(g_actH);
    __half* aseH = symaddr_h(g_aseH);
    __half* othH = symaddr_h(g_othH);
    __half* KVh  = symaddr_h(g_KVh);

    const size_t smem32 = 4 * (size_t)(128 + 128) * 40 * 2;   // 81920 (KCH=32, 4 stages)
    const size_t smem64 = 2 * (size_t)(128 + 128) * 72 * 2;   // 73728 (KCH=64, 2 stages)

    static bool attr_set = false;
    if (!attr_set) {
        cudaFuncSetAttribute(gemm_mma<128, 32, 4>, cudaFuncAttributeMaxDynamicSharedMemorySize, smem32);
        cudaFuncSetAttribute(gemm_mma<128, 64, 2>, cudaFuncAttributeMaxDynamicSharedMemorySize, smem64);
        attr_set = true;
    }

    const long sOBS = (long)BATCH * OBS;
    const long sACT = (long)BATCH * ACT;
    const long sASE = (long)BATCH * 256;
    const long sH   = (long)BATCH * HID;

    // 0
    bn_part_kernel<<<dim3(AGENTS, 5, 8), dim3(32, 32)>>>(obs, actions, ps, ps2, obsH, actH);
    // 1
    bn_fin_kernel<<<AGENTS, 160>>>(ps, ps2, mean, istd);
    // 2
    prep_all<<<dim3(160, 5, AGENTS), 256>>>(W_sa, b_sa, W_s, b_s, Wk, Wsel, Wv, bv,
                                            Wc1, mean, istd,
                                            w1h, kvh, selh, c1h, b1, bkv);

    // 3: ase = lrelu(bn([obs|act]) @ [W_sa|W_s] + b1)  K=144->160, KCH=32
    gemm_mma<128, 32, 4><<<dim3(BATCH / 128, 2, AGENTS), 256, smem32>>>(
        obsH, sOBS, OBS, actH, sACT, ACT, OBS, INP,
        w1h, (long)256 * 160, 160,
        b1, 256, nullptr, sASE, 256, 0,
        1, aseH,
        1 << 28, nullptr, nullptr, 0,
        0, nullptr, nullptr, nullptr, nullptr);

    // 4: merged KV (fp16 out) + Sel (fp32 out).  K=128, KCH=64
    gemm_mma<128, 64, 2><<<dim3(BATCH / 128, 3, AGENTS), 256, smem64>>>(
        aseH, sASE, 256, aseH, 0, 0, 1 << 30, HID,
        kvh, 0, HID,
        bkv, 0, nullptr, sASE, 256, 128,
        1, KVh,
        2, selh, St, sH,
        0, nullptr, nullptr, nullptr, nullptr);

    // 5: attention (KV fp16) -> other (fp16)
    attn_kernel<<<BATCH / 2, 256>>>(KVh, St, othH);

    // 6: q = fused( lrelu([se|other] @ Wc1 + bc1) . Wc2[:,argmax] + bc2 )  K=256, KCH=64
    gemm_mma<128, 64, 2><<<dim3(BATCH / 128, 1, AGENTS), 256, smem64>>>(
        aseH + 128, sASE, 256, othH, sH, HID, HID, 2 * HID,
        c1h, (long)HID * 2 * HID, 2 * HID,
        bc1, HID, nullptr, 0, 0, 1 << 30,
        0, nullptr,
        1 << 28, nullptr, nullptr, 0,
        1, actions, Wc2, bc2, out);
}